// round 1
// baseline (speedup 1.0000x reference)
#include <cuda_runtime.h>

// ---------------------------------------------------------------------------
// Problem constants
// ---------------------------------------------------------------------------
#define B_    64
#define NQ_   1024
#define DM_   1024
#define H_    16
#define D_    64
#define LT_   77          // TEXT_LEN
#define LI_   256         // IMG_LEN
#define NR_   33          // 2*MAX_REL+1
#define RELCUT 92         // for i >= 92, idx(i,j)==0 for all j in [0,77)

// ---------------------------------------------------------------------------
// Scratch (static device globals; no runtime allocation allowed)
// ---------------------------------------------------------------------------
__device__ float g_q  [(size_t)B_ * NQ_ * DM_];       // 256 MB
__device__ float g_att[(size_t)B_ * NQ_ * DM_];       // 256 MB
__device__ float g_kt [(size_t)B_ * H_ * LT_ * D_];
__device__ float g_vt [(size_t)B_ * H_ * LT_ * D_];
__device__ float g_ki [(size_t)B_ * H_ * LI_ * D_];
__device__ float g_vi [(size_t)B_ * H_ * LI_ * D_];

// ---------------------------------------------------------------------------
// Generic guarded SGEMM: C[M,N] = remap(A)[M,K] @ Bm[K,N] (+bias)
//   Logical row m maps to physical A row: seg = m / rows_per_seg,
//   t = m % rows_per_seg, arow = seg*seg_stride + seg_base + t.
//   KV_STORE scatters C into [b][h][t][d] layout (h = n/64, d = n%64).
//   Assumes N % 128 == 0 and K % 8 == 0 (true for every call here).
// ---------------------------------------------------------------------------
template <bool KV_STORE>
__global__ void __launch_bounds__(256, 2)
sgemm_kernel(const float* __restrict__ A, const float* __restrict__ Bm,
             float* __restrict__ C, const float* __restrict__ bias,
             int M, int N, int K,
             int rows_per_seg, int seg_stride, int seg_base)
{
    __shared__ float As[8][128];
    __shared__ float Bs[8][128];

    const int tid = threadIdx.x;
    const int bm  = blockIdx.y * 128;
    const int bn  = blockIdx.x * 128;

    // A tile load mapping: one float4 per thread (128 rows x 8 k)
    const int arow = tid >> 1;
    const int acol = (tid & 1) * 4;
    const int m_g  = bm + arow;
    const int segA = m_g / rows_per_seg;
    const int tA   = m_g - segA * rows_per_seg;
    const float* Aptr = A + ((size_t)(segA * seg_stride + seg_base + tA)) * K + acol;
    const bool a_ok = (m_g < M);

    // B tile load mapping: one float4 per thread (8 k x 128 n)
    const int brow = tid >> 5;
    const int bcol = (tid & 31) * 4;
    const float* Bptr = Bm + (size_t)brow * N + bn + bcol;

    const int trow = (tid >> 4) * 8;
    const int tcol = (tid & 15) * 8;

    float acc[8][8];
#pragma unroll
    for (int i = 0; i < 8; i++)
#pragma unroll
        for (int j = 0; j < 8; j++) acc[i][j] = 0.f;

    for (int k0 = 0; k0 < K; k0 += 8) {
        float4 av = a_ok ? *(const float4*)(Aptr + k0)
                         : make_float4(0.f, 0.f, 0.f, 0.f);
        float4 bv = *(const float4*)(Bptr + (size_t)k0 * N);

        As[acol + 0][arow] = av.x;
        As[acol + 1][arow] = av.y;
        As[acol + 2][arow] = av.z;
        As[acol + 3][arow] = av.w;
        *(float4*)&Bs[brow][bcol] = bv;
        __syncthreads();

#pragma unroll
        for (int kk = 0; kk < 8; kk++) {
            float ra[8], rb[8];
#pragma unroll
            for (int i = 0; i < 8; i++) ra[i] = As[kk][trow + i];
#pragma unroll
            for (int j = 0; j < 8; j++) rb[j] = Bs[kk][tcol + j];
#pragma unroll
            for (int i = 0; i < 8; i++)
#pragma unroll
                for (int j = 0; j < 8; j++)
                    acc[i][j] = fmaf(ra[i], rb[j], acc[i][j]);
        }
        __syncthreads();
    }

#pragma unroll
    for (int i = 0; i < 8; i++) {
        int cm = bm + trow + i;
        if (cm >= M) continue;
        if (KV_STORE) {
            int segc = cm / rows_per_seg;
            int tc   = cm - segc * rows_per_seg;
#pragma unroll
            for (int j = 0; j < 8; j++) {
                int cn = bn + tcol + j;
                int hh = cn >> 6, dd = cn & 63;
                size_t oi = (((size_t)segc * H_ + hh) * rows_per_seg + tc) * 64 + dd;
                C[oi] = acc[i][j];
            }
        } else {
            float* Cp = C + (size_t)cm * N + bn + tcol;
            if (bias) {
                const float* bp = bias + bn + tcol;
#pragma unroll
                for (int j = 0; j < 8; j++) Cp[j] = acc[i][j] + bp[j];
            } else {
#pragma unroll
                for (int j = 0; j < 8; j++) Cp[j] = acc[i][j];
            }
        }
    }
}

// ---------------------------------------------------------------------------
// Attention kernel: one CTA per (b,h). All K/V + rel tables resident in smem.
// Each warp processes 4 queries per pass; 8 warps x 32 passes = 1024 queries.
// ---------------------------------------------------------------------------
__device__ __forceinline__ int relidx(int j, int i)
{
    int d = j - i;
    d = max(-16, min(16, d));
    return d + 16;
}

// smem layout (floats)
#define SM_KTT 0                       // [64][80]  text K transposed (pad 80)
#define SM_VT  (SM_KTT + 64 * 80)      // [77][64]  text V row-major
#define SM_KTI (SM_VT + LT_ * 64)      // [64][257] img K transposed (pad 257)
#define SM_VI  (SM_KTI + 64 * 257)     // [256][64] img V row-major
#define SM_RKT (SM_VI + LI_ * 64)      // [64][33]  rel_k transposed
#define SM_RV  (SM_RKT + 64 * NR_)     // [33][64]  rel_v row-major
#define SM_P   (SM_RV + NR_ * 64)      // [32][34]  per (warp,query) rel-proj p
#define SM_QB  (SM_P + 32 * 34)        // [32][64]  per (warp,query) q rows
#define SM_TOTAL_FLOATS (SM_QB + 32 * 64)
#define ATTN_SMEM_BYTES (SM_TOTAL_FLOATS * 4)

__global__ void __launch_bounds__(256, 1)
attn_kernel(const float* __restrict__ q,
            const float* __restrict__ kt, const float* __restrict__ vt,
            const float* __restrict__ ki, const float* __restrict__ vi,
            const float* __restrict__ relk, const float* __restrict__ relv,
            float* __restrict__ outp)
{
    extern __shared__ float sm[];
    float* kTt = sm + SM_KTT;
    float* vT  = sm + SM_VT;
    float* kTi = sm + SM_KTI;
    float* vI  = sm + SM_VI;
    float* rkT = sm + SM_RKT;
    float* rvS = sm + SM_RV;
    float* pS  = sm + SM_P;
    float* qb  = sm + SM_QB;

    const int bh = blockIdx.x;
    const int b = bh >> 4, h = bh & 15;
    const int tid = threadIdx.x, w = tid >> 5, lane = tid & 31;
    const float scale = 0.125f;  // D^-0.5
    const unsigned FULL = 0xffffffffu;

    // ---- stage K/V/rel tables into shared memory ----
    {
        const float* Kt = kt + (size_t)bh * (LT_ * D_);
        const float* Vt = vt + (size_t)bh * (LT_ * D_);
        const float* Ki = ki + (size_t)bh * (LI_ * D_);
        const float* Vi = vi + (size_t)bh * (LI_ * D_);
        for (int idx = tid; idx < LT_ * D_; idx += 256) {
            int t = idx >> 6, d = idx & 63;
            kTt[d * 80 + t] = Kt[idx];
            vT[idx] = Vt[idx];
        }
        for (int idx = tid; idx < LI_ * D_; idx += 256) {
            int t = idx >> 6, d = idx & 63;
            kTi[d * 257 + t] = Ki[idx];
            vI[idx] = Vi[idx];
        }
        for (int idx = tid; idx < NR_ * D_; idx += 256) {
            int r = idx >> 6, d = idx & 63;
            rkT[d * NR_ + r] = relk[idx];
            rvS[idx] = relv[idx];
        }
    }
    __syncthreads();

    const bool j2ok = (lane < (LT_ - 64));  // lane < 13 -> third text key valid

    for (int it = 0; it < NQ_ / 32; ++it) {
        const int i0 = (it * 8 + w) * 4;
        __syncwarp();  // protect qb/pS reuse across iterations

        // load 4 q rows for this warp into smem
        {
            const float* qg = q + ((size_t)(b * NQ_ + i0)) * DM_ + h * D_;
#pragma unroll
            for (int s = 0; s < 8; s++) {
                int e = s * 32 + lane;
                int qq = e >> 6, d = e & 63;
                qb[(w * 4 + qq) * 64 + d] = qg[(size_t)qq * DM_ + d];
            }
        }
        __syncwarp();
        const float* qw = qb + w * 4 * 64;

        // ---- text sim + rel-k projections p[r] = q . rel_k[r] ----
        float st0[4] = {0, 0, 0, 0}, st1[4] = {0, 0, 0, 0}, st2[4] = {0, 0, 0, 0};
        float sp0[4] = {0, 0, 0, 0}, sp1[4] = {0, 0, 0, 0};
#pragma unroll 8
        for (int d = 0; d < 64; d++) {
            float k0 = kTt[d * 80 + lane];
            float k1 = kTt[d * 80 + lane + 32];
            float k2 = j2ok ? kTt[d * 80 + lane + 64] : 0.f;
            float r0 = rkT[d * NR_ + lane];
            float r1 = (lane == 0) ? rkT[d * NR_ + 32] : 0.f;
#pragma unroll
            for (int qq = 0; qq < 4; qq++) {
                float qd = qw[qq * 64 + d];
                st0[qq] = fmaf(qd, k0, st0[qq]);
                st1[qq] = fmaf(qd, k1, st1[qq]);
                st2[qq] = fmaf(qd, k2, st2[qq]);
                sp0[qq] = fmaf(qd, r0, sp0[qq]);
                sp1[qq] = fmaf(qd, r1, sp1[qq]);
            }
        }
#pragma unroll
        for (int qq = 0; qq < 4; qq++) {
            pS[(w * 4 + qq) * 34 + lane] = sp0[qq];
            if (lane == 0) pS[(w * 4 + qq) * 34 + 32] = sp1[qq];
        }
        __syncwarp();

        // ---- text softmax (per query; lane owns keys lane, lane+32, lane+64) ----
        float at0[4], at1[4], at2[4];
#pragma unroll
        for (int qq = 0; qq < 4; qq++) {
            const int iq = i0 + qq;
            float s0, s1, s2;
            if (iq >= RELCUT) {
                // all rel buckets are 0 -> constant shift -> softmax-invariant
                s0 = st0[qq] * scale;
                s1 = st1[qq] * scale;
                s2 = j2ok ? st2[qq] * scale : -1e30f;
            } else {
                const float* pp = pS + (w * 4 + qq) * 34;
                s0 = (st0[qq] + pp[relidx(lane, iq)]) * scale;
                s1 = (st1[qq] + pp[relidx(lane + 32, iq)]) * scale;
                s2 = j2ok ? (st2[qq] + pp[relidx(lane + 64, iq)]) * scale : -1e30f;
            }
            float mx = fmaxf(s0, fmaxf(s1, s2));
#pragma unroll
            for (int o = 16; o > 0; o >>= 1) mx = fmaxf(mx, __shfl_xor_sync(FULL, mx, o));
            float e0 = __expf(s0 - mx);
            float e1 = __expf(s1 - mx);
            float e2 = j2ok ? __expf(s2 - mx) : 0.f;
            float sv = e0 + e1 + e2;
#pragma unroll
            for (int o = 16; o > 0; o >>= 1) sv += __shfl_xor_sync(FULL, sv, o);
            float inv = 1.f / sv;
            at0[qq] = e0 * inv; at1[qq] = e1 * inv; at2[qq] = e2 * inv;
        }

        float o0[4] = {0, 0, 0, 0}, o1[4] = {0, 0, 0, 0};
        const bool anyrel = (i0 < RELCUT);

        // ---- text attn @ V (+ rel_v gather for early rows) ----
#define TEXT_V_STEP(AT, J, SRC)                                           \
        {                                                                 \
            float v0 = vT[(J) * 64 + lane], v1 = vT[(J) * 64 + lane + 32];\
            _Pragma("unroll")                                             \
            for (int qq = 0; qq < 4; qq++) {                              \
                float a = __shfl_sync(FULL, AT[qq], (SRC));               \
                o0[qq] = fmaf(a, v0, o0[qq]);                             \
                o1[qq] = fmaf(a, v1, o1[qq]);                             \
                if (anyrel && (i0 + qq) < RELCUT) {                       \
                    int rr = relidx((J), i0 + qq);                        \
                    o0[qq] = fmaf(a, rvS[rr * 64 + lane], o0[qq]);        \
                    o1[qq] = fmaf(a, rvS[rr * 64 + lane + 32], o1[qq]);   \
                }                                                         \
            }                                                             \
        }

#pragma unroll 2
        for (int src = 0; src < 32; src++) TEXT_V_STEP(at0, src, src)
#pragma unroll 2
        for (int src = 0; src < 32; src++) TEXT_V_STEP(at1, 32 + src, src)
#pragma unroll
        for (int src = 0; src < 13; src++) TEXT_V_STEP(at2, 64 + src, src)
#undef TEXT_V_STEP

        // rel_v shortcut for rows where every bucket is 0: sum(attn)*rv[0] = rv[0]
#pragma unroll
        for (int qq = 0; qq < 4; qq++) {
            if (i0 + qq >= RELCUT) {
                o0[qq] += rvS[lane];
                o1[qq] += rvS[lane + 32];
            }
        }

        // ---- image branch: sim ----
        float si[8][4];
#pragma unroll
        for (int m2 = 0; m2 < 8; m2++)
#pragma unroll
            for (int qq = 0; qq < 4; qq++) si[m2][qq] = 0.f;

#pragma unroll 4
        for (int d = 0; d < 64; d++) {
            float kk[8];
#pragma unroll
            for (int m2 = 0; m2 < 8; m2++) kk[m2] = kTi[d * 257 + m2 * 32 + lane];
#pragma unroll
            for (int qq = 0; qq < 4; qq++) {
                float qd = qw[qq * 64 + d];
#pragma unroll
                for (int m2 = 0; m2 < 8; m2++)
                    si[m2][qq] = fmaf(qd, kk[m2], si[m2][qq]);
            }
        }

        // ---- image softmax ----
#pragma unroll
        for (int qq = 0; qq < 4; qq++) {
            float mx = -1e30f;
#pragma unroll
            for (int m2 = 0; m2 < 8; m2++) {
                si[m2][qq] *= scale;
                mx = fmaxf(mx, si[m2][qq]);
            }
#pragma unroll
            for (int o = 16; o > 0; o >>= 1) mx = fmaxf(mx, __shfl_xor_sync(FULL, mx, o));
            float sv = 0.f;
#pragma unroll
            for (int m2 = 0; m2 < 8; m2++) {
                float e = __expf(si[m2][qq] - mx);
                si[m2][qq] = e;
                sv += e;
            }
#pragma unroll
            for (int o = 16; o > 0; o >>= 1) sv += __shfl_xor_sync(FULL, sv, o);
            float inv = 1.f / sv;
#pragma unroll
            for (int m2 = 0; m2 < 8; m2++) si[m2][qq] *= inv;
        }

        // ---- image attn @ V ----
#pragma unroll
        for (int slot = 0; slot < 8; slot++) {
#pragma unroll 2
            for (int src = 0; src < 32; src++) {
                int j = slot * 32 + src;
                float v0 = vI[j * 64 + lane], v1 = vI[j * 64 + lane + 32];
#pragma unroll
                for (int qq = 0; qq < 4; qq++) {
                    float a = __shfl_sync(FULL, si[slot][qq], src);
                    o0[qq] = fmaf(a, v0, o0[qq]);
                    o1[qq] = fmaf(a, v1, o1[qq]);
                }
            }
        }

        // ---- store combined attention output [b, i, h*64+d] ----
#pragma unroll
        for (int qq = 0; qq < 4; qq++) {
            size_t oi = ((size_t)(b * NQ_ + i0 + qq)) * DM_ + h * D_;
            outp[oi + lane] = o0[qq];
            outp[oi + lane + 32] = o1[qq];
        }
    }
}

// ---------------------------------------------------------------------------
// Host launcher
// ---------------------------------------------------------------------------
extern "C" void kernel_launch(void* const* d_in, const int* in_sizes, int n_in,
                              void* d_out, int out_size)
{
    const float* x     = (const float*)d_in[0];
    const float* ctx   = (const float*)d_in[1];
    const float* Wq    = (const float*)d_in[2];
    const float* Wk    = (const float*)d_in[3];
    const float* Wv    = (const float*)d_in[4];
    const float* Wk_ip = (const float*)d_in[5];
    const float* Wv_ip = (const float*)d_in[6];
    const float* Wout  = (const float*)d_in[7];
    const float* bout  = (const float*)d_in[8];
    const float* relk  = (const float*)d_in[9];
    const float* relv  = (const float*)d_in[10];
    float* out = (float*)d_out;

    float *pq, *patt, *pkt, *pvt, *pki, *pvi;
    cudaGetSymbolAddress((void**)&pq,   g_q);
    cudaGetSymbolAddress((void**)&patt, g_att);
    cudaGetSymbolAddress((void**)&pkt,  g_kt);
    cudaGetSymbolAddress((void**)&pvt,  g_vt);
    cudaGetSymbolAddress((void**)&pki,  g_ki);
    cudaGetSymbolAddress((void**)&pvi,  g_vi);

    cudaFuncSetAttribute(attn_kernel,
                         cudaFuncAttributeMaxDynamicSharedMemorySize,
                         ATTN_SMEM_BYTES);

    dim3 blk(256);

    // Q = x @ Wq                  [65536 x 1024]
    sgemm_kernel<false><<<dim3(8, 512), blk>>>(
        x, Wq, pq, nullptr, B_ * NQ_, DM_, DM_, B_ * NQ_, B_ * NQ_, 0);

    // K/V (text rows of context)  [4928 x 1024] -> [b,h,t,d]
    sgemm_kernel<true><<<dim3(8, 39), blk>>>(
        ctx, Wk, pkt, nullptr, B_ * LT_, DM_, DM_, LT_, LT_ + LI_, 0);
    sgemm_kernel<true><<<dim3(8, 39), blk>>>(
        ctx, Wv, pvt, nullptr, B_ * LT_, DM_, DM_, LT_, LT_ + LI_, 0);

    // K_ip/V_ip (image rows)      [16384 x 1024] -> [b,h,t,d]
    sgemm_kernel<true><<<dim3(8, 128), blk>>>(
        ctx, Wk_ip, pki, nullptr, B_ * LI_, DM_, DM_, LI_, LT_ + LI_, LT_);
    sgemm_kernel<true><<<dim3(8, 128), blk>>>(
        ctx, Wv_ip, pvi, nullptr, B_ * LI_, DM_, DM_, LI_, LT_ + LI_, LT_);

    // fused attention (text + rel + image IP branch)
    attn_kernel<<<B_ * H_, 256, ATTN_SMEM_BYTES>>>(
        pq, pkt, pvt, pki, pvi, relk, relv, patt);

    // final projection + bias
    sgemm_kernel<false><<<dim3(8, 512), blk>>>(
        patt, Wout, out, bout, B_ * NQ_, DM_, DM_, B_ * NQ_, B_ * NQ_, 0);
}

// round 3
// speedup vs baseline: 1.5189x; 1.5189x over previous
#include <cuda_runtime.h>
#include <cuda_bf16.h>
#include <cstdint>

// ---------------------------------------------------------------------------
// Problem constants
// ---------------------------------------------------------------------------
#define B_    64
#define NQ_   1024
#define DM_   1024
#define H_    16
#define D_    64
#define LT_   77
#define LI_   256
#define NR_   33
#define RELCUT 92
#define CTXR  (LT_ + LI_)     // 333

__device__ __forceinline__ uint32_t smem_to_u32(const void* p) {
    uint32_t a;
    asm("{ .reg .u64 t; cvta.to.shared.u64 t, %1; cvt.u32.u64 %0, t; }"
        : "=r"(a) : "l"(p));
    return a;
}

#define CPA16(dst, src) \
    asm volatile("cp.async.cg.shared.global [%0], [%1], 16;" \
                 :: "r"(dst), "l"(src))
#define CPA_COMMIT() asm volatile("cp.async.commit_group;" ::: "memory")
#define CPA_WAIT(n)  asm volatile("cp.async.wait_group %0;" :: "n"(n) : "memory")

#define LDMX4(r0, r1, r2, r3, addr) \
    asm volatile("ldmatrix.sync.aligned.m8n8.x4.shared.b16 {%0,%1,%2,%3}, [%4];" \
                 : "=r"(r0), "=r"(r1), "=r"(r2), "=r"(r3) : "r"(addr))

#define MMA16816(c, a, b0, b1) \
    asm volatile("mma.sync.aligned.m16n8k16.row.col.f32.bf16.bf16.f32 " \
                 "{%0,%1,%2,%3}, {%4,%5,%6,%7}, {%8,%9}, {%0,%1,%2,%3};" \
                 : "+f"((c)[0]), "+f"((c)[1]), "+f"((c)[2]), "+f"((c)[3]) \
                 : "r"((a)[0]), "r"((a)[1]), "r"((a)[2]), "r"((a)[3]), \
                   "r"(b0), "r"(b1))

// ---------------------------------------------------------------------------
// Scratch (static device globals)
// ---------------------------------------------------------------------------
__device__ float g_q  [(size_t)B_ * NQ_ * DM_];
__device__ float g_att[(size_t)B_ * NQ_ * DM_];
__device__ float g_kt [(size_t)B_ * H_ * LT_ * D_];
__device__ float g_vt [(size_t)B_ * H_ * LT_ * D_];
__device__ float g_ki [(size_t)B_ * H_ * LI_ * D_];
__device__ float g_vi [(size_t)B_ * H_ * LI_ * D_];
__device__ __nv_bfloat16 g_ahi[(size_t)B_ * NQ_ * DM_];
__device__ __nv_bfloat16 g_alo[(size_t)B_ * NQ_ * DM_];
__device__ __nv_bfloat16 g_chi[(size_t)B_ * CTXR * DM_];
__device__ __nv_bfloat16 g_clo[(size_t)B_ * CTXR * DM_];
__device__ __nv_bfloat16 g_whi[6 * (size_t)DM_ * DM_];
__device__ __nv_bfloat16 g_wlo[6 * (size_t)DM_ * DM_];

// ---------------------------------------------------------------------------
// fp32 -> bf16 hi/lo split
// ---------------------------------------------------------------------------
__global__ void conv_rows(const float* __restrict__ src,
                          __nv_bfloat16* __restrict__ hi,
                          __nv_bfloat16* __restrict__ lo, size_t n)
{
    size_t i = ((size_t)blockIdx.x * blockDim.x + threadIdx.x) * 4;
    if (i >= n) return;
    float4 v = *(const float4*)(src + i);
    __nv_bfloat16 h0 = __float2bfloat16(v.x);
    __nv_bfloat16 h1 = __float2bfloat16(v.y);
    __nv_bfloat16 h2 = __float2bfloat16(v.z);
    __nv_bfloat16 h3 = __float2bfloat16(v.w);
    __nv_bfloat16 l0 = __float2bfloat16(v.x - __bfloat162float(h0));
    __nv_bfloat16 l1 = __float2bfloat16(v.y - __bfloat162float(h1));
    __nv_bfloat16 l2 = __float2bfloat16(v.z - __bfloat162float(h2));
    __nv_bfloat16 l3 = __float2bfloat16(v.w - __bfloat162float(h3));
    __nv_bfloat162 hp0 = {h0, h1}, hp1 = {h2, h3};
    __nv_bfloat162 lp0 = {l0, l1}, lp1 = {l2, l3};
    *(uint2*)(hi + i) = make_uint2(*(uint32_t*)&hp0, *(uint32_t*)&hp1);
    *(uint2*)(lo + i) = make_uint2(*(uint32_t*)&lp0, *(uint32_t*)&lp1);
}

// W [K=1024, N=1024] -> Wt hi/lo [N, K]
__global__ void conv_wt(const float* __restrict__ W,
                        __nv_bfloat16* __restrict__ hi,
                        __nv_bfloat16* __restrict__ lo)
{
    __shared__ float tile[32][33];
    const int k0 = blockIdx.y * 32, n0 = blockIdx.x * 32;
    const int tx = threadIdx.x;
    for (int r = threadIdx.y; r < 32; r += 8)
        tile[r][tx] = W[(size_t)(k0 + r) * DM_ + n0 + tx];
    __syncthreads();
    for (int r = threadIdx.y; r < 32; r += 8) {
        float v = tile[tx][r];
        __nv_bfloat16 h = __float2bfloat16(v);
        size_t oi = (size_t)(n0 + r) * DM_ + k0 + tx;
        hi[oi] = h;
        lo[oi] = __float2bfloat16(v - __bfloat162float(h));
    }
}

// ---------------------------------------------------------------------------
// bf16x3 GEMM via mma.sync: C[M,1024] = remap(A)[M,1024] @ B^T (B is [N,K])
// CTA 128x128, BK=32, 8 warps (warp tile 32x64), cp.async double buffer.
// smem per buffer: Ahi/Alo/Bhi/Blo each [128][40] bf16 (80B row stride).
// ---------------------------------------------------------------------------
#define BUF_BYTES   40960            // 4 * 128*40*2
#define GM_SMEM     (2 * BUF_BYTES)  // 81920

template <bool KV_STORE>
__global__ void __launch_bounds__(256, 1)
gemm_mma(const __nv_bfloat16* __restrict__ Ahi, const __nv_bfloat16* __restrict__ Alo,
         const __nv_bfloat16* __restrict__ Bhi, const __nv_bfloat16* __restrict__ Blo,
         float* __restrict__ C, const float* __restrict__ bias,
         int M, int rows_per_seg, int seg_stride, int seg_base)
{
    extern __shared__ __align__(128) char smem[];
    const uint32_t sb = smem_to_u32(smem);
    const int tid = threadIdx.x;
    const int bn = blockIdx.x * 128;
    const int bm = blockIdx.y * 128;
    const int wid = tid >> 5, lane = tid & 31;
    const int Wm = (wid & 3) * 32;
    const int Wn = (wid >> 2) * 64;

    // ---- cp.async load mapping: 2 threads/row, each 2x16B per operand ----
    const int lrow = tid >> 1;
    const int lc = tid & 1;
    int m = bm + lrow; if (m > M - 1) m = M - 1;
    const int seg = m / rows_per_seg;
    const int t = m - seg * rows_per_seg;
    const size_t aoff = (size_t)(seg * seg_stride + seg_base + t) * 1024 + lc * 16;
    const size_t boff = (size_t)(bn + lrow) * 1024 + lc * 16;
    const uint32_t soff = (uint32_t)lrow * 80u + (uint32_t)lc * 32u;

    float acc[2][8][4];
#pragma unroll
    for (int i = 0; i < 2; i++)
#pragma unroll
        for (int j = 0; j < 8; j++)
#pragma unroll
            for (int c = 0; c < 4; c++) acc[i][j][c] = 0.f;

    // ---- fragment addresses (fixed per thread; vary buffer + k16) ----
    const uint32_t a_frag_row = (uint32_t)(Wm + (lane & 15)) * 80u + ((lane >> 4) * 16u);
    const uint32_t b_frag_row =
        (uint32_t)(Wn + (lane & 7) + ((lane >> 4) << 3)) * 80u + (((lane >> 3) & 1) * 16u);

#define ISSUE(p, k0)                                                       \
    {                                                                      \
        uint32_t d = sb + (p) * BUF_BYTES + soff;                          \
        const __nv_bfloat16* s;                                            \
        s = Ahi + aoff + (k0); CPA16(d,           s); CPA16(d + 16,         s + 8); \
        s = Alo + aoff + (k0); CPA16(d + 10240,   s); CPA16(d + 10240 + 16, s + 8); \
        s = Bhi + boff + (k0); CPA16(d + 20480,   s); CPA16(d + 20480 + 16, s + 8); \
        s = Blo + boff + (k0); CPA16(d + 30720,   s); CPA16(d + 30720 + 16, s + 8); \
    }

    ISSUE(0, 0);
    CPA_COMMIT();

    for (int i = 0; i < 32; i++) {
        if (i + 1 < 32) {
            ISSUE((i + 1) & 1, (i + 1) * 32);
            CPA_COMMIT();
            CPA_WAIT(1);
        } else {
            CPA_WAIT(0);
        }
        __syncthreads();

        const uint32_t base = sb + (i & 1) * BUF_BYTES;
#pragma unroll
        for (int kk = 0; kk < 2; kk++) {
            uint32_t ah[2][4], al[2][4];
            const uint32_t ar = base + a_frag_row + kk * 32;
            LDMX4(ah[0][0], ah[0][1], ah[0][2], ah[0][3], ar);
            LDMX4(ah[1][0], ah[1][1], ah[1][2], ah[1][3], ar + 16 * 80);
            LDMX4(al[0][0], al[0][1], al[0][2], al[0][3], ar + 10240);
            LDMX4(al[1][0], al[1][1], al[1][2], al[1][3], ar + 10240 + 16 * 80);
#pragma unroll
            for (int j = 0; j < 4; j++) {
                uint32_t bh0, bh1, bh2, bh3, bl0, bl1, bl2, bl3;
                const uint32_t br = base + b_frag_row + kk * 32 + (uint32_t)j * (16 * 80);
                LDMX4(bh0, bh1, bh2, bh3, br + 20480);
                LDMX4(bl0, bl1, bl2, bl3, br + 30720);
#pragma unroll
                for (int mt = 0; mt < 2; mt++) {
                    MMA16816(acc[mt][2 * j],     ah[mt], bh0, bh1);
                    MMA16816(acc[mt][2 * j],     al[mt], bh0, bh1);
                    MMA16816(acc[mt][2 * j],     ah[mt], bl0, bl1);
                    MMA16816(acc[mt][2 * j + 1], ah[mt], bh2, bh3);
                    MMA16816(acc[mt][2 * j + 1], al[mt], bh2, bh3);
                    MMA16816(acc[mt][2 * j + 1], ah[mt], bl2, bl3);
                }
            }
        }
        __syncthreads();
    }
#undef ISSUE

    // ---- epilogue ----
    const int er = lane >> 2, ec = (lane & 3) * 2;
#pragma unroll
    for (int mt = 0; mt < 2; mt++) {
#pragma unroll
        for (int hrow = 0; hrow < 2; hrow++) {
            const int cm = bm + Wm + mt * 16 + er + hrow * 8;
            if (cm >= M) continue;
            if (KV_STORE) {
                const int segc = cm / rows_per_seg;
                const int tc = cm - segc * rows_per_seg;
#pragma unroll
                for (int nt = 0; nt < 8; nt++) {
                    const int cn = bn + Wn + nt * 8 + ec;
                    const int hh = cn >> 6, dd = cn & 63;
                    size_t oi = (((size_t)segc * H_ + hh) * rows_per_seg + tc) * 64 + dd;
                    C[oi]     = acc[mt][nt][hrow * 2];
                    C[oi + 1] = acc[mt][nt][hrow * 2 + 1];
                }
            } else {
                float* Cp = C + (size_t)cm * DM_ + bn + Wn + ec;
                if (bias) {
                    const float* bp = bias + bn + Wn + ec;
#pragma unroll
                    for (int nt = 0; nt < 8; nt++) {
                        float2 v = make_float2(acc[mt][nt][hrow * 2] + bp[nt * 8],
                                               acc[mt][nt][hrow * 2 + 1] + bp[nt * 8 + 1]);
                        *(float2*)(Cp + nt * 8) = v;
                    }
                } else {
#pragma unroll
                    for (int nt = 0; nt < 8; nt++) {
                        float2 v = make_float2(acc[mt][nt][hrow * 2],
                                               acc[mt][nt][hrow * 2 + 1]);
                        *(float2*)(Cp + nt * 8) = v;
                    }
                }
            }
        }
    }
}

// ---------------------------------------------------------------------------
// Attention kernel (unchanged — fp32, one CTA per (b,h))
// ---------------------------------------------------------------------------
__device__ __forceinline__ int relidx(int j, int i)
{
    int d = j - i;
    d = max(-16, min(16, d));
    return d + 16;
}

#define SM_KTT 0
#define SM_VT  (SM_KTT + 64 * 80)
#define SM_KTI (SM_VT + LT_ * 64)
#define SM_VI  (SM_KTI + 64 * 257)
#define SM_RKT (SM_VI + LI_ * 64)
#define SM_RV  (SM_RKT + 64 * NR_)
#define SM_P   (SM_RV + NR_ * 64)
#define SM_QB  (SM_P + 32 * 34)
#define SM_TOTAL_FLOATS (SM_QB + 32 * 64)
#define ATTN_SMEM_BYTES (SM_TOTAL_FLOATS * 4)

__global__ void __launch_bounds__(256, 1)
attn_kernel(const float* __restrict__ q,
            const float* __restrict__ kt, const float* __restrict__ vt,
            const float* __restrict__ ki, const float* __restrict__ vi,
            const float* __restrict__ relk, const float* __restrict__ relv,
            float* __restrict__ outp)
{
    extern __shared__ float sm[];
    float* kTt = sm + SM_KTT;
    float* vT  = sm + SM_VT;
    float* kTi = sm + SM_KTI;
    float* vI  = sm + SM_VI;
    float* rkT = sm + SM_RKT;
    float* rvS = sm + SM_RV;
    float* pS  = sm + SM_P;
    float* qb  = sm + SM_QB;

    const int bh = blockIdx.x;
    const int b = bh >> 4, h = bh & 15;
    const int tid = threadIdx.x, w = tid >> 5, lane = tid & 31;
    const float scale = 0.125f;
    const unsigned FULL = 0xffffffffu;

    {
        const float* Kt = kt + (size_t)bh * (LT_ * D_);
        const float* Vt = vt + (size_t)bh * (LT_ * D_);
        const float* Ki = ki + (size_t)bh * (LI_ * D_);
        const float* Vi = vi + (size_t)bh * (LI_ * D_);
        for (int idx = tid; idx < LT_ * D_; idx += 256) {
            int t = idx >> 6, d = idx & 63;
            kTt[d * 80 + t] = Kt[idx];
            vT[idx] = Vt[idx];
        }
        for (int idx = tid; idx < LI_ * D_; idx += 256) {
            int t = idx >> 6, d = idx & 63;
            kTi[d * 257 + t] = Ki[idx];
            vI[idx] = Vi[idx];
        }
        for (int idx = tid; idx < NR_ * D_; idx += 256) {
            int r = idx >> 6, d = idx & 63;
            rkT[d * NR_ + r] = relk[idx];
            rvS[idx] = relv[idx];
        }
    }
    __syncthreads();

    const bool j2ok = (lane < (LT_ - 64));

    for (int it = 0; it < NQ_ / 32; ++it) {
        const int i0 = (it * 8 + w) * 4;
        __syncwarp();
        {
            const float* qg = q + ((size_t)(b * NQ_ + i0)) * DM_ + h * D_;
#pragma unroll
            for (int s = 0; s < 8; s++) {
                int e = s * 32 + lane;
                int qq = e >> 6, d = e & 63;
                qb[(w * 4 + qq) * 64 + d] = qg[(size_t)qq * DM_ + d];
            }
        }
        __syncwarp();
        const float* qw = qb + w * 4 * 64;

        float st0[4] = {0, 0, 0, 0}, st1[4] = {0, 0, 0, 0}, st2[4] = {0, 0, 0, 0};
        float sp0[4] = {0, 0, 0, 0}, sp1[4] = {0, 0, 0, 0};
#pragma unroll 8
        for (int d = 0; d < 64; d++) {
            float k0 = kTt[d * 80 + lane];
            float k1 = kTt[d * 80 + lane + 32];
            float k2 = j2ok ? kTt[d * 80 + lane + 64] : 0.f;
            float r0 = rkT[d * NR_ + lane];
            float r1 = (lane == 0) ? rkT[d * NR_ + 32] : 0.f;
#pragma unroll
            for (int qq = 0; qq < 4; qq++) {
                float qd = qw[qq * 64 + d];
                st0[qq] = fmaf(qd, k0, st0[qq]);
                st1[qq] = fmaf(qd, k1, st1[qq]);
                st2[qq] = fmaf(qd, k2, st2[qq]);
                sp0[qq] = fmaf(qd, r0, sp0[qq]);
                sp1[qq] = fmaf(qd, r1, sp1[qq]);
            }
        }
#pragma unroll
        for (int qq = 0; qq < 4; qq++) {
            pS[(w * 4 + qq) * 34 + lane] = sp0[qq];
            if (lane == 0) pS[(w * 4 + qq) * 34 + 32] = sp1[qq];
        }
        __syncwarp();

        float at0[4], at1[4], at2[4];
#pragma unroll
        for (int qq = 0; qq < 4; qq++) {
            const int iq = i0 + qq;
            float s0, s1, s2;
            if (iq >= RELCUT) {
                s0 = st0[qq] * scale;
                s1 = st1[qq] * scale;
                s2 = j2ok ? st2[qq] * scale : -1e30f;
            } else {
                const float* pp = pS + (w * 4 + qq) * 34;
                s0 = (st0[qq] + pp[relidx(lane, iq)]) * scale;
                s1 = (st1[qq] + pp[relidx(lane + 32, iq)]) * scale;
                s2 = j2ok ? (st2[qq] + pp[relidx(lane + 64, iq)]) * scale : -1e30f;
            }
            float mx = fmaxf(s0, fmaxf(s1, s2));
#pragma unroll
            for (int o = 16; o > 0; o >>= 1) mx = fmaxf(mx, __shfl_xor_sync(FULL, mx, o));
            float e0 = __expf(s0 - mx);
            float e1 = __expf(s1 - mx);
            float e2 = j2ok ? __expf(s2 - mx) : 0.f;
            float sv = e0 + e1 + e2;
#pragma unroll
            for (int o = 16; o > 0; o >>= 1) sv += __shfl_xor_sync(FULL, sv, o);
            float inv = 1.f / sv;
            at0[qq] = e0 * inv; at1[qq] = e1 * inv; at2[qq] = e2 * inv;
        }

        float o0[4] = {0, 0, 0, 0}, o1[4] = {0, 0, 0, 0};
        const bool anyrel = (i0 < RELCUT);

#define TEXT_V_STEP(AT, J, SRC)                                           \
        {                                                                 \
            float v0 = vT[(J) * 64 + lane], v1 = vT[(J) * 64 + lane + 32];\
            _Pragma("unroll")                                             \
            for (int qq = 0; qq < 4; qq++) {                              \
                float a = __shfl_sync(FULL, AT[qq], (SRC));               \
                o0[qq] = fmaf(a, v0, o0[qq]);                             \
                o1[qq] = fmaf(a, v1, o1[qq]);                             \
                if (anyrel && (i0 + qq) < RELCUT) {                       \
                    int rr = relidx((J), i0 + qq);                        \
                    o0[qq] = fmaf(a, rvS[rr * 64 + lane], o0[qq]);        \
                    o1[qq] = fmaf(a, rvS[rr * 64 + lane + 32], o1[qq]);   \
                }                                                         \
            }                                                             \
        }

#pragma unroll 2
        for (int src = 0; src < 32; src++) TEXT_V_STEP(at0, src, src)
#pragma unroll 2
        for (int src = 0; src < 32; src++) TEXT_V_STEP(at1, 32 + src, src)
#pragma unroll
        for (int src = 0; src < 13; src++) TEXT_V_STEP(at2, 64 + src, src)
#undef TEXT_V_STEP

#pragma unroll
        for (int qq = 0; qq < 4; qq++) {
            if (i0 + qq >= RELCUT) {
                o0[qq] += rvS[lane];
                o1[qq] += rvS[lane + 32];
            }
        }

        float si[8][4];
#pragma unroll
        for (int m2 = 0; m2 < 8; m2++)
#pragma unroll
            for (int qq = 0; qq < 4; qq++) si[m2][qq] = 0.f;

#pragma unroll 4
        for (int d = 0; d < 64; d++) {
            float kk[8];
#pragma unroll
            for (int m2 = 0; m2 < 8; m2++) kk[m2] = kTi[d * 257 + m2 * 32 + lane];
#pragma unroll
            for (int qq = 0; qq < 4; qq++) {
                float qd = qw[qq * 64 + d];
#pragma unroll
                for (int m2 = 0; m2 < 8; m2++)
                    si[m2][qq] = fmaf(qd, kk[m2], si[m2][qq]);
            }
        }

#pragma unroll
        for (int qq = 0; qq < 4; qq++) {
            float mx = -1e30f;
#pragma unroll
            for (int m2 = 0; m2 < 8; m2++) {
                si[m2][qq] *= scale;
                mx = fmaxf(mx, si[m2][qq]);
            }
#pragma unroll
            for (int o = 16; o > 0; o >>= 1) mx = fmaxf(mx, __shfl_xor_sync(FULL, mx, o));
            float sv = 0.f;
#pragma unroll
            for (int m2 = 0; m2 < 8; m2++) {
                float e = __expf(si[m2][qq] - mx);
                si[m2][qq] = e;
                sv += e;
            }
#pragma unroll
            for (int o = 16; o > 0; o >>= 1) sv += __shfl_xor_sync(FULL, sv, o);
            float inv = 1.f / sv;
#pragma unroll
            for (int m2 = 0; m2 < 8; m2++) si[m2][qq] *= inv;
        }

#pragma unroll
        for (int slot = 0; slot < 8; slot++) {
#pragma unroll 2
            for (int src = 0; src < 32; src++) {
                int j = slot * 32 + src;
                float v0 = vI[j * 64 + lane], v1 = vI[j * 64 + lane + 32];
#pragma unroll
                for (int qq = 0; qq < 4; qq++) {
                    float a = __shfl_sync(FULL, si[slot][qq], src);
                    o0[qq] = fmaf(a, v0, o0[qq]);
                    o1[qq] = fmaf(a, v1, o1[qq]);
                }
            }
        }

#pragma unroll
        for (int qq = 0; qq < 4; qq++) {
            size_t oi = ((size_t)(b * NQ_ + i0 + qq)) * DM_ + h * D_;
            outp[oi + lane] = o0[qq];
            outp[oi + lane + 32] = o1[qq];
        }
    }
}

// ---------------------------------------------------------------------------
// Host launcher
// ---------------------------------------------------------------------------
extern "C" void kernel_launch(void* const* d_in, const int* in_sizes, int n_in,
                              void* d_out, int out_size)
{
    const float* x     = (const float*)d_in[0];
    const float* ctx   = (const float*)d_in[1];
    const float* Wq    = (const float*)d_in[2];
    const float* Wk    = (const float*)d_in[3];
    const float* Wv    = (const float*)d_in[4];
    const float* Wk_ip = (const float*)d_in[5];
    const float* Wv_ip = (const float*)d_in[6];
    const float* Wout  = (const float*)d_in[7];
    const float* bout  = (const float*)d_in[8];
    const float* relk  = (const float*)d_in[9];
    const float* relv  = (const float*)d_in[10];
    float* out = (float*)d_out;

    float *pq, *patt, *pkt, *pvt, *pki, *pvi;
    __nv_bfloat16 *pahi, *palo, *pchi, *pclo, *pwhi, *pwlo;
    cudaGetSymbolAddress((void**)&pq,   g_q);
    cudaGetSymbolAddress((void**)&patt, g_att);
    cudaGetSymbolAddress((void**)&pkt,  g_kt);
    cudaGetSymbolAddress((void**)&pvt,  g_vt);
    cudaGetSymbolAddress((void**)&pki,  g_ki);
    cudaGetSymbolAddress((void**)&pvi,  g_vi);
    cudaGetSymbolAddress((void**)&pahi, g_ahi);
    cudaGetSymbolAddress((void**)&palo, g_alo);
    cudaGetSymbolAddress((void**)&pchi, g_chi);
    cudaGetSymbolAddress((void**)&pclo, g_clo);
    cudaGetSymbolAddress((void**)&pwhi, g_whi);
    cudaGetSymbolAddress((void**)&pwlo, g_wlo);

    cudaFuncSetAttribute(gemm_mma<false>,
                         cudaFuncAttributeMaxDynamicSharedMemorySize, GM_SMEM);
    cudaFuncSetAttribute(gemm_mma<true>,
                         cudaFuncAttributeMaxDynamicSharedMemorySize, GM_SMEM);
    cudaFuncSetAttribute(attn_kernel,
                         cudaFuncAttributeMaxDynamicSharedMemorySize, ATTN_SMEM_BYTES);

    const size_t WSZ = (size_t)DM_ * DM_;
    const float* Ws[6] = {Wq, Wk, Wv, Wk_ip, Wv_ip, Wout};
    for (int wi = 0; wi < 6; wi++)
        conv_wt<<<dim3(32, 32), dim3(32, 8)>>>(Ws[wi], pwhi + wi * WSZ, pwlo + wi * WSZ);

    {
        size_t n = (size_t)B_ * NQ_ * DM_;
        conv_rows<<<(unsigned)(n / 4 / 256), 256>>>(x, pahi, palo, n);
        size_t nc = (size_t)B_ * CTXR * DM_;
        conv_rows<<<(unsigned)((nc / 4 + 255) / 256), 256>>>(ctx, pchi, pclo, nc);
    }

    // Q = x @ Wq
    gemm_mma<false><<<dim3(8, 512), 256, GM_SMEM>>>(
        pahi, palo, pwhi + 0 * WSZ, pwlo + 0 * WSZ, pq, nullptr,
        B_ * NQ_, B_ * NQ_, B_ * NQ_, 0);

    // K/V text
    gemm_mma<true><<<dim3(8, 39), 256, GM_SMEM>>>(
        pchi, pclo, pwhi + 1 * WSZ, pwlo + 1 * WSZ, pkt, nullptr,
        B_ * LT_, LT_, CTXR, 0);
    gemm_mma<true><<<dim3(8, 39), 256, GM_SMEM>>>(
        pchi, pclo, pwhi + 2 * WSZ, pwlo + 2 * WSZ, pvt, nullptr,
        B_ * LT_, LT_, CTXR, 0);

    // K/V image
    gemm_mma<true><<<dim3(8, 128), 256, GM_SMEM>>>(
        pchi, pclo, pwhi + 3 * WSZ, pwlo + 3 * WSZ, pki, nullptr,
        B_ * LI_, LI_, CTXR, LT_);
    gemm_mma<true><<<dim3(8, 128), 256, GM_SMEM>>>(
        pchi, pclo, pwhi + 4 * WSZ, pwlo + 4 * WSZ, pvi, nullptr,
        B_ * LI_, LI_, CTXR, LT_);

    // attention
    attn_kernel<<<B_ * H_, 256, ATTN_SMEM_BYTES>>>(
        pq, pkt, pvt, pki, pvi, relk, relv, patt);

    // convert attention output, final projection + bias
    {
        size_t n = (size_t)B_ * NQ_ * DM_;
        conv_rows<<<(unsigned)(n / 4 / 256), 256>>>(patt, pahi, palo, n);
    }
    gemm_mma<false><<<dim3(8, 512), 256, GM_SMEM>>>(
        pahi, palo, pwhi + 5 * WSZ, pwlo + 5 * WSZ, out, bout,
        B_ * NQ_, B_ * NQ_, B_ * NQ_, 0);
}

// round 4
// speedup vs baseline: 1.5220x; 1.0020x over previous
#include <cuda_runtime.h>
#include <cuda_bf16.h>
#include <cstdint>

// ---------------------------------------------------------------------------
// Problem constants
// ---------------------------------------------------------------------------
#define B_    64
#define NQ_   1024
#define DM_   1024
#define H_    16
#define D_    64
#define LT_   77
#define LI_   256
#define NR_   33
#define RELCUT 92
#define CTXR  (LT_ + LI_)     // 333

__device__ __forceinline__ uint32_t smem_to_u32(const void* p) {
    uint32_t a;
    asm("{ .reg .u64 t; cvta.to.shared.u64 t, %1; cvt.u32.u64 %0, t; }"
        : "=r"(a) : "l"(p));
    return a;
}

#define CPA16(dst, src) \
    asm volatile("cp.async.cg.shared.global [%0], [%1], 16;" \
                 :: "r"(dst), "l"(src))
#define CPA_COMMIT() asm volatile("cp.async.commit_group;" ::: "memory")
#define CPA_WAIT(n)  asm volatile("cp.async.wait_group %0;" :: "n"(n) : "memory")

#define LDMX4(r0, r1, r2, r3, addr) \
    asm volatile("ldmatrix.sync.aligned.m8n8.x4.shared.b16 {%0,%1,%2,%3}, [%4];" \
                 : "=r"(r0), "=r"(r1), "=r"(r2), "=r"(r3) : "r"(addr))

#define MMA16816(c, a, b0, b1) \
    asm volatile("mma.sync.aligned.m16n8k16.row.col.f32.bf16.bf16.f32 " \
                 "{%0,%1,%2,%3}, {%4,%5,%6,%7}, {%8,%9}, {%0,%1,%2,%3};" \
                 : "+f"((c)[0]), "+f"((c)[1]), "+f"((c)[2]), "+f"((c)[3]) \
                 : "r"((a)[0]), "r"((a)[1]), "r"((a)[2]), "r"((a)[3]), \
                   "r"(b0), "r"(b1))

// ---------------------------------------------------------------------------
// Scratch (static device globals)
// ---------------------------------------------------------------------------
__device__ float g_q  [(size_t)B_ * NQ_ * DM_];
__device__ float g_att[(size_t)B_ * NQ_ * DM_];
__device__ float g_kt [(size_t)B_ * H_ * LT_ * D_];
__device__ float g_vt [(size_t)B_ * H_ * LT_ * D_];
__device__ float g_ki [(size_t)B_ * H_ * LI_ * D_];
__device__ float g_vi [(size_t)B_ * H_ * LI_ * D_];
__device__ __nv_bfloat16 g_ahi[(size_t)B_ * NQ_ * DM_];
__device__ __nv_bfloat16 g_alo[(size_t)B_ * NQ_ * DM_];
__device__ __nv_bfloat16 g_chi[(size_t)B_ * CTXR * DM_];
__device__ __nv_bfloat16 g_clo[(size_t)B_ * CTXR * DM_];
__device__ __nv_bfloat16 g_whi[6 * (size_t)DM_ * DM_];
__device__ __nv_bfloat16 g_wlo[6 * (size_t)DM_ * DM_];

// ---------------------------------------------------------------------------
// fp32 -> bf16 hi/lo split
// ---------------------------------------------------------------------------
__global__ void conv_rows(const float* __restrict__ src,
                          __nv_bfloat16* __restrict__ hi,
                          __nv_bfloat16* __restrict__ lo, size_t n)
{
    size_t i = ((size_t)blockIdx.x * blockDim.x + threadIdx.x) * 4;
    if (i >= n) return;
    float4 v = *(const float4*)(src + i);
    __nv_bfloat16 h0 = __float2bfloat16(v.x);
    __nv_bfloat16 h1 = __float2bfloat16(v.y);
    __nv_bfloat16 h2 = __float2bfloat16(v.z);
    __nv_bfloat16 h3 = __float2bfloat16(v.w);
    __nv_bfloat16 l0 = __float2bfloat16(v.x - __bfloat162float(h0));
    __nv_bfloat16 l1 = __float2bfloat16(v.y - __bfloat162float(h1));
    __nv_bfloat16 l2 = __float2bfloat16(v.z - __bfloat162float(h2));
    __nv_bfloat16 l3 = __float2bfloat16(v.w - __bfloat162float(h3));
    __nv_bfloat162 hp0 = {h0, h1}, hp1 = {h2, h3};
    __nv_bfloat162 lp0 = {l0, l1}, lp1 = {l2, l3};
    *(uint2*)(hi + i) = make_uint2(*(uint32_t*)&hp0, *(uint32_t*)&hp1);
    *(uint2*)(lo + i) = make_uint2(*(uint32_t*)&lp0, *(uint32_t*)&lp1);
}

// W [K=1024, N=1024] -> Wt hi/lo [N, K]
__global__ void conv_wt(const float* __restrict__ W,
                        __nv_bfloat16* __restrict__ hi,
                        __nv_bfloat16* __restrict__ lo)
{
    __shared__ float tile[32][33];
    const int k0 = blockIdx.y * 32, n0 = blockIdx.x * 32;
    const int tx = threadIdx.x;
    for (int r = threadIdx.y; r < 32; r += 8)
        tile[r][tx] = W[(size_t)(k0 + r) * DM_ + n0 + tx];
    __syncthreads();
    for (int r = threadIdx.y; r < 32; r += 8) {
        float v = tile[tx][r];
        __nv_bfloat16 h = __float2bfloat16(v);
        size_t oi = (size_t)(n0 + r) * DM_ + k0 + tx;
        hi[oi] = h;
        lo[oi] = __float2bfloat16(v - __bfloat162float(h));
    }
}

// ---------------------------------------------------------------------------
// bf16x3 GEMM via mma.sync: C[M,1024] = remap(A)[M,1024] @ B^T (B is [N,K])
// CTA 128x128, BK=32, 8 warps (warp tile 32x64), cp.async double buffer.
// smem per buffer: Ahi/Alo/Bhi/Blo each [128][40] bf16 (80B row stride).
// ---------------------------------------------------------------------------
#define BUF_BYTES   40960            // 4 * 128*40*2
#define GM_SMEM     (2 * BUF_BYTES)  // 81920

template <bool KV_STORE>
__global__ void __launch_bounds__(256, 1)
gemm_mma(const __nv_bfloat16* __restrict__ Ahi, const __nv_bfloat16* __restrict__ Alo,
         const __nv_bfloat16* __restrict__ Bhi, const __nv_bfloat16* __restrict__ Blo,
         float* __restrict__ C, const float* __restrict__ bias,
         int M, int rows_per_seg, int seg_stride, int seg_base)
{
    extern __shared__ __align__(128) char smem[];
    const uint32_t sb = smem_to_u32(smem);
    const int tid = threadIdx.x;
    const int bn = blockIdx.x * 128;
    const int bm = blockIdx.y * 128;
    const int wid = tid >> 5, lane = tid & 31;
    const int Wm = (wid & 3) * 32;
    const int Wn = (wid >> 2) * 64;

    // ---- cp.async load mapping: 2 threads/row, each 2x16B per operand ----
    const int lrow = tid >> 1;
    const int lc = tid & 1;
    int m = bm + lrow; if (m > M - 1) m = M - 1;
    const int seg = m / rows_per_seg;
    const int t = m - seg * rows_per_seg;
    const size_t aoff = (size_t)(seg * seg_stride + seg_base + t) * 1024 + lc * 16;
    const size_t boff = (size_t)(bn + lrow) * 1024 + lc * 16;
    const uint32_t soff = (uint32_t)lrow * 80u + (uint32_t)lc * 32u;

    float acc[2][8][4];
#pragma unroll
    for (int i = 0; i < 2; i++)
#pragma unroll
        for (int j = 0; j < 8; j++)
#pragma unroll
            for (int c = 0; c < 4; c++) acc[i][j][c] = 0.f;

    // ---- fragment addresses (fixed per thread; vary buffer + k16) ----
    const uint32_t a_frag_row = (uint32_t)(Wm + (lane & 15)) * 80u + ((lane >> 4) * 16u);
    const uint32_t b_frag_row =
        (uint32_t)(Wn + (lane & 7) + ((lane >> 4) << 3)) * 80u + (((lane >> 3) & 1) * 16u);

#define ISSUE(p, k0)                                                       \
    {                                                                      \
        uint32_t d = sb + (p) * BUF_BYTES + soff;                          \
        const __nv_bfloat16* s;                                            \
        s = Ahi + aoff + (k0); CPA16(d,           s); CPA16(d + 16,         s + 8); \
        s = Alo + aoff + (k0); CPA16(d + 10240,   s); CPA16(d + 10240 + 16, s + 8); \
        s = Bhi + boff + (k0); CPA16(d + 20480,   s); CPA16(d + 20480 + 16, s + 8); \
        s = Blo + boff + (k0); CPA16(d + 30720,   s); CPA16(d + 30720 + 16, s + 8); \
    }

    ISSUE(0, 0);
    CPA_COMMIT();

    for (int i = 0; i < 32; i++) {
        if (i + 1 < 32) {
            ISSUE((i + 1) & 1, (i + 1) * 32);
            CPA_COMMIT();
            CPA_WAIT(1);
        } else {
            CPA_WAIT(0);
        }
        __syncthreads();

        const uint32_t base = sb + (i & 1) * BUF_BYTES;
#pragma unroll
        for (int kk = 0; kk < 2; kk++) {
            uint32_t ah[2][4], al[2][4];
            const uint32_t ar = base + a_frag_row + kk * 32;
            LDMX4(ah[0][0], ah[0][1], ah[0][2], ah[0][3], ar);
            LDMX4(ah[1][0], ah[1][1], ah[1][2], ah[1][3], ar + 16 * 80);
            LDMX4(al[0][0], al[0][1], al[0][2], al[0][3], ar + 10240);
            LDMX4(al[1][0], al[1][1], al[1][2], al[1][3], ar + 10240 + 16 * 80);
#pragma unroll
            for (int j = 0; j < 4; j++) {
                uint32_t bh0, bh1, bh2, bh3, bl0, bl1, bl2, bl3;
                const uint32_t br = base + b_frag_row + kk * 32 + (uint32_t)j * (16 * 80);
                LDMX4(bh0, bh1, bh2, bh3, br + 20480);
                LDMX4(bl0, bl1, bl2, bl3, br + 30720);
#pragma unroll
                for (int mt = 0; mt < 2; mt++) {
                    MMA16816(acc[mt][2 * j],     ah[mt], bh0, bh1);
                    MMA16816(acc[mt][2 * j],     al[mt], bh0, bh1);
                    MMA16816(acc[mt][2 * j],     ah[mt], bl0, bl1);
                    MMA16816(acc[mt][2 * j + 1], ah[mt], bh2, bh3);
                    MMA16816(acc[mt][2 * j + 1], al[mt], bh2, bh3);
                    MMA16816(acc[mt][2 * j + 1], ah[mt], bl2, bl3);
                }
            }
        }
        __syncthreads();
    }
#undef ISSUE

    // ---- epilogue ----
    const int er = lane >> 2, ec = (lane & 3) * 2;
#pragma unroll
    for (int mt = 0; mt < 2; mt++) {
#pragma unroll
        for (int hrow = 0; hrow < 2; hrow++) {
            const int cm = bm + Wm + mt * 16 + er + hrow * 8;
            if (cm >= M) continue;
            if (KV_STORE) {
                const int segc = cm / rows_per_seg;
                const int tc = cm - segc * rows_per_seg;
#pragma unroll
                for (int nt = 0; nt < 8; nt++) {
                    const int cn = bn + Wn + nt * 8 + ec;
                    const int hh = cn >> 6, dd = cn & 63;
                    size_t oi = (((size_t)segc * H_ + hh) * rows_per_seg + tc) * 64 + dd;
                    C[oi]     = acc[mt][nt][hrow * 2];
                    C[oi + 1] = acc[mt][nt][hrow * 2 + 1];
                }
            } else {
                float* Cp = C + (size_t)cm * DM_ + bn + Wn + ec;
                if (bias) {
                    const float* bp = bias + bn + Wn + ec;
#pragma unroll
                    for (int nt = 0; nt < 8; nt++) {
                        float2 v = make_float2(acc[mt][nt][hrow * 2] + bp[nt * 8],
                                               acc[mt][nt][hrow * 2 + 1] + bp[nt * 8 + 1]);
                        *(float2*)(Cp + nt * 8) = v;
                    }
                } else {
#pragma unroll
                    for (int nt = 0; nt < 8; nt++) {
                        float2 v = make_float2(acc[mt][nt][hrow * 2],
                                               acc[mt][nt][hrow * 2 + 1]);
                        *(float2*)(Cp + nt * 8) = v;
                    }
                }
            }
        }
    }
}

// ---------------------------------------------------------------------------
// Attention kernel (unchanged — fp32, one CTA per (b,h))
// ---------------------------------------------------------------------------
__device__ __forceinline__ int relidx(int j, int i)
{
    int d = j - i;
    d = max(-16, min(16, d));
    return d + 16;
}

#define SM_KTT 0
#define SM_VT  (SM_KTT + 64 * 80)
#define SM_KTI (SM_VT + LT_ * 64)
#define SM_VI  (SM_KTI + 64 * 257)
#define SM_RKT (SM_VI + LI_ * 64)
#define SM_RV  (SM_RKT + 64 * NR_)
#define SM_P   (SM_RV + NR_ * 64)
#define SM_QB  (SM_P + 32 * 34)
#define SM_TOTAL_FLOATS (SM_QB + 32 * 64)
#define ATTN_SMEM_BYTES (SM_TOTAL_FLOATS * 4)

__global__ void __launch_bounds__(256, 1)
attn_kernel(const float* __restrict__ q,
            const float* __restrict__ kt, const float* __restrict__ vt,
            const float* __restrict__ ki, const float* __restrict__ vi,
            const float* __restrict__ relk, const float* __restrict__ relv,
            float* __restrict__ outp)
{
    extern __shared__ float sm[];
    float* kTt = sm + SM_KTT;
    float* vT  = sm + SM_VT;
    float* kTi = sm + SM_KTI;
    float* vI  = sm + SM_VI;
    float* rkT = sm + SM_RKT;
    float* rvS = sm + SM_RV;
    float* pS  = sm + SM_P;
    float* qb  = sm + SM_QB;

    const int bh = blockIdx.x;
    const int b = bh >> 4, h = bh & 15;
    const int tid = threadIdx.x, w = tid >> 5, lane = tid & 31;
    const float scale = 0.125f;
    const unsigned FULL = 0xffffffffu;

    {
        const float* Kt = kt + (size_t)bh * (LT_ * D_);
        const float* Vt = vt + (size_t)bh * (LT_ * D_);
        const float* Ki = ki + (size_t)bh * (LI_ * D_);
        const float* Vi = vi + (size_t)bh * (LI_ * D_);
        for (int idx = tid; idx < LT_ * D_; idx += 256) {
            int t = idx >> 6, d = idx & 63;
            kTt[d * 80 + t] = Kt[idx];
            vT[idx] = Vt[idx];
        }
        for (int idx = tid; idx < LI_ * D_; idx += 256) {
            int t = idx >> 6, d = idx & 63;
            kTi[d * 257 + t] = Ki[idx];
            vI[idx] = Vi[idx];
        }
        for (int idx = tid; idx < NR_ * D_; idx += 256) {
            int r = idx >> 6, d = idx & 63;
            rkT[d * NR_ + r] = relk[idx];
            rvS[idx] = relv[idx];
        }
    }
    __syncthreads();

    const bool j2ok = (lane < (LT_ - 64));

    for (int it = 0; it < NQ_ / 32; ++it) {
        const int i0 = (it * 8 + w) * 4;
        __syncwarp();
        {
            const float* qg = q + ((size_t)(b * NQ_ + i0)) * DM_ + h * D_;
#pragma unroll
            for (int s = 0; s < 8; s++) {
                int e = s * 32 + lane;
                int qq = e >> 6, d = e & 63;
                qb[(w * 4 + qq) * 64 + d] = qg[(size_t)qq * DM_ + d];
            }
        }
        __syncwarp();
        const float* qw = qb + w * 4 * 64;

        float st0[4] = {0, 0, 0, 0}, st1[4] = {0, 0, 0, 0}, st2[4] = {0, 0, 0, 0};
        float sp0[4] = {0, 0, 0, 0}, sp1[4] = {0, 0, 0, 0};
#pragma unroll 8
        for (int d = 0; d < 64; d++) {
            float k0 = kTt[d * 80 + lane];
            float k1 = kTt[d * 80 + lane + 32];
            float k2 = j2ok ? kTt[d * 80 + lane + 64] : 0.f;
            float r0 = rkT[d * NR_ + lane];
            float r1 = (lane == 0) ? rkT[d * NR_ + 32] : 0.f;
#pragma unroll
            for (int qq = 0; qq < 4; qq++) {
                float qd = qw[qq * 64 + d];
                st0[qq] = fmaf(qd, k0, st0[qq]);
                st1[qq] = fmaf(qd, k1, st1[qq]);
                st2[qq] = fmaf(qd, k2, st2[qq]);
                sp0[qq] = fmaf(qd, r0, sp0[qq]);
                sp1[qq] = fmaf(qd, r1, sp1[qq]);
            }
        }
#pragma unroll
        for (int qq = 0; qq < 4; qq++) {
            pS[(w * 4 + qq) * 34 + lane] = sp0[qq];
            if (lane == 0) pS[(w * 4 + qq) * 34 + 32] = sp1[qq];
        }
        __syncwarp();

        float at0[4], at1[4], at2[4];
#pragma unroll
        for (int qq = 0; qq < 4; qq++) {
            const int iq = i0 + qq;
            float s0, s1, s2;
            if (iq >= RELCUT) {
                s0 = st0[qq] * scale;
                s1 = st1[qq] * scale;
                s2 = j2ok ? st2[qq] * scale : -1e30f;
            } else {
                const float* pp = pS + (w * 4 + qq) * 34;
                s0 = (st0[qq] + pp[relidx(lane, iq)]) * scale;
                s1 = (st1[qq] + pp[relidx(lane + 32, iq)]) * scale;
                s2 = j2ok ? (st2[qq] + pp[relidx(lane + 64, iq)]) * scale : -1e30f;
            }
            float mx = fmaxf(s0, fmaxf(s1, s2));
#pragma unroll
            for (int o = 16; o > 0; o >>= 1) mx = fmaxf(mx, __shfl_xor_sync(FULL, mx, o));
            float e0 = __expf(s0 - mx);
            float e1 = __expf(s1 - mx);
            float e2 = j2ok ? __expf(s2 - mx) : 0.f;
            float sv = e0 + e1 + e2;
#pragma unroll
            for (int o = 16; o > 0; o >>= 1) sv += __shfl_xor_sync(FULL, sv, o);
            float inv = 1.f / sv;
            at0[qq] = e0 * inv; at1[qq] = e1 * inv; at2[qq] = e2 * inv;
        }

        float o0[4] = {0, 0, 0, 0}, o1[4] = {0, 0, 0, 0};
        const bool anyrel = (i0 < RELCUT);

#define TEXT_V_STEP(AT, J, SRC)                                           \
        {                                                                 \
            float v0 = vT[(J) * 64 + lane], v1 = vT[(J) * 64 + lane + 32];\
            _Pragma("unroll")                                             \
            for (int qq = 0; qq < 4; qq++) {                              \
                float a = __shfl_sync(FULL, AT[qq], (SRC));               \
                o0[qq] = fmaf(a, v0, o0[qq]);                             \
                o1[qq] = fmaf(a, v1, o1[qq]);                             \
                if (anyrel && (i0 + qq) < RELCUT) {                       \
                    int rr = relidx((J), i0 + qq);                        \
                    o0[qq] = fmaf(a, rvS[rr * 64 + lane], o0[qq]);        \
                    o1[qq] = fmaf(a, rvS[rr * 64 + lane + 32], o1[qq]);   \
                }                                                         \
            }                                                             \
        }

#pragma unroll 2
        for (int src = 0; src < 32; src++) TEXT_V_STEP(at0, src, src)
#pragma unroll 2
        for (int src = 0; src < 32; src++) TEXT_V_STEP(at1, 32 + src, src)
#pragma unroll
        for (int src = 0; src < 13; src++) TEXT_V_STEP(at2, 64 + src, src)
#undef TEXT_V_STEP

#pragma unroll
        for (int qq = 0; qq < 4; qq++) {
            if (i0 + qq >= RELCUT) {
                o0[qq] += rvS[lane];
                o1[qq] += rvS[lane + 32];
            }
        }

        float si[8][4];
#pragma unroll
        for (int m2 = 0; m2 < 8; m2++)
#pragma unroll
            for (int qq = 0; qq < 4; qq++) si[m2][qq] = 0.f;

#pragma unroll 4
        for (int d = 0; d < 64; d++) {
            float kk[8];
#pragma unroll
            for (int m2 = 0; m2 < 8; m2++) kk[m2] = kTi[d * 257 + m2 * 32 + lane];
#pragma unroll
            for (int qq = 0; qq < 4; qq++) {
                float qd = qw[qq * 64 + d];
#pragma unroll
                for (int m2 = 0; m2 < 8; m2++)
                    si[m2][qq] = fmaf(qd, kk[m2], si[m2][qq]);
            }
        }

#pragma unroll
        for (int qq = 0; qq < 4; qq++) {
            float mx = -1e30f;
#pragma unroll
            for (int m2 = 0; m2 < 8; m2++) {
                si[m2][qq] *= scale;
                mx = fmaxf(mx, si[m2][qq]);
            }
#pragma unroll
            for (int o = 16; o > 0; o >>= 1) mx = fmaxf(mx, __shfl_xor_sync(FULL, mx, o));
            float sv = 0.f;
#pragma unroll
            for (int m2 = 0; m2 < 8; m2++) {
                float e = __expf(si[m2][qq] - mx);
                si[m2][qq] = e;
                sv += e;
            }
#pragma unroll
            for (int o = 16; o > 0; o >>= 1) sv += __shfl_xor_sync(FULL, sv, o);
            float inv = 1.f / sv;
#pragma unroll
            for (int m2 = 0; m2 < 8; m2++) si[m2][qq] *= inv;
        }

#pragma unroll
        for (int slot = 0; slot < 8; slot++) {
#pragma unroll 2
            for (int src = 0; src < 32; src++) {
                int j = slot * 32 + src;
                float v0 = vI[j * 64 + lane], v1 = vI[j * 64 + lane + 32];
#pragma unroll
                for (int qq = 0; qq < 4; qq++) {
                    float a = __shfl_sync(FULL, si[slot][qq], src);
                    o0[qq] = fmaf(a, v0, o0[qq]);
                    o1[qq] = fmaf(a, v1, o1[qq]);
                }
            }
        }

#pragma unroll
        for (int qq = 0; qq < 4; qq++) {
            size_t oi = ((size_t)(b * NQ_ + i0 + qq)) * DM_ + h * D_;
            outp[oi + lane] = o0[qq];
            outp[oi + lane + 32] = o1[qq];
        }
    }
}

// ---------------------------------------------------------------------------
// Host launcher
// ---------------------------------------------------------------------------
extern "C" void kernel_launch(void* const* d_in, const int* in_sizes, int n_in,
                              void* d_out, int out_size)
{
    const float* x     = (const float*)d_in[0];
    const float* ctx   = (const float*)d_in[1];
    const float* Wq    = (const float*)d_in[2];
    const float* Wk    = (const float*)d_in[3];
    const float* Wv    = (const float*)d_in[4];
    const float* Wk_ip = (const float*)d_in[5];
    const float* Wv_ip = (const float*)d_in[6];
    const float* Wout  = (const float*)d_in[7];
    const float* bout  = (const float*)d_in[8];
    const float* relk  = (const float*)d_in[9];
    const float* relv  = (const float*)d_in[10];
    float* out = (float*)d_out;

    float *pq, *patt, *pkt, *pvt, *pki, *pvi;
    __nv_bfloat16 *pahi, *palo, *pchi, *pclo, *pwhi, *pwlo;
    cudaGetSymbolAddress((void**)&pq,   g_q);
    cudaGetSymbolAddress((void**)&patt, g_att);
    cudaGetSymbolAddress((void**)&pkt,  g_kt);
    cudaGetSymbolAddress((void**)&pvt,  g_vt);
    cudaGetSymbolAddress((void**)&pki,  g_ki);
    cudaGetSymbolAddress((void**)&pvi,  g_vi);
    cudaGetSymbolAddress((void**)&pahi, g_ahi);
    cudaGetSymbolAddress((void**)&palo, g_alo);
    cudaGetSymbolAddress((void**)&pchi, g_chi);
    cudaGetSymbolAddress((void**)&pclo, g_clo);
    cudaGetSymbolAddress((void**)&pwhi, g_whi);
    cudaGetSymbolAddress((void**)&pwlo, g_wlo);

    cudaFuncSetAttribute(gemm_mma<false>,
                         cudaFuncAttributeMaxDynamicSharedMemorySize, GM_SMEM);
    cudaFuncSetAttribute(gemm_mma<true>,
                         cudaFuncAttributeMaxDynamicSharedMemorySize, GM_SMEM);
    cudaFuncSetAttribute(attn_kernel,
                         cudaFuncAttributeMaxDynamicSharedMemorySize, ATTN_SMEM_BYTES);

    const size_t WSZ = (size_t)DM_ * DM_;
    const float* Ws[6] = {Wq, Wk, Wv, Wk_ip, Wv_ip, Wout};
    for (int wi = 0; wi < 6; wi++)
        conv_wt<<<dim3(32, 32), dim3(32, 8)>>>(Ws[wi], pwhi + wi * WSZ, pwlo + wi * WSZ);

    {
        size_t n = (size_t)B_ * NQ_ * DM_;
        conv_rows<<<(unsigned)(n / 4 / 256), 256>>>(x, pahi, palo, n);
        size_t nc = (size_t)B_ * CTXR * DM_;
        conv_rows<<<(unsigned)((nc / 4 + 255) / 256), 256>>>(ctx, pchi, pclo, nc);
    }

    // Q = x @ Wq
    gemm_mma<false><<<dim3(8, 512), 256, GM_SMEM>>>(
        pahi, palo, pwhi + 0 * WSZ, pwlo + 0 * WSZ, pq, nullptr,
        B_ * NQ_, B_ * NQ_, B_ * NQ_, 0);

    // K/V text
    gemm_mma<true><<<dim3(8, 39), 256, GM_SMEM>>>(
        pchi, pclo, pwhi + 1 * WSZ, pwlo + 1 * WSZ, pkt, nullptr,
        B_ * LT_, LT_, CTXR, 0);
    gemm_mma<true><<<dim3(8, 39), 256, GM_SMEM>>>(
        pchi, pclo, pwhi + 2 * WSZ, pwlo + 2 * WSZ, pvt, nullptr,
        B_ * LT_, LT_, CTXR, 0);

    // K/V image
    gemm_mma<true><<<dim3(8, 128), 256, GM_SMEM>>>(
        pchi, pclo, pwhi + 3 * WSZ, pwlo + 3 * WSZ, pki, nullptr,
        B_ * LI_, LI_, CTXR, LT_);
    gemm_mma<true><<<dim3(8, 128), 256, GM_SMEM>>>(
        pchi, pclo, pwhi + 4 * WSZ, pwlo + 4 * WSZ, pvi, nullptr,
        B_ * LI_, LI_, CTXR, LT_);

    // attention
    attn_kernel<<<B_ * H_, 256, ATTN_SMEM_BYTES>>>(
        pq, pkt, pvt, pki, pvi, relk, relv, patt);

    // convert attention output, final projection + bias
    {
        size_t n = (size_t)B_ * NQ_ * DM_;
        conv_rows<<<(unsigned)(n / 4 / 256), 256>>>(patt, pahi, palo, n);
    }
    gemm_mma<false><<<dim3(8, 512), 256, GM_SMEM>>>(
        pahi, palo, pwhi + 5 * WSZ, pwlo + 5 * WSZ, out, bout,
        B_ * NQ_, B_ * NQ_, B_ * NQ_, 0);
}

// round 5
// speedup vs baseline: 2.7895x; 1.8328x over previous
#include <cuda_runtime.h>
#include <cuda_bf16.h>
#include <cstdint>

// ---------------------------------------------------------------------------
// Problem constants
// ---------------------------------------------------------------------------
#define B_    64
#define NQ_   1024
#define DM_   1024
#define H_    16
#define D_    64
#define LT_   77
#define LI_   256
#define NR_   33
#define CTXR  (LT_ + LI_)     // 333

__device__ __forceinline__ uint32_t smem_to_u32(const void* p) {
    uint32_t a;
    asm("{ .reg .u64 t; cvta.to.shared.u64 t, %1; cvt.u32.u64 %0, t; }"
        : "=r"(a) : "l"(p));
    return a;
}

#define CPA16(dst, src) \
    asm volatile("cp.async.cg.shared.global [%0], [%1], 16;" \
                 :: "r"(dst), "l"(src))
#define CPA_COMMIT() asm volatile("cp.async.commit_group;" ::: "memory")
#define CPA_WAIT(n)  asm volatile("cp.async.wait_group %0;" :: "n"(n) : "memory")

#define LDMX4(r0, r1, r2, r3, addr) \
    asm volatile("ldmatrix.sync.aligned.m8n8.x4.shared.b16 {%0,%1,%2,%3}, [%4];" \
                 : "=r"(r0), "=r"(r1), "=r"(r2), "=r"(r3) : "r"(addr))
#define LDMX4T(r0, r1, r2, r3, addr) \
    asm volatile("ldmatrix.sync.aligned.m8n8.x4.trans.shared.b16 {%0,%1,%2,%3}, [%4];" \
                 : "=r"(r0), "=r"(r1), "=r"(r2), "=r"(r3) : "r"(addr))

#define MMA16816(c, a, b0, b1) \
    asm volatile("mma.sync.aligned.m16n8k16.row.col.f32.bf16.bf16.f32 " \
                 "{%0,%1,%2,%3}, {%4,%5,%6,%7}, {%8,%9}, {%0,%1,%2,%3};" \
                 : "+f"((c)[0]), "+f"((c)[1]), "+f"((c)[2]), "+f"((c)[3]) \
                 : "r"((a)[0]), "r"((a)[1]), "r"((a)[2]), "r"((a)[3]), \
                   "r"(b0), "r"(b1))

__device__ __forceinline__ uint32_t packbf(float lo, float hi) {
    uint32_t d;
    asm("cvt.rn.bf16x2.f32 %0, %1, %2;" : "=r"(d) : "f"(hi), "f"(lo));
    return d;
}

// ---------------------------------------------------------------------------
// Scratch (static device globals)
// ---------------------------------------------------------------------------
__device__ __nv_bfloat16 g_ahi[(size_t)B_ * NQ_ * DM_];  // x hi, later att hi
__device__ __nv_bfloat16 g_alo[(size_t)B_ * NQ_ * DM_];
__device__ __nv_bfloat16 g_qhi[(size_t)B_ * NQ_ * DM_];
__device__ __nv_bfloat16 g_qlo[(size_t)B_ * NQ_ * DM_];
__device__ __nv_bfloat16 g_chi[(size_t)B_ * CTXR * DM_];
__device__ __nv_bfloat16 g_clo[(size_t)B_ * CTXR * DM_];
__device__ __nv_bfloat16 g_whi[6 * (size_t)DM_ * DM_];
__device__ __nv_bfloat16 g_wlo[6 * (size_t)DM_ * DM_];
__device__ __nv_bfloat16 g_kthi[(size_t)B_ * H_ * LT_ * D_];
__device__ __nv_bfloat16 g_ktlo[(size_t)B_ * H_ * LT_ * D_];
__device__ __nv_bfloat16 g_vthi[(size_t)B_ * H_ * LT_ * D_];
__device__ __nv_bfloat16 g_vtlo[(size_t)B_ * H_ * LT_ * D_];
__device__ __nv_bfloat16 g_kihi[(size_t)B_ * H_ * LI_ * D_];
__device__ __nv_bfloat16 g_kilo[(size_t)B_ * H_ * LI_ * D_];
__device__ __nv_bfloat16 g_vihi[(size_t)B_ * H_ * LI_ * D_];
__device__ __nv_bfloat16 g_vilo[(size_t)B_ * H_ * LI_ * D_];

// ---------------------------------------------------------------------------
// fp32 -> bf16 hi/lo split
// ---------------------------------------------------------------------------
__global__ void conv_rows(const float* __restrict__ src,
                          __nv_bfloat16* __restrict__ hi,
                          __nv_bfloat16* __restrict__ lo, size_t n)
{
    size_t i = ((size_t)blockIdx.x * blockDim.x + threadIdx.x) * 4;
    if (i >= n) return;
    float4 v = *(const float4*)(src + i);
    float h0 = __bfloat162float(__float2bfloat16(v.x));
    float h1 = __bfloat162float(__float2bfloat16(v.y));
    float h2 = __bfloat162float(__float2bfloat16(v.z));
    float h3 = __bfloat162float(__float2bfloat16(v.w));
    *(uint2*)(hi + i) = make_uint2(packbf(h0, h1), packbf(h2, h3));
    *(uint2*)(lo + i) = make_uint2(packbf(v.x - h0, v.y - h1),
                                   packbf(v.z - h2, v.w - h3));
}

// W [K=1024, N=1024] -> Wt hi/lo [N, K]
__global__ void conv_wt(const float* __restrict__ W,
                        __nv_bfloat16* __restrict__ hi,
                        __nv_bfloat16* __restrict__ lo)
{
    __shared__ float tile[32][33];
    const int k0 = blockIdx.y * 32, n0 = blockIdx.x * 32;
    const int tx = threadIdx.x;
    for (int r = threadIdx.y; r < 32; r += 8)
        tile[r][tx] = W[(size_t)(k0 + r) * DM_ + n0 + tx];
    __syncthreads();
    for (int r = threadIdx.y; r < 32; r += 8) {
        float v = tile[tx][r];
        __nv_bfloat16 h = __float2bfloat16(v);
        size_t oi = (size_t)(n0 + r) * DM_ + k0 + tx;
        hi[oi] = h;
        lo[oi] = __float2bfloat16(v - __bfloat162float(h));
    }
}

// ---------------------------------------------------------------------------
// bf16x3 GEMM via mma.sync: C[M,1024] = remap(A)[M,1024] @ B^T (B is [N,K])
// MODE 0: fp32 C + bias.  MODE 1: KV scatter bf16 hi/lo to [b][h][t][d].
// MODE 2: Q row-major bf16 hi/lo, scaled by 0.125.
// ---------------------------------------------------------------------------
#define BUF_BYTES   40960
#define GM_SMEM     (2 * BUF_BYTES)

template <int MODE>
__global__ void __launch_bounds__(256, 1)
gemm_mma(const __nv_bfloat16* __restrict__ Ahi, const __nv_bfloat16* __restrict__ Alo,
         const __nv_bfloat16* __restrict__ Bhi, const __nv_bfloat16* __restrict__ Blo,
         float* __restrict__ C, const float* __restrict__ bias,
         __nv_bfloat16* __restrict__ Chi, __nv_bfloat16* __restrict__ Clo,
         int M, int rows_per_seg, int seg_stride, int seg_base)
{
    extern __shared__ __align__(128) char smem[];
    const uint32_t sb = smem_to_u32(smem);
    const int tid = threadIdx.x;
    const int bn = blockIdx.x * 128;
    const int bm = blockIdx.y * 128;
    const int wid = tid >> 5, lane = tid & 31;
    const int Wm = (wid & 3) * 32;
    const int Wn = (wid >> 2) * 64;

    const int lrow = tid >> 1;
    const int lc = tid & 1;
    int m = bm + lrow; if (m > M - 1) m = M - 1;
    const int seg = m / rows_per_seg;
    const int t = m - seg * rows_per_seg;
    const size_t aoff = (size_t)(seg * seg_stride + seg_base + t) * 1024 + lc * 16;
    const size_t boff = (size_t)(bn + lrow) * 1024 + lc * 16;
    const uint32_t soff = (uint32_t)lrow * 80u + (uint32_t)lc * 32u;

    float acc[2][8][4];
#pragma unroll
    for (int i = 0; i < 2; i++)
#pragma unroll
        for (int j = 0; j < 8; j++)
#pragma unroll
            for (int c = 0; c < 4; c++) acc[i][j][c] = 0.f;

    const uint32_t a_frag_row = (uint32_t)(Wm + (lane & 15)) * 80u + ((lane >> 4) * 16u);
    const uint32_t b_frag_row =
        (uint32_t)(Wn + (lane & 7) + ((lane >> 4) << 3)) * 80u + (((lane >> 3) & 1) * 16u);

#define ISSUE(p, k0)                                                       \
    {                                                                      \
        uint32_t d = sb + (p) * BUF_BYTES + soff;                          \
        const __nv_bfloat16* s;                                            \
        s = Ahi + aoff + (k0); CPA16(d,           s); CPA16(d + 16,         s + 8); \
        s = Alo + aoff + (k0); CPA16(d + 10240,   s); CPA16(d + 10240 + 16, s + 8); \
        s = Bhi + boff + (k0); CPA16(d + 20480,   s); CPA16(d + 20480 + 16, s + 8); \
        s = Blo + boff + (k0); CPA16(d + 30720,   s); CPA16(d + 30720 + 16, s + 8); \
    }

    ISSUE(0, 0);
    CPA_COMMIT();

    for (int i = 0; i < 32; i++) {
        if (i + 1 < 32) {
            ISSUE((i + 1) & 1, (i + 1) * 32);
            CPA_COMMIT();
            CPA_WAIT(1);
        } else {
            CPA_WAIT(0);
        }
        __syncthreads();

        const uint32_t base = sb + (i & 1) * BUF_BYTES;
#pragma unroll
        for (int kk = 0; kk < 2; kk++) {
            uint32_t ah[2][4], al[2][4];
            const uint32_t ar = base + a_frag_row + kk * 32;
            LDMX4(ah[0][0], ah[0][1], ah[0][2], ah[0][3], ar);
            LDMX4(ah[1][0], ah[1][1], ah[1][2], ah[1][3], ar + 16 * 80);
            LDMX4(al[0][0], al[0][1], al[0][2], al[0][3], ar + 10240);
            LDMX4(al[1][0], al[1][1], al[1][2], al[1][3], ar + 10240 + 16 * 80);
#pragma unroll
            for (int j = 0; j < 4; j++) {
                uint32_t bh0, bh1, bh2, bh3, bl0, bl1, bl2, bl3;
                const uint32_t br = base + b_frag_row + kk * 32 + (uint32_t)j * (16 * 80);
                LDMX4(bh0, bh1, bh2, bh3, br + 20480);
                LDMX4(bl0, bl1, bl2, bl3, br + 30720);
#pragma unroll
                for (int mt = 0; mt < 2; mt++) {
                    MMA16816(acc[mt][2 * j],     ah[mt], bh0, bh1);
                    MMA16816(acc[mt][2 * j],     al[mt], bh0, bh1);
                    MMA16816(acc[mt][2 * j],     ah[mt], bl0, bl1);
                    MMA16816(acc[mt][2 * j + 1], ah[mt], bh2, bh3);
                    MMA16816(acc[mt][2 * j + 1], al[mt], bh2, bh3);
                    MMA16816(acc[mt][2 * j + 1], ah[mt], bl2, bl3);
                }
            }
        }
        __syncthreads();
    }
#undef ISSUE

    const int er = lane >> 2, ec = (lane & 3) * 2;
#pragma unroll
    for (int mt = 0; mt < 2; mt++) {
#pragma unroll
        for (int hrow = 0; hrow < 2; hrow++) {
            const int cm = bm + Wm + mt * 16 + er + hrow * 8;
            if (cm >= M) continue;
            if (MODE == 1) {
                const int segc = cm / rows_per_seg;
                const int tc = cm - segc * rows_per_seg;
#pragma unroll
                for (int nt = 0; nt < 8; nt++) {
                    const int cn = bn + Wn + nt * 8 + ec;
                    const int hh = cn >> 6, dd = cn & 63;
                    size_t oi = (((size_t)segc * H_ + hh) * rows_per_seg + tc) * 64 + dd;
                    float v0 = acc[mt][nt][hrow * 2], v1 = acc[mt][nt][hrow * 2 + 1];
                    float h0 = __bfloat162float(__float2bfloat16(v0));
                    float h1 = __bfloat162float(__float2bfloat16(v1));
                    *(uint32_t*)(Chi + oi) = packbf(h0, h1);
                    *(uint32_t*)(Clo + oi) = packbf(v0 - h0, v1 - h1);
                }
            } else if (MODE == 2) {
#pragma unroll
                for (int nt = 0; nt < 8; nt++) {
                    const int cn = bn + Wn + nt * 8 + ec;
                    size_t oi = (size_t)cm * DM_ + cn;
                    float v0 = acc[mt][nt][hrow * 2] * 0.125f;
                    float v1 = acc[mt][nt][hrow * 2 + 1] * 0.125f;
                    float h0 = __bfloat162float(__float2bfloat16(v0));
                    float h1 = __bfloat162float(__float2bfloat16(v1));
                    *(uint32_t*)(Chi + oi) = packbf(h0, h1);
                    *(uint32_t*)(Clo + oi) = packbf(v0 - h0, v1 - h1);
                }
            } else {
                float* Cp = C + (size_t)cm * DM_ + bn + Wn + ec;
                const float* bp = bias + bn + Wn + ec;
#pragma unroll
                for (int nt = 0; nt < 8; nt++) {
                    float2 v = make_float2(acc[mt][nt][hrow * 2] + bp[nt * 8],
                                           acc[mt][nt][hrow * 2 + 1] + bp[nt * 8 + 1]);
                    *(float2*)(Cp + nt * 8) = v;
                }
            }
        }
    }
}

// ---------------------------------------------------------------------------
// Tensor-core flash attention. One CTA = (b, h, 128-query tile).
// 8 warps x 16 rows. K/V rows: text 0..76 (pad 77..79 zero), image 80..335.
// All tiles bf16 hi/lo, row stride 144 bytes (64 elems + 8 pad).
// ---------------------------------------------------------------------------
#define AT_KHI 0
#define AT_KLO 48384
#define AT_VHI 96768
#define AT_VLO 145152
#define AT_QHI 193536
#define AT_QLO 211968
#define AT_PS  193536            /* fp32 [128][34], reuses QHI after frag load */
#define AT_RKH 211968            /* relk hi (reuses QLO) */
#define AT_RKL 217728
#define AT_SMEM 230400

__device__ __forceinline__ int bidx(int j, int i)
{
    int d = j - i;
    d = max(-16, min(16, d));
    return d + 16;
}

__device__ __forceinline__ void wsplit(const float* s0, const float* s1,
                                       uint32_t* ahi, uint32_t* alo)
{
    float v[8] = {s0[0], s0[1], s0[2], s0[3], s1[0], s1[1], s1[2], s1[3]};
    float hv[8];
#pragma unroll
    for (int i = 0; i < 8; i++)
        hv[i] = __bfloat162float(__float2bfloat16(v[i]));
    ahi[0] = packbf(hv[0], hv[1]); ahi[1] = packbf(hv[2], hv[3]);
    ahi[2] = packbf(hv[4], hv[5]); ahi[3] = packbf(hv[6], hv[7]);
    alo[0] = packbf(v[0] - hv[0], v[1] - hv[1]);
    alo[1] = packbf(v[2] - hv[2], v[3] - hv[3]);
    alo[2] = packbf(v[4] - hv[4], v[5] - hv[5]);
    alo[3] = packbf(v[6] - hv[6], v[7] - hv[7]);
}

__global__ void __launch_bounds__(256, 1)
attn_mma(const __nv_bfloat16* __restrict__ qhi, const __nv_bfloat16* __restrict__ qlo,
         const __nv_bfloat16* __restrict__ kthi, const __nv_bfloat16* __restrict__ ktlo,
         const __nv_bfloat16* __restrict__ vthi, const __nv_bfloat16* __restrict__ vtlo,
         const __nv_bfloat16* __restrict__ kihi, const __nv_bfloat16* __restrict__ kilo,
         const __nv_bfloat16* __restrict__ vihi, const __nv_bfloat16* __restrict__ vilo,
         const float* __restrict__ relk, const float* __restrict__ relv,
         __nv_bfloat16* __restrict__ atthi, __nv_bfloat16* __restrict__ attlo)
{
    extern __shared__ __align__(128) char sm[];
    const uint32_t sb = smem_to_u32(sm);
    const int tid = threadIdx.x, w = tid >> 5, lane = tid & 31;
    const int bh = blockIdx.x >> 3, qt = blockIdx.x & 7;
    const int b = bh >> 4, h = bh & 15;
    const int i0 = qt * 128;
    const unsigned FULL = 0xffffffffu;

    // ---- stage K/V/Q ----
    {
        size_t tb = (size_t)bh * (LT_ * 64);
        for (int idx = tid; idx < LT_ * 8; idx += 256) {
            int r = idx >> 3, c = idx & 7;
            uint32_t d = (uint32_t)r * 144 + c * 16;
            size_t s = tb + (size_t)r * 64 + c * 8;
            CPA16(sb + AT_KHI + d, kthi + s);
            CPA16(sb + AT_KLO + d, ktlo + s);
            CPA16(sb + AT_VHI + d, vthi + s);
            CPA16(sb + AT_VLO + d, vtlo + s);
        }
        size_t ib = (size_t)bh * (LI_ * 64);
        for (int idx = tid; idx < LI_ * 8; idx += 256) {
            int r = idx >> 3, c = idx & 7;
            uint32_t d = (uint32_t)(80 + r) * 144 + c * 16;
            size_t s = ib + (size_t)r * 64 + c * 8;
            CPA16(sb + AT_KHI + d, kihi + s);
            CPA16(sb + AT_KLO + d, kilo + s);
            CPA16(sb + AT_VHI + d, vihi + s);
            CPA16(sb + AT_VLO + d, vilo + s);
        }
        size_t qb = ((size_t)(b * NQ_ + i0)) * 1024 + h * 64;
        for (int idx = tid; idx < 128 * 8; idx += 256) {
            int r = idx >> 3, c = idx & 7;
            uint32_t d = (uint32_t)r * 144 + c * 16;
            size_t s = qb + (size_t)r * 1024 + c * 8;
            CPA16(sb + AT_QHI + d, qhi + s);
            CPA16(sb + AT_QLO + d, qlo + s);
        }
        for (int idx = tid; idx < 3 * 36; idx += 256) {
            uint32_t d = (uint32_t)(77 + idx / 36) * 144 + (idx % 36) * 4;
            *(uint32_t*)(sm + AT_KHI + d) = 0;
            *(uint32_t*)(sm + AT_KLO + d) = 0;
            *(uint32_t*)(sm + AT_VHI + d) = 0;
            *(uint32_t*)(sm + AT_VLO + d) = 0;
        }
        CPA_COMMIT();
        CPA_WAIT(0);
        __syncthreads();
    }

    const int wr = w * 16;
    const int r0l = wr + (lane >> 2);        // this thread's rows: r0l, r0l+8

    // ---- Q fragments (A operand, 4 k16-steps) ----
    uint32_t qh[4][4], ql[4][4];
    {
        int row = wr + (lane & 15);
        int kb = (lane >> 4) * 16;            // byte offset within k16 chunk
#pragma unroll
        for (int kk = 0; kk < 4; kk++) {
            uint32_t a = sb + AT_QHI + (uint32_t)row * 144 + kk * 32 + kb;
            LDMX4(qh[kk][0], qh[kk][1], qh[kk][2], qh[kk][3], a);
            LDMX4(ql[kk][0], ql[kk][1], ql[kk][2], ql[kk][3], a + (AT_QLO - AT_QHI));
        }
    }
    __syncthreads();   // Q smem regions now reusable

    // ---- stage relk hi/lo into reused QLO region (tile 0 only) ----
    if (qt == 0) {
        for (int idx = tid; idx < NR_ * 64; idx += 256) {
            int r = idx >> 6, dc = idx & 63;
            float v = relk[idx];
            float hh = __bfloat162float(__float2bfloat16(v));
            *(__nv_bfloat16*)(sm + AT_RKH + r * 144 + dc * 2) = __float2bfloat16(hh);
            *(__nv_bfloat16*)(sm + AT_RKL + r * 144 + dc * 2) = __float2bfloat16(v - hh);
        }
    }
    __syncthreads();

    float* pS = (float*)(sm + AT_PS);   // [128][34]

    const int brow = ((lane >> 4) << 3) + (lane & 7);
    const int bdb = (lane & 8) * 2;     // byte offset 0/16 within k16 chunk

    // ---- rel-K projections p[i][bucket] (tile 0) ----
    if (qt == 0) {
        float pr[5][4];
#pragma unroll
        for (int i = 0; i < 5; i++)
#pragma unroll
            for (int c = 0; c < 4; c++) pr[i][c] = 0.f;
#pragma unroll
        for (int kk = 0; kk < 4; kk++) {
#pragma unroll
            for (int p2 = 0; p2 < 3; p2++) {
                uint32_t bh4[4], bl4[4];
                uint32_t ad = sb + AT_RKH + (uint32_t)(p2 * 16 + brow) * 144
                              + kk * 32 + bdb;
                LDMX4(bh4[0], bh4[1], bh4[2], bh4[3], ad);
                LDMX4(bl4[0], bl4[1], bl4[2], bl4[3], ad + (AT_RKL - AT_RKH));
                MMA16816(pr[2 * p2], qh[kk], bh4[0], bh4[1]);
                MMA16816(pr[2 * p2], ql[kk], bh4[0], bh4[1]);
                MMA16816(pr[2 * p2], qh[kk], bl4[0], bl4[1]);
                if (p2 < 2) {
                    MMA16816(pr[2 * p2 + 1], qh[kk], bh4[2], bh4[3]);
                    MMA16816(pr[2 * p2 + 1], ql[kk], bh4[2], bh4[3]);
                    MMA16816(pr[2 * p2 + 1], qh[kk], bl4[2], bl4[3]);
                }
            }
        }
#pragma unroll
        for (int nt = 0; nt < 5; nt++) {
            int c0 = nt * 8 + 2 * (lane & 3);
            if (c0 < NR_) {
                pS[r0l * 34 + c0] = pr[nt][0];
                pS[(r0l + 8) * 34 + c0] = pr[nt][2];
            }
            if (c0 + 1 < NR_) {
                pS[r0l * 34 + c0 + 1] = pr[nt][1];
                pS[(r0l + 8) * 34 + c0 + 1] = pr[nt][3];
            }
        }
        __syncwarp();
    }

    // ---- text scores S (80 cols in registers) ----
    float s[10][4];
#pragma unroll
    for (int i = 0; i < 10; i++)
#pragma unroll
        for (int c = 0; c < 4; c++) s[i][c] = 0.f;
#pragma unroll
    for (int kk = 0; kk < 4; kk++) {
#pragma unroll
        for (int p2 = 0; p2 < 5; p2++) {
            uint32_t kh4[4], kl4[4];
            uint32_t ad = sb + AT_KHI + (uint32_t)(p2 * 16 + brow) * 144
                          + kk * 32 + bdb;
            LDMX4(kh4[0], kh4[1], kh4[2], kh4[3], ad);
            LDMX4(kl4[0], kl4[1], kl4[2], kl4[3], ad + (AT_KLO - AT_KHI));
            MMA16816(s[2 * p2], qh[kk], kh4[0], kh4[1]);
            MMA16816(s[2 * p2], ql[kk], kh4[0], kh4[1]);
            MMA16816(s[2 * p2], qh[kk], kl4[0], kl4[1]);
            MMA16816(s[2 * p2 + 1], qh[kk], kh4[2], kh4[3]);
            MMA16816(s[2 * p2 + 1], ql[kk], kh4[2], kh4[3]);
            MMA16816(s[2 * p2 + 1], qh[kk], kl4[2], kl4[3]);
        }
    }

    // ---- rel add + mask ----
#pragma unroll
    for (int nt = 0; nt < 10; nt++) {
        int c0 = nt * 8 + 2 * (lane & 3);
        if (qt == 0) {
            s[nt][0] += pS[r0l * 34 + bidx(c0, r0l)];
            s[nt][1] += pS[r0l * 34 + bidx(c0 + 1, r0l)];
            s[nt][2] += pS[(r0l + 8) * 34 + bidx(c0, r0l + 8)];
            s[nt][3] += pS[(r0l + 8) * 34 + bidx(c0 + 1, r0l + 8)];
        }
        if (c0 >= LT_) { s[nt][0] = -1e30f; s[nt][2] = -1e30f; }
        if (c0 + 1 >= LT_) { s[nt][1] = -1e30f; s[nt][3] = -1e30f; }
    }

    // ---- exact softmax over text cols ----
    float m0 = -1e30f, m1 = -1e30f;
#pragma unroll
    for (int nt = 0; nt < 10; nt++) {
        m0 = fmaxf(m0, fmaxf(s[nt][0], s[nt][1]));
        m1 = fmaxf(m1, fmaxf(s[nt][2], s[nt][3]));
    }
    m0 = fmaxf(m0, __shfl_xor_sync(FULL, m0, 1));
    m0 = fmaxf(m0, __shfl_xor_sync(FULL, m0, 2));
    m1 = fmaxf(m1, __shfl_xor_sync(FULL, m1, 1));
    m1 = fmaxf(m1, __shfl_xor_sync(FULL, m1, 2));
    float l0 = 0.f, l1 = 0.f;
#pragma unroll
    for (int nt = 0; nt < 10; nt++) {
        s[nt][0] = __expf(s[nt][0] - m0); l0 += s[nt][0];
        s[nt][1] = __expf(s[nt][1] - m0); l0 += s[nt][1];
        s[nt][2] = __expf(s[nt][2] - m1); l1 += s[nt][2];
        s[nt][3] = __expf(s[nt][3] - m1); l1 += s[nt][3];
    }
    l0 += __shfl_xor_sync(FULL, l0, 1); l0 += __shfl_xor_sync(FULL, l0, 2);
    l1 += __shfl_xor_sync(FULL, l1, 1); l1 += __shfl_xor_sync(FULL, l1, 2);
    float inv0 = 1.f / l0, inv1 = 1.f / l1;
#pragma unroll
    for (int nt = 0; nt < 10; nt++) {
        s[nt][0] *= inv0; s[nt][1] *= inv0;
        s[nt][2] *= inv1; s[nt][3] *= inv1;
    }

    // ---- bucket weight sums (tile 0; pS reused as wsum) ----
    if (qt == 0) {
        for (int idx = lane; idx < 16 * 34; idx += 32)
            pS[(wr + idx / 34) * 34 + idx % 34] = 0.f;
        __syncwarp();
#pragma unroll
        for (int nt = 0; nt < 10; nt++) {
            int c0 = nt * 8 + 2 * (lane & 3);
            if (c0 < LT_) {
                atomicAdd(&pS[r0l * 34 + bidx(c0, r0l)], s[nt][0]);
                atomicAdd(&pS[(r0l + 8) * 34 + bidx(c0, r0l + 8)], s[nt][2]);
            }
            if (c0 + 1 < LT_) {
                atomicAdd(&pS[r0l * 34 + bidx(c0 + 1, r0l)], s[nt][1]);
                atomicAdd(&pS[(r0l + 8) * 34 + bidx(c0 + 1, r0l + 8)], s[nt][3]);
            }
        }
        __syncwarp();
    }

    const int vrow = (lane & 8) + (lane & 7);
    const int vdb = (lane >> 4) * 16;   // byte offset 0/16 within d16 chunk

    // ---- O_text = W @ V_text ----
    float ot[8][4];
#pragma unroll
    for (int i = 0; i < 8; i++)
#pragma unroll
        for (int c = 0; c < 4; c++) ot[i][c] = 0.f;
#pragma unroll
    for (int wk = 0; wk < 5; wk++) {
        uint32_t ahi[4], alo[4];
        wsplit(s[2 * wk], s[2 * wk + 1], ahi, alo);
#pragma unroll
        for (int dp = 0; dp < 4; dp++) {
            uint32_t vh4[4], vl4[4];
            uint32_t ad = sb + AT_VHI + (uint32_t)(wk * 16 + vrow) * 144
                          + dp * 32 + vdb;
            LDMX4T(vh4[0], vh4[1], vh4[2], vh4[3], ad);
            LDMX4T(vl4[0], vl4[1], vl4[2], vl4[3], ad + (AT_VLO - AT_VHI));
            MMA16816(ot[2 * dp], ahi, vh4[0], vh4[1]);
            MMA16816(ot[2 * dp], alo, vh4[0], vh4[1]);
            MMA16816(ot[2 * dp], ahi, vl4[0], vl4[1]);
            MMA16816(ot[2 * dp + 1], ahi, vh4[2], vh4[3]);
            MMA16816(ot[2 * dp + 1], alo, vh4[2], vh4[3]);
            MMA16816(ot[2 * dp + 1], ahi, vl4[2], vl4[3]);
        }
    }

    // ---- rel-V contribution ----
    if (qt == 0) {
#pragma unroll 1
        for (int r = 0; r < NR_; r++) {
            float w0 = pS[r0l * 34 + r];
            float w1 = pS[(r0l + 8) * 34 + r];
            const float* rv = relv + r * 64 + 2 * (lane & 3);
#pragma unroll
            for (int dt = 0; dt < 8; dt++) {
                float rv0 = rv[dt * 8], rv1 = rv[dt * 8 + 1];
                ot[dt][0] += w0 * rv0; ot[dt][1] += w0 * rv1;
                ot[dt][2] += w1 * rv0; ot[dt][3] += w1 * rv1;
            }
        }
    } else {
        const float* rv = relv + 2 * (lane & 3);
#pragma unroll
        for (int dt = 0; dt < 8; dt++) {
            float rv0 = rv[dt * 8], rv1 = rv[dt * 8 + 1];
            ot[dt][0] += rv0; ot[dt][1] += rv1;
            ot[dt][2] += rv0; ot[dt][3] += rv1;
        }
    }

    // ---- image branch: online softmax over 8 chunks of 32 keys ----
    float oi[8][4];
#pragma unroll
    for (int i = 0; i < 8; i++)
#pragma unroll
        for (int c = 0; c < 4; c++) oi[i][c] = 0.f;
    float mi0 = -1e30f, mi1 = -1e30f, li0 = 0.f, li1 = 0.f;
#pragma unroll 1
    for (int ch = 0; ch < 8; ch++) {
        const int j0 = 80 + ch * 32;
        float sc[4][4];
#pragma unroll
        for (int i = 0; i < 4; i++)
#pragma unroll
            for (int c = 0; c < 4; c++) sc[i][c] = 0.f;
#pragma unroll
        for (int kk = 0; kk < 4; kk++) {
#pragma unroll
            for (int p2 = 0; p2 < 2; p2++) {
                uint32_t kh4[4], kl4[4];
                uint32_t ad = sb + AT_KHI + (uint32_t)(j0 + p2 * 16 + brow) * 144
                              + kk * 32 + bdb;
                LDMX4(kh4[0], kh4[1], kh4[2], kh4[3], ad);
                LDMX4(kl4[0], kl4[1], kl4[2], kl4[3], ad + (AT_KLO - AT_KHI));
                MMA16816(sc[2 * p2], qh[kk], kh4[0], kh4[1]);
                MMA16816(sc[2 * p2], ql[kk], kh4[0], kh4[1]);
                MMA16816(sc[2 * p2], qh[kk], kl4[0], kl4[1]);
                MMA16816(sc[2 * p2 + 1], qh[kk], kh4[2], kh4[3]);
                MMA16816(sc[2 * p2 + 1], ql[kk], kh4[2], kh4[3]);
                MMA16816(sc[2 * p2 + 1], qh[kk], kl4[2], kl4[3]);
            }
        }
        float cm0 = -1e30f, cm1 = -1e30f;
#pragma unroll
        for (int t = 0; t < 4; t++) {
            cm0 = fmaxf(cm0, fmaxf(sc[t][0], sc[t][1]));
            cm1 = fmaxf(cm1, fmaxf(sc[t][2], sc[t][3]));
        }
        cm0 = fmaxf(cm0, __shfl_xor_sync(FULL, cm0, 1));
        cm0 = fmaxf(cm0, __shfl_xor_sync(FULL, cm0, 2));
        cm1 = fmaxf(cm1, __shfl_xor_sync(FULL, cm1, 1));
        cm1 = fmaxf(cm1, __shfl_xor_sync(FULL, cm1, 2));
        float mn0 = fmaxf(mi0, cm0), mn1 = fmaxf(mi1, cm1);
        float al0 = __expf(mi0 - mn0), al1 = __expf(mi1 - mn1);
        float cs0 = 0.f, cs1 = 0.f;
#pragma unroll
        for (int t = 0; t < 4; t++) {
            sc[t][0] = __expf(sc[t][0] - mn0); cs0 += sc[t][0];
            sc[t][1] = __expf(sc[t][1] - mn0); cs0 += sc[t][1];
            sc[t][2] = __expf(sc[t][2] - mn1); cs1 += sc[t][2];
            sc[t][3] = __expf(sc[t][3] - mn1); cs1 += sc[t][3];
        }
        cs0 += __shfl_xor_sync(FULL, cs0, 1); cs0 += __shfl_xor_sync(FULL, cs0, 2);
        cs1 += __shfl_xor_sync(FULL, cs1, 1); cs1 += __shfl_xor_sync(FULL, cs1, 2);
        li0 = li0 * al0 + cs0; li1 = li1 * al1 + cs1;
        mi0 = mn0; mi1 = mn1;
#pragma unroll
        for (int dt = 0; dt < 8; dt++) {
            oi[dt][0] *= al0; oi[dt][1] *= al0;
            oi[dt][2] *= al1; oi[dt][3] *= al1;
        }
#pragma unroll
        for (int wk = 0; wk < 2; wk++) {
            uint32_t ahi[4], alo[4];
            wsplit(sc[2 * wk], sc[2 * wk + 1], ahi, alo);
#pragma unroll
            for (int dp = 0; dp < 4; dp++) {
                uint32_t vh4[4], vl4[4];
                uint32_t ad = sb + AT_VHI + (uint32_t)(j0 + wk * 16 + vrow) * 144
                              + dp * 32 + vdb;
                LDMX4T(vh4[0], vh4[1], vh4[2], vh4[3], ad);
                LDMX4T(vl4[0], vl4[1], vl4[2], vl4[3], ad + (AT_VLO - AT_VHI));
                MMA16816(oi[2 * dp], ahi, vh4[0], vh4[1]);
                MMA16816(oi[2 * dp], alo, vh4[0], vh4[1]);
                MMA16816(oi[2 * dp], ahi, vl4[0], vl4[1]);
                MMA16816(oi[2 * dp + 1], ahi, vh4[2], vh4[3]);
                MMA16816(oi[2 * dp + 1], alo, vh4[2], vh4[3]);
                MMA16816(oi[2 * dp + 1], ahi, vl4[2], vl4[3]);
            }
        }
    }
    float ii0 = 1.f / li0, ii1 = 1.f / li1;

    // ---- combine + store bf16 hi/lo ----
    {
        size_t ob = ((size_t)(b * NQ_ + i0 + r0l)) * 1024 + h * 64 + 2 * (lane & 3);
#pragma unroll
        for (int dt = 0; dt < 8; dt++) {
            float v0 = ot[dt][0] + oi[dt][0] * ii0;
            float v1 = ot[dt][1] + oi[dt][1] * ii0;
            float v2 = ot[dt][2] + oi[dt][2] * ii1;
            float v3 = ot[dt][3] + oi[dt][3] * ii1;
            float h0 = __bfloat162float(__float2bfloat16(v0));
            float h1 = __bfloat162float(__float2bfloat16(v1));
            float h2 = __bfloat162float(__float2bfloat16(v2));
            float h3 = __bfloat162float(__float2bfloat16(v3));
            size_t o0 = ob + dt * 8;
            size_t o1 = o0 + 8 * 1024;
            *(uint32_t*)(atthi + o0) = packbf(h0, h1);
            *(uint32_t*)(attlo + o0) = packbf(v0 - h0, v1 - h1);
            *(uint32_t*)(atthi + o1) = packbf(h2, h3);
            *(uint32_t*)(attlo + o1) = packbf(v2 - h2, v3 - h3);
        }
    }
}

// ---------------------------------------------------------------------------
// Host launcher
// ---------------------------------------------------------------------------
extern "C" void kernel_launch(void* const* d_in, const int* in_sizes, int n_in,
                              void* d_out, int out_size)
{
    const float* x     = (const float*)d_in[0];
    const float* ctx   = (const float*)d_in[1];
    const float* Wq    = (const float*)d_in[2];
    const float* Wk    = (const float*)d_in[3];
    const float* Wv    = (const float*)d_in[4];
    const float* Wk_ip = (const float*)d_in[5];
    const float* Wv_ip = (const float*)d_in[6];
    const float* Wout  = (const float*)d_in[7];
    const float* bout  = (const float*)d_in[8];
    const float* relk  = (const float*)d_in[9];
    const float* relv  = (const float*)d_in[10];
    float* out = (float*)d_out;

    __nv_bfloat16 *pahi, *palo, *pqhi, *pqlo, *pchi, *pclo, *pwhi, *pwlo;
    __nv_bfloat16 *pkthi, *pktlo, *pvthi, *pvtlo, *pkihi, *pkilo, *pvihi, *pvilo;
    cudaGetSymbolAddress((void**)&pahi, g_ahi);
    cudaGetSymbolAddress((void**)&palo, g_alo);
    cudaGetSymbolAddress((void**)&pqhi, g_qhi);
    cudaGetSymbolAddress((void**)&pqlo, g_qlo);
    cudaGetSymbolAddress((void**)&pchi, g_chi);
    cudaGetSymbolAddress((void**)&pclo, g_clo);
    cudaGetSymbolAddress((void**)&pwhi, g_whi);
    cudaGetSymbolAddress((void**)&pwlo, g_wlo);
    cudaGetSymbolAddress((void**)&pkthi, g_kthi);
    cudaGetSymbolAddress((void**)&pktlo, g_ktlo);
    cudaGetSymbolAddress((void**)&pvthi, g_vthi);
    cudaGetSymbolAddress((void**)&pvtlo, g_vtlo);
    cudaGetSymbolAddress((void**)&pkihi, g_kihi);
    cudaGetSymbolAddress((void**)&pkilo, g_kilo);
    cudaGetSymbolAddress((void**)&pvihi, g_vihi);
    cudaGetSymbolAddress((void**)&pvilo, g_vilo);

    cudaFuncSetAttribute(gemm_mma<0>,
                         cudaFuncAttributeMaxDynamicSharedMemorySize, GM_SMEM);
    cudaFuncSetAttribute(gemm_mma<1>,
                         cudaFuncAttributeMaxDynamicSharedMemorySize, GM_SMEM);
    cudaFuncSetAttribute(gemm_mma<2>,
                         cudaFuncAttributeMaxDynamicSharedMemorySize, GM_SMEM);
    cudaFuncSetAttribute(attn_mma,
                         cudaFuncAttributeMaxDynamicSharedMemorySize, AT_SMEM);

    const size_t WSZ = (size_t)DM_ * DM_;
    const float* Ws[6] = {Wq, Wk, Wv, Wk_ip, Wv_ip, Wout};
    for (int wi = 0; wi < 6; wi++)
        conv_wt<<<dim3(32, 32), dim3(32, 8)>>>(Ws[wi], pwhi + wi * WSZ, pwlo + wi * WSZ);

    {
        size_t n = (size_t)B_ * NQ_ * DM_;
        conv_rows<<<(unsigned)(n / 4 / 256), 256>>>(x, pahi, palo, n);
        size_t nc = (size_t)B_ * CTXR * DM_;
        conv_rows<<<(unsigned)((nc / 4 + 255) / 256), 256>>>(ctx, pchi, pclo, nc);
    }

    // Q = (x @ Wq) * 0.125 -> bf16 hi/lo
    gemm_mma<2><<<dim3(8, 512), 256, GM_SMEM>>>(
        pahi, palo, pwhi + 0 * WSZ, pwlo + 0 * WSZ, nullptr, nullptr,
        pqhi, pqlo, B_ * NQ_, B_ * NQ_, B_ * NQ_, 0);

    // K/V text -> [b][h][t][d] bf16 hi/lo
    gemm_mma<1><<<dim3(8, 39), 256, GM_SMEM>>>(
        pchi, pclo, pwhi + 1 * WSZ, pwlo + 1 * WSZ, nullptr, nullptr,
        pkthi, pktlo, B_ * LT_, LT_, CTXR, 0);
    gemm_mma<1><<<dim3(8, 39), 256, GM_SMEM>>>(
        pchi, pclo, pwhi + 2 * WSZ, pwlo + 2 * WSZ, nullptr, nullptr,
        pvthi, pvtlo, B_ * LT_, LT_, CTXR, 0);

    // K/V image
    gemm_mma<1><<<dim3(8, 128), 256, GM_SMEM>>>(
        pchi, pclo, pwhi + 3 * WSZ, pwlo + 3 * WSZ, nullptr, nullptr,
        pkihi, pkilo, B_ * LI_, LI_, CTXR, LT_);
    gemm_mma<1><<<dim3(8, 128), 256, GM_SMEM>>>(
        pchi, pclo, pwhi + 4 * WSZ, pwlo + 4 * WSZ, nullptr, nullptr,
        pvihi, pvilo, B_ * LI_, LI_, CTXR, LT_);

    // tensor-core attention -> bf16 hi/lo into final-GEMM input buffers
    attn_mma<<<B_ * H_ * 8, 256, AT_SMEM>>>(
        pqhi, pqlo, pkthi, pktlo, pvthi, pvtlo,
        pkihi, pkilo, pvihi, pvilo, relk, relv, pahi, palo);

    // final projection + bias
    gemm_mma<0><<<dim3(8, 512), 256, GM_SMEM>>>(
        pahi, palo, pwhi + 5 * WSZ, pwlo + 5 * WSZ, out, bout,
        nullptr, nullptr, B_ * NQ_, B_ * NQ_, B_ * NQ_, 0);
}

// round 6
// speedup vs baseline: 3.0774x; 1.1032x over previous
#include <cuda_runtime.h>
#include <cuda_fp16.h>
#include <cstdint>

// ---------------------------------------------------------------------------
// Problem constants
// ---------------------------------------------------------------------------
#define B_    64
#define NQ_   1024
#define DM_   1024
#define H_    16
#define D_    64
#define LT_   77
#define LI_   256
#define NR_   33
#define CTXR  (LT_ + LI_)     // 333

__device__ __forceinline__ uint32_t smem_to_u32(const void* p) {
    uint32_t a;
    asm("{ .reg .u64 t; cvta.to.shared.u64 t, %1; cvt.u32.u64 %0, t; }"
        : "=r"(a) : "l"(p));
    return a;
}

#define CPA16(dst, src) \
    asm volatile("cp.async.cg.shared.global [%0], [%1], 16;" \
                 :: "r"(dst), "l"(src))
#define CPA_COMMIT() asm volatile("cp.async.commit_group;" ::: "memory")
#define CPA_WAIT(n)  asm volatile("cp.async.wait_group %0;" :: "n"(n) : "memory")

#define LDMX4(r0, r1, r2, r3, addr) \
    asm volatile("ldmatrix.sync.aligned.m8n8.x4.shared.b16 {%0,%1,%2,%3}, [%4];" \
                 : "=r"(r0), "=r"(r1), "=r"(r2), "=r"(r3) : "r"(addr))
#define LDMX4T(r0, r1, r2, r3, addr) \
    asm volatile("ldmatrix.sync.aligned.m8n8.x4.trans.shared.b16 {%0,%1,%2,%3}, [%4];" \
                 : "=r"(r0), "=r"(r1), "=r"(r2), "=r"(r3) : "r"(addr))

#define MMA16816(c, a, b0, b1) \
    asm volatile("mma.sync.aligned.m16n8k16.row.col.f32.f16.f16.f32 " \
                 "{%0,%1,%2,%3}, {%4,%5,%6,%7}, {%8,%9}, {%0,%1,%2,%3};" \
                 : "+f"((c)[0]), "+f"((c)[1]), "+f"((c)[2]), "+f"((c)[3]) \
                 : "r"((a)[0]), "r"((a)[1]), "r"((a)[2]), "r"((a)[3]), \
                   "r"(b0), "r"(b1))

__device__ __forceinline__ uint32_t packh(float lo, float hi) {
    uint32_t d;
    asm("cvt.rn.f16x2.f32 %0, %1, %2;" : "=r"(d) : "f"(hi), "f"(lo));
    return d;
}

// ---------------------------------------------------------------------------
// Scratch (static device globals)
// ---------------------------------------------------------------------------
__device__ __half g_ahi[(size_t)B_ * NQ_ * DM_];  // x hi, later att hi
__device__ __half g_alo[(size_t)B_ * NQ_ * DM_];
__device__ __half g_qhi[(size_t)B_ * NQ_ * DM_];
__device__ __half g_qlo[(size_t)B_ * NQ_ * DM_];
__device__ __half g_chi[(size_t)B_ * CTXR * DM_];
__device__ __half g_clo[(size_t)B_ * CTXR * DM_];
__device__ __half g_whi[6 * (size_t)DM_ * DM_];
__device__ __half g_wlo[6 * (size_t)DM_ * DM_];
__device__ __half g_kthi[(size_t)B_ * H_ * LT_ * D_];
__device__ __half g_ktlo[(size_t)B_ * H_ * LT_ * D_];
__device__ __half g_vthi[(size_t)B_ * H_ * LT_ * D_];
__device__ __half g_vtlo[(size_t)B_ * H_ * LT_ * D_];
__device__ __half g_kihi[(size_t)B_ * H_ * LI_ * D_];
__device__ __half g_kilo[(size_t)B_ * H_ * LI_ * D_];
__device__ __half g_vihi[(size_t)B_ * H_ * LI_ * D_];
__device__ __half g_vilo[(size_t)B_ * H_ * LI_ * D_];

// ---------------------------------------------------------------------------
// fp32 -> fp16 hi/lo split
// ---------------------------------------------------------------------------
__global__ void conv_rows(const float* __restrict__ src,
                          __half* __restrict__ hi,
                          __half* __restrict__ lo, size_t n)
{
    size_t i = ((size_t)blockIdx.x * blockDim.x + threadIdx.x) * 4;
    if (i >= n) return;
    float4 v = *(const float4*)(src + i);
    float h0 = __half2float(__float2half(v.x));
    float h1 = __half2float(__float2half(v.y));
    float h2 = __half2float(__float2half(v.z));
    float h3 = __half2float(__float2half(v.w));
    *(uint2*)(hi + i) = make_uint2(packh(h0, h1), packh(h2, h3));
    *(uint2*)(lo + i) = make_uint2(packh(v.x - h0, v.y - h1),
                                   packh(v.z - h2, v.w - h3));
}

// W [K=1024, N=1024] -> Wt hi/lo [N, K]
__global__ void conv_wt(const float* __restrict__ W,
                        __half* __restrict__ hi,
                        __half* __restrict__ lo)
{
    __shared__ float tile[32][33];
    const int k0 = blockIdx.y * 32, n0 = blockIdx.x * 32;
    const int tx = threadIdx.x;
    for (int r = threadIdx.y; r < 32; r += 8)
        tile[r][tx] = W[(size_t)(k0 + r) * DM_ + n0 + tx];
    __syncthreads();
    for (int r = threadIdx.y; r < 32; r += 8) {
        float v = tile[tx][r];
        float h = __half2float(__float2half(v));
        size_t oi = (size_t)(n0 + r) * DM_ + k0 + tx;
        hi[oi] = __float2half(h);
        lo[oi] = __float2half(v - h);
    }
}

// ---------------------------------------------------------------------------
// fp16 split GEMM via mma.sync: C[M,1024] = remap(A)[M,1024] @ B^T (B is [N,K])
// MODE 0: fp32 C + bias.  MODE 1: KV scatter fp16 hi/lo.  MODE 2: Q *0.125.
// TERMS 3: AhiBhi + AloBhi + AhiBlo.  TERMS 2: AhiBhi + AloBhi (Blo not loaded).
// CTA 128x128, BK=32, 3-stage cp.async pipeline, 1 syncthreads/iter.
// ---------------------------------------------------------------------------
#define BUF_BYTES   40960
#define GM_SMEM     (3 * BUF_BYTES)

template <int MODE, int TERMS>
__global__ void __launch_bounds__(256, 1)
gemm_mma(const __half* __restrict__ Ahi, const __half* __restrict__ Alo,
         const __half* __restrict__ Bhi, const __half* __restrict__ Blo,
         float* __restrict__ C, const float* __restrict__ bias,
         __half* __restrict__ Chi, __half* __restrict__ Clo,
         int M, int rows_per_seg, int seg_stride, int seg_base)
{
    extern __shared__ __align__(128) char smem[];
    const uint32_t sb = smem_to_u32(smem);
    const int tid = threadIdx.x;
    const int bn = blockIdx.x * 128;
    const int bm = blockIdx.y * 128;
    const int wid = tid >> 5, lane = tid & 31;
    const int Wm = (wid & 3) * 32;
    const int Wn = (wid >> 2) * 64;

    const int lrow = tid >> 1;
    const int lc = tid & 1;
    int m = bm + lrow; if (m > M - 1) m = M - 1;
    const int seg = m / rows_per_seg;
    const int t = m - seg * rows_per_seg;
    const size_t aoff = (size_t)(seg * seg_stride + seg_base + t) * 1024 + lc * 16;
    const size_t boff = (size_t)(bn + lrow) * 1024 + lc * 16;
    const uint32_t soff = (uint32_t)lrow * 80u + (uint32_t)lc * 32u;

    float acc[2][8][4];
#pragma unroll
    for (int i = 0; i < 2; i++)
#pragma unroll
        for (int j = 0; j < 8; j++)
#pragma unroll
            for (int c = 0; c < 4; c++) acc[i][j][c] = 0.f;

    const uint32_t a_frag_row = (uint32_t)(Wm + (lane & 15)) * 80u + ((lane >> 4) * 16u);
    const uint32_t b_frag_row =
        (uint32_t)(Wn + (lane & 7) + ((lane >> 4) << 3)) * 80u + (((lane >> 3) & 1) * 16u);

#define ISSUE(p, k0)                                                       \
    {                                                                      \
        uint32_t d = sb + (p) * BUF_BYTES + soff;                          \
        const __half* s;                                                   \
        s = Ahi + aoff + (k0); CPA16(d,           s); CPA16(d + 16,         s + 8); \
        s = Alo + aoff + (k0); CPA16(d + 10240,   s); CPA16(d + 10240 + 16, s + 8); \
        s = Bhi + boff + (k0); CPA16(d + 20480,   s); CPA16(d + 20480 + 16, s + 8); \
        if (TERMS == 3) {                                                  \
            s = Blo + boff + (k0); CPA16(d + 30720, s); CPA16(d + 30720 + 16, s + 8); \
        }                                                                  \
    }

    ISSUE(0, 0);
    CPA_COMMIT();
    ISSUE(1, 32);
    CPA_COMMIT();

    int stage = 0;
    for (int i = 0; i < 32; i++) {
        if (i < 30) { CPA_WAIT(1); } else { CPA_WAIT(0); }
        __syncthreads();
        if (i + 2 < 32) {
            int ns = stage + 2; if (ns >= 3) ns -= 3;
            ISSUE(ns, (i + 2) * 32);
            CPA_COMMIT();
        }

        const uint32_t base = sb + stage * BUF_BYTES;
#pragma unroll
        for (int kk = 0; kk < 2; kk++) {
            uint32_t ah[2][4], al[2][4];
            const uint32_t ar = base + a_frag_row + kk * 32;
            LDMX4(ah[0][0], ah[0][1], ah[0][2], ah[0][3], ar);
            LDMX4(ah[1][0], ah[1][1], ah[1][2], ah[1][3], ar + 16 * 80);
            LDMX4(al[0][0], al[0][1], al[0][2], al[0][3], ar + 10240);
            LDMX4(al[1][0], al[1][1], al[1][2], al[1][3], ar + 10240 + 16 * 80);
#pragma unroll
            for (int j = 0; j < 4; j++) {
                uint32_t bh0, bh1, bh2, bh3;
                const uint32_t br = base + b_frag_row + kk * 32 + (uint32_t)j * (16 * 80);
                LDMX4(bh0, bh1, bh2, bh3, br + 20480);
                uint32_t bl0 = 0, bl1 = 0, bl2 = 0, bl3 = 0;
                if (TERMS == 3) { LDMX4(bl0, bl1, bl2, bl3, br + 30720); }
#pragma unroll
                for (int mt = 0; mt < 2; mt++) {
                    MMA16816(acc[mt][2 * j],     ah[mt], bh0, bh1);
                    MMA16816(acc[mt][2 * j],     al[mt], bh0, bh1);
                    MMA16816(acc[mt][2 * j + 1], ah[mt], bh2, bh3);
                    MMA16816(acc[mt][2 * j + 1], al[mt], bh2, bh3);
                    if (TERMS == 3) {
                        MMA16816(acc[mt][2 * j],     ah[mt], bl0, bl1);
                        MMA16816(acc[mt][2 * j + 1], ah[mt], bl2, bl3);
                    }
                }
            }
        }
        stage++; if (stage >= 3) stage = 0;
    }
#undef ISSUE

    const int er = lane >> 2, ec = (lane & 3) * 2;
#pragma unroll
    for (int mt = 0; mt < 2; mt++) {
#pragma unroll
        for (int hrow = 0; hrow < 2; hrow++) {
            const int cm = bm + Wm + mt * 16 + er + hrow * 8;
            if (cm >= M) continue;
            if (MODE == 1) {
                const int segc = cm / rows_per_seg;
                const int tc = cm - segc * rows_per_seg;
#pragma unroll
                for (int nt = 0; nt < 8; nt++) {
                    const int cn = bn + Wn + nt * 8 + ec;
                    const int hh = cn >> 6, dd = cn & 63;
                    size_t oi = (((size_t)segc * H_ + hh) * rows_per_seg + tc) * 64 + dd;
                    float v0 = acc[mt][nt][hrow * 2], v1 = acc[mt][nt][hrow * 2 + 1];
                    float h0 = __half2float(__float2half(v0));
                    float h1 = __half2float(__float2half(v1));
                    *(uint32_t*)(Chi + oi) = packh(h0, h1);
                    *(uint32_t*)(Clo + oi) = packh(v0 - h0, v1 - h1);
                }
            } else if (MODE == 2) {
#pragma unroll
                for (int nt = 0; nt < 8; nt++) {
                    const int cn = bn + Wn + nt * 8 + ec;
                    size_t oi = (size_t)cm * DM_ + cn;
                    float v0 = acc[mt][nt][hrow * 2] * 0.125f;
                    float v1 = acc[mt][nt][hrow * 2 + 1] * 0.125f;
                    float h0 = __half2float(__float2half(v0));
                    float h1 = __half2float(__float2half(v1));
                    *(uint32_t*)(Chi + oi) = packh(h0, h1);
                    *(uint32_t*)(Clo + oi) = packh(v0 - h0, v1 - h1);
                }
            } else {
                float* Cp = C + (size_t)cm * DM_ + bn + Wn + ec;
                const float* bp = bias + bn + Wn + ec;
#pragma unroll
                for (int nt = 0; nt < 8; nt++) {
                    float2 v = make_float2(acc[mt][nt][hrow * 2] + bp[nt * 8],
                                           acc[mt][nt][hrow * 2 + 1] + bp[nt * 8 + 1]);
                    *(float2*)(Cp + nt * 8) = v;
                }
            }
        }
    }
}

// ---------------------------------------------------------------------------
// Tensor-core flash attention (fp16 hi/lo). One CTA = (b, h, 128-query tile).
// ---------------------------------------------------------------------------
#define AT_KHI 0
#define AT_KLO 48384
#define AT_VHI 96768
#define AT_VLO 145152
#define AT_QHI 193536
#define AT_QLO 211968
#define AT_PS  193536
#define AT_RKH 211968
#define AT_RKL 217728
#define AT_SMEM 230400

__device__ __forceinline__ int bidx(int j, int i)
{
    int d = j - i;
    d = max(-16, min(16, d));
    return d + 16;
}

__device__ __forceinline__ void wsplit(const float* s0, const float* s1,
                                       uint32_t* ahi, uint32_t* alo)
{
    float v[8] = {s0[0], s0[1], s0[2], s0[3], s1[0], s1[1], s1[2], s1[3]};
    float hv[8];
#pragma unroll
    for (int i = 0; i < 8; i++)
        hv[i] = __half2float(__float2half(v[i]));
    ahi[0] = packh(hv[0], hv[1]); ahi[1] = packh(hv[2], hv[3]);
    ahi[2] = packh(hv[4], hv[5]); ahi[3] = packh(hv[6], hv[7]);
    alo[0] = packh(v[0] - hv[0], v[1] - hv[1]);
    alo[1] = packh(v[2] - hv[2], v[3] - hv[3]);
    alo[2] = packh(v[4] - hv[4], v[5] - hv[5]);
    alo[3] = packh(v[6] - hv[6], v[7] - hv[7]);
}

__global__ void __launch_bounds__(256, 1)
attn_mma(const __half* __restrict__ qhi, const __half* __restrict__ qlo,
         const __half* __restrict__ kthi, const __half* __restrict__ ktlo,
         const __half* __restrict__ vthi, const __half* __restrict__ vtlo,
         const __half* __restrict__ kihi, const __half* __restrict__ kilo,
         const __half* __restrict__ vihi, const __half* __restrict__ vilo,
         const float* __restrict__ relk, const float* __restrict__ relv,
         __half* __restrict__ atthi, __half* __restrict__ attlo)
{
    extern __shared__ __align__(128) char sm[];
    const uint32_t sb = smem_to_u32(sm);
    const int tid = threadIdx.x, w = tid >> 5, lane = tid & 31;
    const int bh = blockIdx.x >> 3, qt = blockIdx.x & 7;
    const int b = bh >> 4, h = bh & 15;
    const int i0 = qt * 128;
    const unsigned FULL = 0xffffffffu;

    // ---- stage K/V/Q ----
    {
        size_t tb = (size_t)bh * (LT_ * 64);
        for (int idx = tid; idx < LT_ * 8; idx += 256) {
            int r = idx >> 3, c = idx & 7;
            uint32_t d = (uint32_t)r * 144 + c * 16;
            size_t s = tb + (size_t)r * 64 + c * 8;
            CPA16(sb + AT_KHI + d, kthi + s);
            CPA16(sb + AT_KLO + d, ktlo + s);
            CPA16(sb + AT_VHI + d, vthi + s);
            CPA16(sb + AT_VLO + d, vtlo + s);
        }
        size_t ib = (size_t)bh * (LI_ * 64);
        for (int idx = tid; idx < LI_ * 8; idx += 256) {
            int r = idx >> 3, c = idx & 7;
            uint32_t d = (uint32_t)(80 + r) * 144 + c * 16;
            size_t s = ib + (size_t)r * 64 + c * 8;
            CPA16(sb + AT_KHI + d, kihi + s);
            CPA16(sb + AT_KLO + d, kilo + s);
            CPA16(sb + AT_VHI + d, vihi + s);
            CPA16(sb + AT_VLO + d, vilo + s);
        }
        size_t qb = ((size_t)(b * NQ_ + i0)) * 1024 + h * 64;
        for (int idx = tid; idx < 128 * 8; idx += 256) {
            int r = idx >> 3, c = idx & 7;
            uint32_t d = (uint32_t)r * 144 + c * 16;
            size_t s = qb + (size_t)r * 1024 + c * 8;
            CPA16(sb + AT_QHI + d, qhi + s);
            CPA16(sb + AT_QLO + d, qlo + s);
        }
        for (int idx = tid; idx < 3 * 36; idx += 256) {
            uint32_t d = (uint32_t)(77 + idx / 36) * 144 + (idx % 36) * 4;
            *(uint32_t*)(sm + AT_KHI + d) = 0;
            *(uint32_t*)(sm + AT_KLO + d) = 0;
            *(uint32_t*)(sm + AT_VHI + d) = 0;
            *(uint32_t*)(sm + AT_VLO + d) = 0;
        }
        CPA_COMMIT();
        CPA_WAIT(0);
        __syncthreads();
    }

    const int wr = w * 16;
    const int r0l = wr + (lane >> 2);

    // ---- Q fragments ----
    uint32_t qh[4][4], ql[4][4];
    {
        int row = wr + (lane & 15);
        int kb = (lane >> 4) * 16;
#pragma unroll
        for (int kk = 0; kk < 4; kk++) {
            uint32_t a = sb + AT_QHI + (uint32_t)row * 144 + kk * 32 + kb;
            LDMX4(qh[kk][0], qh[kk][1], qh[kk][2], qh[kk][3], a);
            LDMX4(ql[kk][0], ql[kk][1], ql[kk][2], ql[kk][3], a + (AT_QLO - AT_QHI));
        }
    }
    __syncthreads();

    if (qt == 0) {
        for (int idx = tid; idx < NR_ * 64; idx += 256) {
            int r = idx >> 6, dc = idx & 63;
            float v = relk[idx];
            float hh = __half2float(__float2half(v));
            *(__half*)(sm + AT_RKH + r * 144 + dc * 2) = __float2half(hh);
            *(__half*)(sm + AT_RKL + r * 144 + dc * 2) = __float2half(v - hh);
        }
    }
    __syncthreads();

    float* pS = (float*)(sm + AT_PS);

    const int brow = ((lane >> 4) << 3) + (lane & 7);
    const int bdb = (lane & 8) * 2;

    // ---- rel-K projections (tile 0) ----
    if (qt == 0) {
        float pr[5][4];
#pragma unroll
        for (int i = 0; i < 5; i++)
#pragma unroll
            for (int c = 0; c < 4; c++) pr[i][c] = 0.f;
#pragma unroll
        for (int kk = 0; kk < 4; kk++) {
#pragma unroll
            for (int p2 = 0; p2 < 3; p2++) {
                uint32_t bh4[4], bl4[4];
                uint32_t ad = sb + AT_RKH + (uint32_t)(p2 * 16 + brow) * 144
                              + kk * 32 + bdb;
                LDMX4(bh4[0], bh4[1], bh4[2], bh4[3], ad);
                LDMX4(bl4[0], bl4[1], bl4[2], bl4[3], ad + (AT_RKL - AT_RKH));
                MMA16816(pr[2 * p2], qh[kk], bh4[0], bh4[1]);
                MMA16816(pr[2 * p2], ql[kk], bh4[0], bh4[1]);
                MMA16816(pr[2 * p2], qh[kk], bl4[0], bl4[1]);
                if (p2 < 2) {
                    MMA16816(pr[2 * p2 + 1], qh[kk], bh4[2], bh4[3]);
                    MMA16816(pr[2 * p2 + 1], ql[kk], bh4[2], bh4[3]);
                    MMA16816(pr[2 * p2 + 1], qh[kk], bl4[2], bl4[3]);
                }
            }
        }
#pragma unroll
        for (int nt = 0; nt < 5; nt++) {
            int c0 = nt * 8 + 2 * (lane & 3);
            if (c0 < NR_) {
                pS[r0l * 34 + c0] = pr[nt][0];
                pS[(r0l + 8) * 34 + c0] = pr[nt][2];
            }
            if (c0 + 1 < NR_) {
                pS[r0l * 34 + c0 + 1] = pr[nt][1];
                pS[(r0l + 8) * 34 + c0 + 1] = pr[nt][3];
            }
        }
        __syncwarp();
    }

    // ---- text scores ----
    float s[10][4];
#pragma unroll
    for (int i = 0; i < 10; i++)
#pragma unroll
        for (int c = 0; c < 4; c++) s[i][c] = 0.f;
#pragma unroll
    for (int kk = 0; kk < 4; kk++) {
#pragma unroll
        for (int p2 = 0; p2 < 5; p2++) {
            uint32_t kh4[4], kl4[4];
            uint32_t ad = sb + AT_KHI + (uint32_t)(p2 * 16 + brow) * 144
                          + kk * 32 + bdb;
            LDMX4(kh4[0], kh4[1], kh4[2], kh4[3], ad);
            LDMX4(kl4[0], kl4[1], kl4[2], kl4[3], ad + (AT_KLO - AT_KHI));
            MMA16816(s[2 * p2], qh[kk], kh4[0], kh4[1]);
            MMA16816(s[2 * p2], ql[kk], kh4[0], kh4[1]);
            MMA16816(s[2 * p2], qh[kk], kl4[0], kl4[1]);
            MMA16816(s[2 * p2 + 1], qh[kk], kh4[2], kh4[3]);
            MMA16816(s[2 * p2 + 1], ql[kk], kh4[2], kh4[3]);
            MMA16816(s[2 * p2 + 1], qh[kk], kl4[2], kl4[3]);
        }
    }

#pragma unroll
    for (int nt = 0; nt < 10; nt++) {
        int c0 = nt * 8 + 2 * (lane & 3);
        if (qt == 0) {
            s[nt][0] += pS[r0l * 34 + bidx(c0, r0l)];
            s[nt][1] += pS[r0l * 34 + bidx(c0 + 1, r0l)];
            s[nt][2] += pS[(r0l + 8) * 34 + bidx(c0, r0l + 8)];
            s[nt][3] += pS[(r0l + 8) * 34 + bidx(c0 + 1, r0l + 8)];
        }
        if (c0 >= LT_) { s[nt][0] = -1e30f; s[nt][2] = -1e30f; }
        if (c0 + 1 >= LT_) { s[nt][1] = -1e30f; s[nt][3] = -1e30f; }
    }

    float m0 = -1e30f, m1 = -1e30f;
#pragma unroll
    for (int nt = 0; nt < 10; nt++) {
        m0 = fmaxf(m0, fmaxf(s[nt][0], s[nt][1]));
        m1 = fmaxf(m1, fmaxf(s[nt][2], s[nt][3]));
    }
    m0 = fmaxf(m0, __shfl_xor_sync(FULL, m0, 1));
    m0 = fmaxf(m0, __shfl_xor_sync(FULL, m0, 2));
    m1 = fmaxf(m1, __shfl_xor_sync(FULL, m1, 1));
    m1 = fmaxf(m1, __shfl_xor_sync(FULL, m1, 2));
    float l0 = 0.f, l1 = 0.f;
#pragma unroll
    for (int nt = 0; nt < 10; nt++) {
        s[nt][0] = __expf(s[nt][0] - m0); l0 += s[nt][0];
        s[nt][1] = __expf(s[nt][1] - m0); l0 += s[nt][1];
        s[nt][2] = __expf(s[nt][2] - m1); l1 += s[nt][2];
        s[nt][3] = __expf(s[nt][3] - m1); l1 += s[nt][3];
    }
    l0 += __shfl_xor_sync(FULL, l0, 1); l0 += __shfl_xor_sync(FULL, l0, 2);
    l1 += __shfl_xor_sync(FULL, l1, 1); l1 += __shfl_xor_sync(FULL, l1, 2);
    float inv0 = 1.f / l0, inv1 = 1.f / l1;
#pragma unroll
    for (int nt = 0; nt < 10; nt++) {
        s[nt][0] *= inv0; s[nt][1] *= inv0;
        s[nt][2] *= inv1; s[nt][3] *= inv1;
    }

    if (qt == 0) {
        for (int idx = lane; idx < 16 * 34; idx += 32)
            pS[(wr + idx / 34) * 34 + idx % 34] = 0.f;
        __syncwarp();
#pragma unroll
        for (int nt = 0; nt < 10; nt++) {
            int c0 = nt * 8 + 2 * (lane & 3);
            if (c0 < LT_) {
                atomicAdd(&pS[r0l * 34 + bidx(c0, r0l)], s[nt][0]);
                atomicAdd(&pS[(r0l + 8) * 34 + bidx(c0, r0l + 8)], s[nt][2]);
            }
            if (c0 + 1 < LT_) {
                atomicAdd(&pS[r0l * 34 + bidx(c0 + 1, r0l)], s[nt][1]);
                atomicAdd(&pS[(r0l + 8) * 34 + bidx(c0 + 1, r0l + 8)], s[nt][3]);
            }
        }
        __syncwarp();
    }

    const int vrow = (lane & 8) + (lane & 7);
    const int vdb = (lane >> 4) * 16;

    float ot[8][4];
#pragma unroll
    for (int i = 0; i < 8; i++)
#pragma unroll
        for (int c = 0; c < 4; c++) ot[i][c] = 0.f;
#pragma unroll
    for (int wk = 0; wk < 5; wk++) {
        uint32_t ahi[4], alo[4];
        wsplit(s[2 * wk], s[2 * wk + 1], ahi, alo);
#pragma unroll
        for (int dp = 0; dp < 4; dp++) {
            uint32_t vh4[4], vl4[4];
            uint32_t ad = sb + AT_VHI + (uint32_t)(wk * 16 + vrow) * 144
                          + dp * 32 + vdb;
            LDMX4T(vh4[0], vh4[1], vh4[2], vh4[3], ad);
            LDMX4T(vl4[0], vl4[1], vl4[2], vl4[3], ad + (AT_VLO - AT_VHI));
            MMA16816(ot[2 * dp], ahi, vh4[0], vh4[1]);
            MMA16816(ot[2 * dp], alo, vh4[0], vh4[1]);
            MMA16816(ot[2 * dp], ahi, vl4[0], vl4[1]);
            MMA16816(ot[2 * dp + 1], ahi, vh4[2], vh4[3]);
            MMA16816(ot[2 * dp + 1], alo, vh4[2], vh4[3]);
            MMA16816(ot[2 * dp + 1], ahi, vl4[2], vl4[3]);
        }
    }

    if (qt == 0) {
#pragma unroll 1
        for (int r = 0; r < NR_; r++) {
            float w0 = pS[r0l * 34 + r];
            float w1 = pS[(r0l + 8) * 34 + r];
            const float* rv = relv + r * 64 + 2 * (lane & 3);
#pragma unroll
            for (int dt = 0; dt < 8; dt++) {
                float rv0 = rv[dt * 8], rv1 = rv[dt * 8 + 1];
                ot[dt][0] += w0 * rv0; ot[dt][1] += w0 * rv1;
                ot[dt][2] += w1 * rv0; ot[dt][3] += w1 * rv1;
            }
        }
    } else {
        const float* rv = relv + 2 * (lane & 3);
#pragma unroll
        for (int dt = 0; dt < 8; dt++) {
            float rv0 = rv[dt * 8], rv1 = rv[dt * 8 + 1];
            ot[dt][0] += rv0; ot[dt][1] += rv1;
            ot[dt][2] += rv0; ot[dt][3] += rv1;
        }
    }

    float oi[8][4];
#pragma unroll
    for (int i = 0; i < 8; i++)
#pragma unroll
        for (int c = 0; c < 4; c++) oi[i][c] = 0.f;
    float mi0 = -1e30f, mi1 = -1e30f, li0 = 0.f, li1 = 0.f;
#pragma unroll 1
    for (int ch = 0; ch < 8; ch++) {
        const int j0 = 80 + ch * 32;
        float sc[4][4];
#pragma unroll
        for (int i = 0; i < 4; i++)
#pragma unroll
            for (int c = 0; c < 4; c++) sc[i][c] = 0.f;
#pragma unroll
        for (int kk = 0; kk < 4; kk++) {
#pragma unroll
            for (int p2 = 0; p2 < 2; p2++) {
                uint32_t kh4[4], kl4[4];
                uint32_t ad = sb + AT_KHI + (uint32_t)(j0 + p2 * 16 + brow) * 144
                              + kk * 32 + bdb;
                LDMX4(kh4[0], kh4[1], kh4[2], kh4[3], ad);
                LDMX4(kl4[0], kl4[1], kl4[2], kl4[3], ad + (AT_KLO - AT_KHI));
                MMA16816(sc[2 * p2], qh[kk], kh4[0], kh4[1]);
                MMA16816(sc[2 * p2], ql[kk], kh4[0], kh4[1]);
                MMA16816(sc[2 * p2], qh[kk], kl4[0], kl4[1]);
                MMA16816(sc[2 * p2 + 1], qh[kk], kh4[2], kh4[3]);
                MMA16816(sc[2 * p2 + 1], ql[kk], kh4[2], kh4[3]);
                MMA16816(sc[2 * p2 + 1], qh[kk], kl4[2], kl4[3]);
            }
        }
        float cm0 = -1e30f, cm1 = -1e30f;
#pragma unroll
        for (int t = 0; t < 4; t++) {
            cm0 = fmaxf(cm0, fmaxf(sc[t][0], sc[t][1]));
            cm1 = fmaxf(cm1, fmaxf(sc[t][2], sc[t][3]));
        }
        cm0 = fmaxf(cm0, __shfl_xor_sync(FULL, cm0, 1));
        cm0 = fmaxf(cm0, __shfl_xor_sync(FULL, cm0, 2));
        cm1 = fmaxf(cm1, __shfl_xor_sync(FULL, cm1, 1));
        cm1 = fmaxf(cm1, __shfl_xor_sync(FULL, cm1, 2));
        float mn0 = fmaxf(mi0, cm0), mn1 = fmaxf(mi1, cm1);
        float al0 = __expf(mi0 - mn0), al1 = __expf(mi1 - mn1);
        float cs0 = 0.f, cs1 = 0.f;
#pragma unroll
        for (int t = 0; t < 4; t++) {
            sc[t][0] = __expf(sc[t][0] - mn0); cs0 += sc[t][0];
            sc[t][1] = __expf(sc[t][1] - mn0); cs0 += sc[t][1];
            sc[t][2] = __expf(sc[t][2] - mn1); cs1 += sc[t][2];
            sc[t][3] = __expf(sc[t][3] - mn1); cs1 += sc[t][3];
        }
        cs0 += __shfl_xor_sync(FULL, cs0, 1); cs0 += __shfl_xor_sync(FULL, cs0, 2);
        cs1 += __shfl_xor_sync(FULL, cs1, 1); cs1 += __shfl_xor_sync(FULL, cs1, 2);
        li0 = li0 * al0 + cs0; li1 = li1 * al1 + cs1;
        mi0 = mn0; mi1 = mn1;
#pragma unroll
        for (int dt = 0; dt < 8; dt++) {
            oi[dt][0] *= al0; oi[dt][1] *= al0;
            oi[dt][2] *= al1; oi[dt][3] *= al1;
        }
#pragma unroll
        for (int wk = 0; wk < 2; wk++) {
            uint32_t ahi[4], alo[4];
            wsplit(sc[2 * wk], sc[2 * wk + 1], ahi, alo);
#pragma unroll
            for (int dp = 0; dp < 4; dp++) {
                uint32_t vh4[4], vl4[4];
                uint32_t ad = sb + AT_VHI + (uint32_t)(j0 + wk * 16 + vrow) * 144
                              + dp * 32 + vdb;
                LDMX4T(vh4[0], vh4[1], vh4[2], vh4[3], ad);
                LDMX4T(vl4[0], vl4[1], vl4[2], vl4[3], ad + (AT_VLO - AT_VHI));
                MMA16816(oi[2 * dp], ahi, vh4[0], vh4[1]);
                MMA16816(oi[2 * dp], alo, vh4[0], vh4[1]);
                MMA16816(oi[2 * dp], ahi, vl4[0], vl4[1]);
                MMA16816(oi[2 * dp + 1], ahi, vh4[2], vh4[3]);
                MMA16816(oi[2 * dp + 1], alo, vh4[2], vh4[3]);
                MMA16816(oi[2 * dp + 1], ahi, vl4[2], vl4[3]);
            }
        }
    }
    float ii0 = 1.f / li0, ii1 = 1.f / li1;

    {
        size_t ob = ((size_t)(b * NQ_ + i0 + r0l)) * 1024 + h * 64 + 2 * (lane & 3);
#pragma unroll
        for (int dt = 0; dt < 8; dt++) {
            float v0 = ot[dt][0] + oi[dt][0] * ii0;
            float v1 = ot[dt][1] + oi[dt][1] * ii0;
            float v2 = ot[dt][2] + oi[dt][2] * ii1;
            float v3 = ot[dt][3] + oi[dt][3] * ii1;
            float h0 = __half2float(__float2half(v0));
            float h1 = __half2float(__float2half(v1));
            float h2 = __half2float(__float2half(v2));
            float h3 = __half2float(__float2half(v3));
            size_t o0 = ob + dt * 8;
            size_t o1 = o0 + 8 * 1024;
            *(uint32_t*)(atthi + o0) = packh(h0, h1);
            *(uint32_t*)(attlo + o0) = packh(v0 - h0, v1 - h1);
            *(uint32_t*)(atthi + o1) = packh(h2, h3);
            *(uint32_t*)(attlo + o1) = packh(v2 - h2, v3 - h3);
        }
    }
}

// ---------------------------------------------------------------------------
// Host launcher
// ---------------------------------------------------------------------------
extern "C" void kernel_launch(void* const* d_in, const int* in_sizes, int n_in,
                              void* d_out, int out_size)
{
    const float* x     = (const float*)d_in[0];
    const float* ctx   = (const float*)d_in[1];
    const float* Wq    = (const float*)d_in[2];
    const float* Wk    = (const float*)d_in[3];
    const float* Wv    = (const float*)d_in[4];
    const float* Wk_ip = (const float*)d_in[5];
    const float* Wv_ip = (const float*)d_in[6];
    const float* Wout  = (const float*)d_in[7];
    const float* bout  = (const float*)d_in[8];
    const float* relk  = (const float*)d_in[9];
    const float* relv  = (const float*)d_in[10];
    float* out = (float*)d_out;

    __half *pahi, *palo, *pqhi, *pqlo, *pchi, *pclo, *pwhi, *pwlo;
    __half *pkthi, *pktlo, *pvthi, *pvtlo, *pkihi, *pkilo, *pvihi, *pvilo;
    cudaGetSymbolAddress((void**)&pahi, g_ahi);
    cudaGetSymbolAddress((void**)&palo, g_alo);
    cudaGetSymbolAddress((void**)&pqhi, g_qhi);
    cudaGetSymbolAddress((void**)&pqlo, g_qlo);
    cudaGetSymbolAddress((void**)&pchi, g_chi);
    cudaGetSymbolAddress((void**)&pclo, g_clo);
    cudaGetSymbolAddress((void**)&pwhi, g_whi);
    cudaGetSymbolAddress((void**)&pwlo, g_wlo);
    cudaGetSymbolAddress((void**)&pkthi, g_kthi);
    cudaGetSymbolAddress((void**)&pktlo, g_ktlo);
    cudaGetSymbolAddress((void**)&pvthi, g_vthi);
    cudaGetSymbolAddress((void**)&pvtlo, g_vtlo);
    cudaGetSymbolAddress((void**)&pkihi, g_kihi);
    cudaGetSymbolAddress((void**)&pkilo, g_kilo);
    cudaGetSymbolAddress((void**)&pvihi, g_vihi);
    cudaGetSymbolAddress((void**)&pvilo, g_vilo);

    cudaFuncSetAttribute(gemm_mma<0, 2>,
                         cudaFuncAttributeMaxDynamicSharedMemorySize, GM_SMEM);
    cudaFuncSetAttribute(gemm_mma<1, 3>,
                         cudaFuncAttributeMaxDynamicSharedMemorySize, GM_SMEM);
    cudaFuncSetAttribute(gemm_mma<2, 3>,
                         cudaFuncAttributeMaxDynamicSharedMemorySize, GM_SMEM);
    cudaFuncSetAttribute(attn_mma,
                         cudaFuncAttributeMaxDynamicSharedMemorySize, AT_SMEM);

    const size_t WSZ = (size_t)DM_ * DM_;
    size_t nx = (size_t)B_ * NQ_ * DM_;
    size_t nc = (size_t)B_ * CTXR * DM_;

    // launches 1-5 (ncu -s 5 profiles launch 6 = the big Q GEMM)
    conv_wt<<<dim3(32, 32), dim3(32, 8)>>>(Wq, pwhi + 0 * WSZ, pwlo + 0 * WSZ);
    conv_rows<<<(unsigned)(nx / 4 / 256), 256>>>(x, pahi, palo, nx);
    conv_rows<<<(unsigned)((nc / 4 + 255) / 256), 256>>>(ctx, pchi, pclo, nc);
    conv_wt<<<dim3(32, 32), dim3(32, 8)>>>(Wk, pwhi + 1 * WSZ, pwlo + 1 * WSZ);
    conv_wt<<<dim3(32, 32), dim3(32, 8)>>>(Wv, pwhi + 2 * WSZ, pwlo + 2 * WSZ);

    // launch 6: Q = (x @ Wq) * 0.125 -> fp16 hi/lo
    gemm_mma<2, 3><<<dim3(8, 512), 256, GM_SMEM>>>(
        pahi, palo, pwhi + 0 * WSZ, pwlo + 0 * WSZ, nullptr, nullptr,
        pqhi, pqlo, B_ * NQ_, B_ * NQ_, B_ * NQ_, 0);

    conv_wt<<<dim3(32, 32), dim3(32, 8)>>>(Wk_ip, pwhi + 3 * WSZ, pwlo + 3 * WSZ);
    conv_wt<<<dim3(32, 32), dim3(32, 8)>>>(Wv_ip, pwhi + 4 * WSZ, pwlo + 4 * WSZ);
    conv_wt<<<dim3(32, 32), dim3(32, 8)>>>(Wout,  pwhi + 5 * WSZ, pwlo + 5 * WSZ);

    // K/V text -> [b][h][t][d] fp16 hi/lo
    gemm_mma<1, 3><<<dim3(8, 39), 256, GM_SMEM>>>(
        pchi, pclo, pwhi + 1 * WSZ, pwlo + 1 * WSZ, nullptr, nullptr,
        pkthi, pktlo, B_ * LT_, LT_, CTXR, 0);
    gemm_mma<1, 3><<<dim3(8, 39), 256, GM_SMEM>>>(
        pchi, pclo, pwhi + 2 * WSZ, pwlo + 2 * WSZ, nullptr, nullptr,
        pvthi, pvtlo, B_ * LT_, LT_, CTXR, 0);

    // K/V image
    gemm_mma<1, 3><<<dim3(8, 128), 256, GM_SMEM>>>(
        pchi, pclo, pwhi + 3 * WSZ, pwlo + 3 * WSZ, nullptr, nullptr,
        pkihi, pkilo, B_ * LI_, LI_, CTXR, LT_);
    gemm_mma<1, 3><<<dim3(8, 128), 256, GM_SMEM>>>(
        pchi, pclo, pwhi + 4 * WSZ, pwlo + 4 * WSZ, nullptr, nullptr,
        pvihi, pvilo, B_ * LI_, LI_, CTXR, LT_);

    // tensor-core attention -> fp16 hi/lo into final-GEMM input buffers
    attn_mma<<<B_ * H_ * 8, 256, AT_SMEM>>>(
        pqhi, pqlo, pkthi, pktlo, pvthi, pvtlo,
        pkihi, pkilo, pvihi, pvilo, relk, relv, pahi, palo);

    // final projection + bias (2-term: Wout lo dropped)
    gemm_mma<0, 2><<<dim3(8, 512), 256, GM_SMEM>>>(
        pahi, palo, pwhi + 5 * WSZ, pwlo + 5 * WSZ, out, bout,
        nullptr, nullptr, B_ * NQ_, B_ * NQ_, B_ * NQ_, 0);
}

// round 7
// speedup vs baseline: 3.4578x; 1.1236x over previous
#include <cuda_runtime.h>
#include <cuda_fp16.h>
#include <cstdint>

// ---------------------------------------------------------------------------
// Problem constants
// ---------------------------------------------------------------------------
#define B_    64
#define NQ_   1024
#define DM_   1024
#define H_    16
#define D_    64
#define LT_   77
#define LI_   256
#define NR_   33
#define CTXR  (LT_ + LI_)     // 333

__device__ __forceinline__ uint32_t smem_to_u32(const void* p) {
    uint32_t a;
    asm("{ .reg .u64 t; cvta.to.shared.u64 t, %1; cvt.u32.u64 %0, t; }"
        : "=r"(a) : "l"(p));
    return a;
}

#define CPA16(dst, src) \
    asm volatile("cp.async.cg.shared.global [%0], [%1], 16;" \
                 :: "r"(dst), "l"(src))
#define CPA_COMMIT() asm volatile("cp.async.commit_group;" ::: "memory")
#define CPA_WAIT(n)  asm volatile("cp.async.wait_group %0;" :: "n"(n) : "memory")

#define LDMX4(r0, r1, r2, r3, addr) \
    asm volatile("ldmatrix.sync.aligned.m8n8.x4.shared.b16 {%0,%1,%2,%3}, [%4];" \
                 : "=r"(r0), "=r"(r1), "=r"(r2), "=r"(r3) : "r"(addr))
#define LDMX4T(r0, r1, r2, r3, addr) \
    asm volatile("ldmatrix.sync.aligned.m8n8.x4.trans.shared.b16 {%0,%1,%2,%3}, [%4];" \
                 : "=r"(r0), "=r"(r1), "=r"(r2), "=r"(r3) : "r"(addr))

#define MMA16816(c, a, b0, b1) \
    asm volatile("mma.sync.aligned.m16n8k16.row.col.f32.f16.f16.f32 " \
                 "{%0,%1,%2,%3}, {%4,%5,%6,%7}, {%8,%9}, {%0,%1,%2,%3};" \
                 : "+f"((c)[0]), "+f"((c)[1]), "+f"((c)[2]), "+f"((c)[3]) \
                 : "r"((a)[0]), "r"((a)[1]), "r"((a)[2]), "r"((a)[3]), \
                   "r"(b0), "r"(b1))

__device__ __forceinline__ uint32_t packh(float lo, float hi) {
    uint32_t d;
    asm("cvt.rn.f16x2.f32 %0, %1, %2;" : "=r"(d) : "f"(hi), "f"(lo));
    return d;
}

// ---------------------------------------------------------------------------
// Scratch (static device globals)
// ---------------------------------------------------------------------------
__device__ __half g_ahi[(size_t)B_ * NQ_ * DM_];  // x hi, later att hi
__device__ __half g_alo[(size_t)B_ * NQ_ * DM_];
__device__ __half g_qhi[(size_t)B_ * NQ_ * DM_];
__device__ __half g_qlo[(size_t)B_ * NQ_ * DM_];
__device__ __half g_chi[(size_t)B_ * CTXR * DM_];
__device__ __half g_clo[(size_t)B_ * CTXR * DM_];
__device__ __half g_whi[6 * (size_t)DM_ * DM_];
__device__ __half g_wlo[6 * (size_t)DM_ * DM_];
__device__ __half g_kthi[(size_t)B_ * H_ * LT_ * D_];
__device__ __half g_ktlo[(size_t)B_ * H_ * LT_ * D_];
__device__ __half g_vthi[(size_t)B_ * H_ * LT_ * D_];
__device__ __half g_vtlo[(size_t)B_ * H_ * LT_ * D_];
__device__ __half g_kihi[(size_t)B_ * H_ * LI_ * D_];
__device__ __half g_kilo[(size_t)B_ * H_ * LI_ * D_];
__device__ __half g_vihi[(size_t)B_ * H_ * LI_ * D_];
__device__ __half g_vilo[(size_t)B_ * H_ * LI_ * D_];

// ---------------------------------------------------------------------------
// fp32 -> fp16 hi/lo split
// ---------------------------------------------------------------------------
__global__ void conv_rows(const float* __restrict__ src,
                          __half* __restrict__ hi,
                          __half* __restrict__ lo, size_t n)
{
    size_t i = ((size_t)blockIdx.x * blockDim.x + threadIdx.x) * 4;
    if (i >= n) return;
    float4 v = *(const float4*)(src + i);
    float h0 = __half2float(__float2half(v.x));
    float h1 = __half2float(__float2half(v.y));
    float h2 = __half2float(__float2half(v.z));
    float h3 = __half2float(__float2half(v.w));
    *(uint2*)(hi + i) = make_uint2(packh(h0, h1), packh(h2, h3));
    *(uint2*)(lo + i) = make_uint2(packh(v.x - h0, v.y - h1),
                                   packh(v.z - h2, v.w - h3));
}

// W [K=1024, N=1024] -> Wt hi/lo [N, K]
__global__ void conv_wt(const float* __restrict__ W,
                        __half* __restrict__ hi,
                        __half* __restrict__ lo)
{
    __shared__ float tile[32][33];
    const int k0 = blockIdx.y * 32, n0 = blockIdx.x * 32;
    const int tx = threadIdx.x;
    for (int r = threadIdx.y; r < 32; r += 8)
        tile[r][tx] = W[(size_t)(k0 + r) * DM_ + n0 + tx];
    __syncthreads();
    for (int r = threadIdx.y; r < 32; r += 8) {
        float v = tile[tx][r];
        float h = __half2float(__float2half(v));
        size_t oi = (size_t)(n0 + r) * DM_ + k0 + tx;
        hi[oi] = __float2half(h);
        lo[oi] = __float2half(v - h);
    }
}

// ---------------------------------------------------------------------------
// fp16 split GEMM via mma.sync: C[M,1024] = remap(A)[M,1024] @ B^T (B is [N,K])
// MODE 0: fp32 C + bias.  MODE 1: KV scatter fp16 hi/lo.  MODE 2: Q *0.125.
// TERMS 3: AhiBhi + AloBhi + AhiBlo.  TERMS 2: AhiBhi + AloBhi (Blo not loaded).
// CTA 128x128, BK=32, 2-stage cp.async pipeline, 2 CTAs/SM.
// ---------------------------------------------------------------------------
#define BUF_BYTES   40960
#define GM_SMEM     (2 * BUF_BYTES)

template <int MODE, int TERMS>
__global__ void __launch_bounds__(256, 2)
gemm_mma(const __half* __restrict__ Ahi, const __half* __restrict__ Alo,
         const __half* __restrict__ Bhi, const __half* __restrict__ Blo,
         float* __restrict__ C, const float* __restrict__ bias,
         __half* __restrict__ Chi, __half* __restrict__ Clo,
         int M, int rows_per_seg, int seg_stride, int seg_base)
{
    extern __shared__ __align__(128) char smem[];
    const uint32_t sb = smem_to_u32(smem);
    const int tid = threadIdx.x;
    const int bn = blockIdx.x * 128;
    const int bm = blockIdx.y * 128;
    const int wid = tid >> 5, lane = tid & 31;
    const int Wm = (wid & 3) * 32;
    const int Wn = (wid >> 2) * 64;

    const int lrow = tid >> 1;
    const int lc = tid & 1;
    int m = bm + lrow; if (m > M - 1) m = M - 1;
    const int seg = m / rows_per_seg;
    const int t = m - seg * rows_per_seg;
    const size_t aoff = (size_t)(seg * seg_stride + seg_base + t) * 1024 + lc * 16;
    const size_t boff = (size_t)(bn + lrow) * 1024 + lc * 16;
    const uint32_t soff = (uint32_t)lrow * 80u + (uint32_t)lc * 32u;

    float acc[2][8][4];
#pragma unroll
    for (int i = 0; i < 2; i++)
#pragma unroll
        for (int j = 0; j < 8; j++)
#pragma unroll
            for (int c = 0; c < 4; c++) acc[i][j][c] = 0.f;

    const uint32_t a_frag_row = (uint32_t)(Wm + (lane & 15)) * 80u + ((lane >> 4) * 16u);
    const uint32_t b_frag_row =
        (uint32_t)(Wn + (lane & 7) + ((lane >> 4) << 3)) * 80u + (((lane >> 3) & 1) * 16u);

#define ISSUE(p, k0)                                                       \
    {                                                                      \
        uint32_t d = sb + (p) * BUF_BYTES + soff;                          \
        const __half* s;                                                   \
        s = Ahi + aoff + (k0); CPA16(d,           s); CPA16(d + 16,         s + 8); \
        s = Alo + aoff + (k0); CPA16(d + 10240,   s); CPA16(d + 10240 + 16, s + 8); \
        s = Bhi + boff + (k0); CPA16(d + 20480,   s); CPA16(d + 20480 + 16, s + 8); \
        if (TERMS == 3) {                                                  \
            s = Blo + boff + (k0); CPA16(d + 30720, s); CPA16(d + 30720 + 16, s + 8); \
        }                                                                  \
    }

    ISSUE(0, 0);
    CPA_COMMIT();

    for (int i = 0; i < 32; i++) {
        if (i + 1 < 32) {
            ISSUE((i + 1) & 1, (i + 1) * 32);
            CPA_COMMIT();
            CPA_WAIT(1);
        } else {
            CPA_WAIT(0);
        }
        __syncthreads();

        const uint32_t base = sb + (i & 1) * BUF_BYTES;
#pragma unroll
        for (int kk = 0; kk < 2; kk++) {
            uint32_t ah[2][4], al[2][4];
            const uint32_t ar = base + a_frag_row + kk * 32;
            LDMX4(ah[0][0], ah[0][1], ah[0][2], ah[0][3], ar);
            LDMX4(ah[1][0], ah[1][1], ah[1][2], ah[1][3], ar + 16 * 80);
            LDMX4(al[0][0], al[0][1], al[0][2], al[0][3], ar + 10240);
            LDMX4(al[1][0], al[1][1], al[1][2], al[1][3], ar + 10240 + 16 * 80);
#pragma unroll
            for (int j = 0; j < 4; j++) {
                uint32_t bh0, bh1, bh2, bh3;
                const uint32_t br = base + b_frag_row + kk * 32 + (uint32_t)j * (16 * 80);
                LDMX4(bh0, bh1, bh2, bh3, br + 20480);
                uint32_t bl0 = 0, bl1 = 0, bl2 = 0, bl3 = 0;
                if (TERMS == 3) { LDMX4(bl0, bl1, bl2, bl3, br + 30720); }
#pragma unroll
                for (int mt = 0; mt < 2; mt++) {
                    MMA16816(acc[mt][2 * j],     ah[mt], bh0, bh1);
                    MMA16816(acc[mt][2 * j],     al[mt], bh0, bh1);
                    MMA16816(acc[mt][2 * j + 1], ah[mt], bh2, bh3);
                    MMA16816(acc[mt][2 * j + 1], al[mt], bh2, bh3);
                    if (TERMS == 3) {
                        MMA16816(acc[mt][2 * j],     ah[mt], bl0, bl1);
                        MMA16816(acc[mt][2 * j + 1], ah[mt], bl2, bl3);
                    }
                }
            }
        }
        __syncthreads();
    }
#undef ISSUE

    const int er = lane >> 2, ec = (lane & 3) * 2;
#pragma unroll
    for (int mt = 0; mt < 2; mt++) {
#pragma unroll
        for (int hrow = 0; hrow < 2; hrow++) {
            const int cm = bm + Wm + mt * 16 + er + hrow * 8;
            if (cm >= M) continue;
            if (MODE == 1) {
                const int segc = cm / rows_per_seg;
                const int tc = cm - segc * rows_per_seg;
#pragma unroll
                for (int nt = 0; nt < 8; nt++) {
                    const int cn = bn + Wn + nt * 8 + ec;
                    const int hh = cn >> 6, dd = cn & 63;
                    size_t oi = (((size_t)segc * H_ + hh) * rows_per_seg + tc) * 64 + dd;
                    float v0 = acc[mt][nt][hrow * 2], v1 = acc[mt][nt][hrow * 2 + 1];
                    float h0 = __half2float(__float2half(v0));
                    float h1 = __half2float(__float2half(v1));
                    *(uint32_t*)(Chi + oi) = packh(h0, h1);
                    *(uint32_t*)(Clo + oi) = packh(v0 - h0, v1 - h1);
                }
            } else if (MODE == 2) {
#pragma unroll
                for (int nt = 0; nt < 8; nt++) {
                    const int cn = bn + Wn + nt * 8 + ec;
                    size_t oi = (size_t)cm * DM_ + cn;
                    float v0 = acc[mt][nt][hrow * 2] * 0.125f;
                    float v1 = acc[mt][nt][hrow * 2 + 1] * 0.125f;
                    float h0 = __half2float(__float2half(v0));
                    float h1 = __half2float(__float2half(v1));
                    *(uint32_t*)(Chi + oi) = packh(h0, h1);
                    *(uint32_t*)(Clo + oi) = packh(v0 - h0, v1 - h1);
                }
            } else {
                float* Cp = C + (size_t)cm * DM_ + bn + Wn + ec;
                const float* bp = bias + bn + Wn + ec;
#pragma unroll
                for (int nt = 0; nt < 8; nt++) {
                    float2 v = make_float2(acc[mt][nt][hrow * 2] + bp[nt * 8],
                                           acc[mt][nt][hrow * 2 + 1] + bp[nt * 8 + 1]);
                    *(float2*)(Cp + nt * 8) = v;
                }
            }
        }
    }
}

// ---------------------------------------------------------------------------
// Tensor-core flash attention (fp16 hi/lo). One CTA = (b, h, 128-query tile).
// ---------------------------------------------------------------------------
#define AT_KHI 0
#define AT_KLO 48384
#define AT_VHI 96768
#define AT_VLO 145152
#define AT_QHI 193536
#define AT_QLO 211968
#define AT_PS  193536
#define AT_RKH 211968
#define AT_RKL 217728
#define AT_SMEM 230400

__device__ __forceinline__ int bidx(int j, int i)
{
    int d = j - i;
    d = max(-16, min(16, d));
    return d + 16;
}

__device__ __forceinline__ void wsplit(const float* s0, const float* s1,
                                       uint32_t* ahi, uint32_t* alo)
{
    float v[8] = {s0[0], s0[1], s0[2], s0[3], s1[0], s1[1], s1[2], s1[3]};
    float hv[8];
#pragma unroll
    for (int i = 0; i < 8; i++)
        hv[i] = __half2float(__float2half(v[i]));
    ahi[0] = packh(hv[0], hv[1]); ahi[1] = packh(hv[2], hv[3]);
    ahi[2] = packh(hv[4], hv[5]); ahi[3] = packh(hv[6], hv[7]);
    alo[0] = packh(v[0] - hv[0], v[1] - hv[1]);
    alo[1] = packh(v[2] - hv[2], v[3] - hv[3]);
    alo[2] = packh(v[4] - hv[4], v[5] - hv[5]);
    alo[3] = packh(v[6] - hv[6], v[7] - hv[7]);
}

__global__ void __launch_bounds__(256, 1)
attn_mma(const __half* __restrict__ qhi, const __half* __restrict__ qlo,
         const __half* __restrict__ kthi, const __half* __restrict__ ktlo,
         const __half* __restrict__ vthi, const __half* __restrict__ vtlo,
         const __half* __restrict__ kihi, const __half* __restrict__ kilo,
         const __half* __restrict__ vihi, const __half* __restrict__ vilo,
         const float* __restrict__ relk, const float* __restrict__ relv,
         __half* __restrict__ atthi, __half* __restrict__ attlo)
{
    extern __shared__ __align__(128) char sm[];
    const uint32_t sb = smem_to_u32(sm);
    const int tid = threadIdx.x, w = tid >> 5, lane = tid & 31;
    const int bh = blockIdx.x >> 3, qt = blockIdx.x & 7;
    const int b = bh >> 4, h = bh & 15;
    const int i0 = qt * 128;
    const unsigned FULL = 0xffffffffu;

    // ---- stage K/V/Q ----
    {
        size_t tb = (size_t)bh * (LT_ * 64);
        for (int idx = tid; idx < LT_ * 8; idx += 256) {
            int r = idx >> 3, c = idx & 7;
            uint32_t d = (uint32_t)r * 144 + c * 16;
            size_t s = tb + (size_t)r * 64 + c * 8;
            CPA16(sb + AT_KHI + d, kthi + s);
            CPA16(sb + AT_KLO + d, ktlo + s);
            CPA16(sb + AT_VHI + d, vthi + s);
            CPA16(sb + AT_VLO + d, vtlo + s);
        }
        size_t ib = (size_t)bh * (LI_ * 64);
        for (int idx = tid; idx < LI_ * 8; idx += 256) {
            int r = idx >> 3, c = idx & 7;
            uint32_t d = (uint32_t)(80 + r) * 144 + c * 16;
            size_t s = ib + (size_t)r * 64 + c * 8;
            CPA16(sb + AT_KHI + d, kihi + s);
            CPA16(sb + AT_KLO + d, kilo + s);
            CPA16(sb + AT_VHI + d, vihi + s);
            CPA16(sb + AT_VLO + d, vilo + s);
        }
        size_t qb = ((size_t)(b * NQ_ + i0)) * 1024 + h * 64;
        for (int idx = tid; idx < 128 * 8; idx += 256) {
            int r = idx >> 3, c = idx & 7;
            uint32_t d = (uint32_t)r * 144 + c * 16;
            size_t s = qb + (size_t)r * 1024 + c * 8;
            CPA16(sb + AT_QHI + d, qhi + s);
            CPA16(sb + AT_QLO + d, qlo + s);
        }
        for (int idx = tid; idx < 3 * 36; idx += 256) {
            uint32_t d = (uint32_t)(77 + idx / 36) * 144 + (idx % 36) * 4;
            *(uint32_t*)(sm + AT_KHI + d) = 0;
            *(uint32_t*)(sm + AT_KLO + d) = 0;
            *(uint32_t*)(sm + AT_VHI + d) = 0;
            *(uint32_t*)(sm + AT_VLO + d) = 0;
        }
        CPA_COMMIT();
        CPA_WAIT(0);
        __syncthreads();
    }

    const int wr = w * 16;
    const int r0l = wr + (lane >> 2);

    // ---- Q fragments ----
    uint32_t qh[4][4], ql[4][4];
    {
        int row = wr + (lane & 15);
        int kb = (lane >> 4) * 16;
#pragma unroll
        for (int kk = 0; kk < 4; kk++) {
            uint32_t a = sb + AT_QHI + (uint32_t)row * 144 + kk * 32 + kb;
            LDMX4(qh[kk][0], qh[kk][1], qh[kk][2], qh[kk][3], a);
            LDMX4(ql[kk][0], ql[kk][1], ql[kk][2], ql[kk][3], a + (AT_QLO - AT_QHI));
        }
    }
    __syncthreads();

    if (qt == 0) {
        for (int idx = tid; idx < NR_ * 64; idx += 256) {
            int r = idx >> 6, dc = idx & 63;
            float v = relk[idx];
            float hh = __half2float(__float2half(v));
            *(__half*)(sm + AT_RKH + r * 144 + dc * 2) = __float2half(hh);
            *(__half*)(sm + AT_RKL + r * 144 + dc * 2) = __float2half(v - hh);
        }
    }
    __syncthreads();

    float* pS = (float*)(sm + AT_PS);

    const int brow = ((lane >> 4) << 3) + (lane & 7);
    const int bdb = (lane & 8) * 2;

    // ---- rel-K projections (tile 0) ----
    if (qt == 0) {
        float pr[5][4];
#pragma unroll
        for (int i = 0; i < 5; i++)
#pragma unroll
            for (int c = 0; c < 4; c++) pr[i][c] = 0.f;
#pragma unroll
        for (int kk = 0; kk < 4; kk++) {
#pragma unroll
            for (int p2 = 0; p2 < 3; p2++) {
                uint32_t bh4[4], bl4[4];
                uint32_t ad = sb + AT_RKH + (uint32_t)(p2 * 16 + brow) * 144
                              + kk * 32 + bdb;
                LDMX4(bh4[0], bh4[1], bh4[2], bh4[3], ad);
                LDMX4(bl4[0], bl4[1], bl4[2], bl4[3], ad + (AT_RKL - AT_RKH));
                MMA16816(pr[2 * p2], qh[kk], bh4[0], bh4[1]);
                MMA16816(pr[2 * p2], ql[kk], bh4[0], bh4[1]);
                MMA16816(pr[2 * p2], qh[kk], bl4[0], bl4[1]);
                if (p2 < 2) {
                    MMA16816(pr[2 * p2 + 1], qh[kk], bh4[2], bh4[3]);
                    MMA16816(pr[2 * p2 + 1], ql[kk], bh4[2], bh4[3]);
                    MMA16816(pr[2 * p2 + 1], qh[kk], bl4[2], bl4[3]);
                }
            }
        }
#pragma unroll
        for (int nt = 0; nt < 5; nt++) {
            int c0 = nt * 8 + 2 * (lane & 3);
            if (c0 < NR_) {
                pS[r0l * 34 + c0] = pr[nt][0];
                pS[(r0l + 8) * 34 + c0] = pr[nt][2];
            }
            if (c0 + 1 < NR_) {
                pS[r0l * 34 + c0 + 1] = pr[nt][1];
                pS[(r0l + 8) * 34 + c0 + 1] = pr[nt][3];
            }
        }
        __syncwarp();
    }

    // ---- text scores ----
    float s[10][4];
#pragma unroll
    for (int i = 0; i < 10; i++)
#pragma unroll
        for (int c = 0; c < 4; c++) s[i][c] = 0.f;
#pragma unroll
    for (int kk = 0; kk < 4; kk++) {
#pragma unroll
        for (int p2 = 0; p2 < 5; p2++) {
            uint32_t kh4[4], kl4[4];
            uint32_t ad = sb + AT_KHI + (uint32_t)(p2 * 16 + brow) * 144
                          + kk * 32 + bdb;
            LDMX4(kh4[0], kh4[1], kh4[2], kh4[3], ad);
            LDMX4(kl4[0], kl4[1], kl4[2], kl4[3], ad + (AT_KLO - AT_KHI));
            MMA16816(s[2 * p2], qh[kk], kh4[0], kh4[1]);
            MMA16816(s[2 * p2], ql[kk], kh4[0], kh4[1]);
            MMA16816(s[2 * p2], qh[kk], kl4[0], kl4[1]);
            MMA16816(s[2 * p2 + 1], qh[kk], kh4[2], kh4[3]);
            MMA16816(s[2 * p2 + 1], ql[kk], kh4[2], kh4[3]);
            MMA16816(s[2 * p2 + 1], qh[kk], kl4[2], kl4[3]);
        }
    }

#pragma unroll
    for (int nt = 0; nt < 10; nt++) {
        int c0 = nt * 8 + 2 * (lane & 3);
        if (qt == 0) {
            s[nt][0] += pS[r0l * 34 + bidx(c0, r0l)];
            s[nt][1] += pS[r0l * 34 + bidx(c0 + 1, r0l)];
            s[nt][2] += pS[(r0l + 8) * 34 + bidx(c0, r0l + 8)];
            s[nt][3] += pS[(r0l + 8) * 34 + bidx(c0 + 1, r0l + 8)];
        }
        if (c0 >= LT_) { s[nt][0] = -1e30f; s[nt][2] = -1e30f; }
        if (c0 + 1 >= LT_) { s[nt][1] = -1e30f; s[nt][3] = -1e30f; }
    }

    float m0 = -1e30f, m1 = -1e30f;
#pragma unroll
    for (int nt = 0; nt < 10; nt++) {
        m0 = fmaxf(m0, fmaxf(s[nt][0], s[nt][1]));
        m1 = fmaxf(m1, fmaxf(s[nt][2], s[nt][3]));
    }
    m0 = fmaxf(m0, __shfl_xor_sync(FULL, m0, 1));
    m0 = fmaxf(m0, __shfl_xor_sync(FULL, m0, 2));
    m1 = fmaxf(m1, __shfl_xor_sync(FULL, m1, 1));
    m1 = fmaxf(m1, __shfl_xor_sync(FULL, m1, 2));
    float l0 = 0.f, l1 = 0.f;
#pragma unroll
    for (int nt = 0; nt < 10; nt++) {
        s[nt][0] = __expf(s[nt][0] - m0); l0 += s[nt][0];
        s[nt][1] = __expf(s[nt][1] - m0); l0 += s[nt][1];
        s[nt][2] = __expf(s[nt][2] - m1); l1 += s[nt][2];
        s[nt][3] = __expf(s[nt][3] - m1); l1 += s[nt][3];
    }
    l0 += __shfl_xor_sync(FULL, l0, 1); l0 += __shfl_xor_sync(FULL, l0, 2);
    l1 += __shfl_xor_sync(FULL, l1, 1); l1 += __shfl_xor_sync(FULL, l1, 2);
    float inv0 = 1.f / l0, inv1 = 1.f / l1;
#pragma unroll
    for (int nt = 0; nt < 10; nt++) {
        s[nt][0] *= inv0; s[nt][1] *= inv0;
        s[nt][2] *= inv1; s[nt][3] *= inv1;
    }

    if (qt == 0) {
        for (int idx = lane; idx < 16 * 34; idx += 32)
            pS[(wr + idx / 34) * 34 + idx % 34] = 0.f;
        __syncwarp();
#pragma unroll
        for (int nt = 0; nt < 10; nt++) {
            int c0 = nt * 8 + 2 * (lane & 3);
            if (c0 < LT_) {
                atomicAdd(&pS[r0l * 34 + bidx(c0, r0l)], s[nt][0]);
                atomicAdd(&pS[(r0l + 8) * 34 + bidx(c0, r0l + 8)], s[nt][2]);
            }
            if (c0 + 1 < LT_) {
                atomicAdd(&pS[r0l * 34 + bidx(c0 + 1, r0l)], s[nt][1]);
                atomicAdd(&pS[(r0l + 8) * 34 + bidx(c0 + 1, r0l + 8)], s[nt][3]);
            }
        }
        __syncwarp();
    }

    const int vrow = (lane & 8) + (lane & 7);
    const int vdb = (lane >> 4) * 16;

    float ot[8][4];
#pragma unroll
    for (int i = 0; i < 8; i++)
#pragma unroll
        for (int c = 0; c < 4; c++) ot[i][c] = 0.f;
#pragma unroll
    for (int wk = 0; wk < 5; wk++) {
        uint32_t ahi[4], alo[4];
        wsplit(s[2 * wk], s[2 * wk + 1], ahi, alo);
#pragma unroll
        for (int dp = 0; dp < 4; dp++) {
            uint32_t vh4[4], vl4[4];
            uint32_t ad = sb + AT_VHI + (uint32_t)(wk * 16 + vrow) * 144
                          + dp * 32 + vdb;
            LDMX4T(vh4[0], vh4[1], vh4[2], vh4[3], ad);
            LDMX4T(vl4[0], vl4[1], vl4[2], vl4[3], ad + (AT_VLO - AT_VHI));
            MMA16816(ot[2 * dp], ahi, vh4[0], vh4[1]);
            MMA16816(ot[2 * dp], alo, vh4[0], vh4[1]);
            MMA16816(ot[2 * dp], ahi, vl4[0], vl4[1]);
            MMA16816(ot[2 * dp + 1], ahi, vh4[2], vh4[3]);
            MMA16816(ot[2 * dp + 1], alo, vh4[2], vh4[3]);
            MMA16816(ot[2 * dp + 1], ahi, vl4[2], vl4[3]);
        }
    }

    if (qt == 0) {
#pragma unroll 1
        for (int r = 0; r < NR_; r++) {
            float w0 = pS[r0l * 34 + r];
            float w1 = pS[(r0l + 8) * 34 + r];
            const float* rv = relv + r * 64 + 2 * (lane & 3);
#pragma unroll
            for (int dt = 0; dt < 8; dt++) {
                float rv0 = rv[dt * 8], rv1 = rv[dt * 8 + 1];
                ot[dt][0] += w0 * rv0; ot[dt][1] += w0 * rv1;
                ot[dt][2] += w1 * rv0; ot[dt][3] += w1 * rv1;
            }
        }
    } else {
        const float* rv = relv + 2 * (lane & 3);
#pragma unroll
        for (int dt = 0; dt < 8; dt++) {
            float rv0 = rv[dt * 8], rv1 = rv[dt * 8 + 1];
            ot[dt][0] += rv0; ot[dt][1] += rv1;
            ot[dt][2] += rv0; ot[dt][3] += rv1;
        }
    }

    float oi[8][4];
#pragma unroll
    for (int i = 0; i < 8; i++)
#pragma unroll
        for (int c = 0; c < 4; c++) oi[i][c] = 0.f;
    float mi0 = -1e30f, mi1 = -1e30f, li0 = 0.f, li1 = 0.f;
#pragma unroll 1
    for (int ch = 0; ch < 8; ch++) {
        const int j0 = 80 + ch * 32;
        float sc[4][4];
#pragma unroll
        for (int i = 0; i < 4; i++)
#pragma unroll
            for (int c = 0; c < 4; c++) sc[i][c] = 0.f;
#pragma unroll
        for (int kk = 0; kk < 4; kk++) {
#pragma unroll
            for (int p2 = 0; p2 < 2; p2++) {
                uint32_t kh4[4], kl4[4];
                uint32_t ad = sb + AT_KHI + (uint32_t)(j0 + p2 * 16 + brow) * 144
                              + kk * 32 + bdb;
                LDMX4(kh4[0], kh4[1], kh4[2], kh4[3], ad);
                LDMX4(kl4[0], kl4[1], kl4[2], kl4[3], ad + (AT_KLO - AT_KHI));
                MMA16816(sc[2 * p2], qh[kk], kh4[0], kh4[1]);
                MMA16816(sc[2 * p2], ql[kk], kh4[0], kh4[1]);
                MMA16816(sc[2 * p2], qh[kk], kl4[0], kl4[1]);
                MMA16816(sc[2 * p2 + 1], qh[kk], kh4[2], kh4[3]);
                MMA16816(sc[2 * p2 + 1], ql[kk], kh4[2], kh4[3]);
                MMA16816(sc[2 * p2 + 1], qh[kk], kl4[2], kl4[3]);
            }
        }
        float cm0 = -1e30f, cm1 = -1e30f;
#pragma unroll
        for (int t = 0; t < 4; t++) {
            cm0 = fmaxf(cm0, fmaxf(sc[t][0], sc[t][1]));
            cm1 = fmaxf(cm1, fmaxf(sc[t][2], sc[t][3]));
        }
        cm0 = fmaxf(cm0, __shfl_xor_sync(FULL, cm0, 1));
        cm0 = fmaxf(cm0, __shfl_xor_sync(FULL, cm0, 2));
        cm1 = fmaxf(cm1, __shfl_xor_sync(FULL, cm1, 1));
        cm1 = fmaxf(cm1, __shfl_xor_sync(FULL, cm1, 2));
        float mn0 = fmaxf(mi0, cm0), mn1 = fmaxf(mi1, cm1);
        float al0 = __expf(mi0 - mn0), al1 = __expf(mi1 - mn1);
        float cs0 = 0.f, cs1 = 0.f;
#pragma unroll
        for (int t = 0; t < 4; t++) {
            sc[t][0] = __expf(sc[t][0] - mn0); cs0 += sc[t][0];
            sc[t][1] = __expf(sc[t][1] - mn0); cs0 += sc[t][1];
            sc[t][2] = __expf(sc[t][2] - mn1); cs1 += sc[t][2];
            sc[t][3] = __expf(sc[t][3] - mn1); cs1 += sc[t][3];
        }
        cs0 += __shfl_xor_sync(FULL, cs0, 1); cs0 += __shfl_xor_sync(FULL, cs0, 2);
        cs1 += __shfl_xor_sync(FULL, cs1, 1); cs1 += __shfl_xor_sync(FULL, cs1, 2);
        li0 = li0 * al0 + cs0; li1 = li1 * al1 + cs1;
        mi0 = mn0; mi1 = mn1;
#pragma unroll
        for (int dt = 0; dt < 8; dt++) {
            oi[dt][0] *= al0; oi[dt][1] *= al0;
            oi[dt][2] *= al1; oi[dt][3] *= al1;
        }
#pragma unroll
        for (int wk = 0; wk < 2; wk++) {
            uint32_t ahi[4], alo[4];
            wsplit(sc[2 * wk], sc[2 * wk + 1], ahi, alo);
#pragma unroll
            for (int dp = 0; dp < 4; dp++) {
                uint32_t vh4[4], vl4[4];
                uint32_t ad = sb + AT_VHI + (uint32_t)(j0 + wk * 16 + vrow) * 144
                              + dp * 32 + vdb;
                LDMX4T(vh4[0], vh4[1], vh4[2], vh4[3], ad);
                LDMX4T(vl4[0], vl4[1], vl4[2], vl4[3], ad + (AT_VLO - AT_VHI));
                MMA16816(oi[2 * dp], ahi, vh4[0], vh4[1]);
                MMA16816(oi[2 * dp], alo, vh4[0], vh4[1]);
                MMA16816(oi[2 * dp], ahi, vl4[0], vl4[1]);
                MMA16816(oi[2 * dp + 1], ahi, vh4[2], vh4[3]);
                MMA16816(oi[2 * dp + 1], alo, vh4[2], vh4[3]);
                MMA16816(oi[2 * dp + 1], ahi, vl4[2], vl4[3]);
            }
        }
    }
    float ii0 = 1.f / li0, ii1 = 1.f / li1;

    {
        size_t ob = ((size_t)(b * NQ_ + i0 + r0l)) * 1024 + h * 64 + 2 * (lane & 3);
#pragma unroll
        for (int dt = 0; dt < 8; dt++) {
            float v0 = ot[dt][0] + oi[dt][0] * ii0;
            float v1 = ot[dt][1] + oi[dt][1] * ii0;
            float v2 = ot[dt][2] + oi[dt][2] * ii1;
            float v3 = ot[dt][3] + oi[dt][3] * ii1;
            float h0 = __half2float(__float2half(v0));
            float h1 = __half2float(__float2half(v1));
            float h2 = __half2float(__float2half(v2));
            float h3 = __half2float(__float2half(v3));
            size_t o0 = ob + dt * 8;
            size_t o1 = o0 + 8 * 1024;
            *(uint32_t*)(atthi + o0) = packh(h0, h1);
            *(uint32_t*)(attlo + o0) = packh(v0 - h0, v1 - h1);
            *(uint32_t*)(atthi + o1) = packh(h2, h3);
            *(uint32_t*)(attlo + o1) = packh(v2 - h2, v3 - h3);
        }
    }
}

// ---------------------------------------------------------------------------
// Host launcher
// ---------------------------------------------------------------------------
extern "C" void kernel_launch(void* const* d_in, const int* in_sizes, int n_in,
                              void* d_out, int out_size)
{
    const float* x     = (const float*)d_in[0];
    const float* ctx   = (const float*)d_in[1];
    const float* Wq    = (const float*)d_in[2];
    const float* Wk    = (const float*)d_in[3];
    const float* Wv    = (const float*)d_in[4];
    const float* Wk_ip = (const float*)d_in[5];
    const float* Wv_ip = (const float*)d_in[6];
    const float* Wout  = (const float*)d_in[7];
    const float* bout  = (const float*)d_in[8];
    const float* relk  = (const float*)d_in[9];
    const float* relv  = (const float*)d_in[10];
    float* out = (float*)d_out;

    __half *pahi, *palo, *pqhi, *pqlo, *pchi, *pclo, *pwhi, *pwlo;
    __half *pkthi, *pktlo, *pvthi, *pvtlo, *pkihi, *pkilo, *pvihi, *pvilo;
    cudaGetSymbolAddress((void**)&pahi, g_ahi);
    cudaGetSymbolAddress((void**)&palo, g_alo);
    cudaGetSymbolAddress((void**)&pqhi, g_qhi);
    cudaGetSymbolAddress((void**)&pqlo, g_qlo);
    cudaGetSymbolAddress((void**)&pchi, g_chi);
    cudaGetSymbolAddress((void**)&pclo, g_clo);
    cudaGetSymbolAddress((void**)&pwhi, g_whi);
    cudaGetSymbolAddress((void**)&pwlo, g_wlo);
    cudaGetSymbolAddress((void**)&pkthi, g_kthi);
    cudaGetSymbolAddress((void**)&pktlo, g_ktlo);
    cudaGetSymbolAddress((void**)&pvthi, g_vthi);
    cudaGetSymbolAddress((void**)&pvtlo, g_vtlo);
    cudaGetSymbolAddress((void**)&pkihi, g_kihi);
    cudaGetSymbolAddress((void**)&pkilo, g_kilo);
    cudaGetSymbolAddress((void**)&pvihi, g_vihi);
    cudaGetSymbolAddress((void**)&pvilo, g_vilo);

    cudaFuncSetAttribute(gemm_mma<0, 2>,
                         cudaFuncAttributeMaxDynamicSharedMemorySize, GM_SMEM);
    cudaFuncSetAttribute(gemm_mma<1, 3>,
                         cudaFuncAttributeMaxDynamicSharedMemorySize, GM_SMEM);
    cudaFuncSetAttribute(gemm_mma<2, 3>,
                         cudaFuncAttributeMaxDynamicSharedMemorySize, GM_SMEM);
    cudaFuncSetAttribute(attn_mma,
                         cudaFuncAttributeMaxDynamicSharedMemorySize, AT_SMEM);

    const size_t WSZ = (size_t)DM_ * DM_;
    size_t nx = (size_t)B_ * NQ_ * DM_;
    size_t nc = (size_t)B_ * CTXR * DM_;

    conv_wt<<<dim3(32, 32), dim3(32, 8)>>>(Wq, pwhi + 0 * WSZ, pwlo + 0 * WSZ);
    conv_rows<<<(unsigned)(nx / 4 / 256), 256>>>(x, pahi, palo, nx);
    conv_rows<<<(unsigned)((nc / 4 + 255) / 256), 256>>>(ctx, pchi, pclo, nc);
    conv_wt<<<dim3(32, 32), dim3(32, 8)>>>(Wk, pwhi + 1 * WSZ, pwlo + 1 * WSZ);
    conv_wt<<<dim3(32, 32), dim3(32, 8)>>>(Wv, pwhi + 2 * WSZ, pwlo + 2 * WSZ);

    // Q = (x @ Wq) * 0.125 -> fp16 hi/lo
    gemm_mma<2, 3><<<dim3(8, 512), 256, GM_SMEM>>>(
        pahi, palo, pwhi + 0 * WSZ, pwlo + 0 * WSZ, nullptr, nullptr,
        pqhi, pqlo, B_ * NQ_, B_ * NQ_, B_ * NQ_, 0);

    conv_wt<<<dim3(32, 32), dim3(32, 8)>>>(Wk_ip, pwhi + 3 * WSZ, pwlo + 3 * WSZ);
    conv_wt<<<dim3(32, 32), dim3(32, 8)>>>(Wv_ip, pwhi + 4 * WSZ, pwlo + 4 * WSZ);
    conv_wt<<<dim3(32, 32), dim3(32, 8)>>>(Wout,  pwhi + 5 * WSZ, pwlo + 5 * WSZ);

    // K/V text -> [b][h][t][d] fp16 hi/lo
    gemm_mma<1, 3><<<dim3(8, 39), 256, GM_SMEM>>>(
        pchi, pclo, pwhi + 1 * WSZ, pwlo + 1 * WSZ, nullptr, nullptr,
        pkthi, pktlo, B_ * LT_, LT_, CTXR, 0);
    gemm_mma<1, 3><<<dim3(8, 39), 256, GM_SMEM>>>(
        pchi, pclo, pwhi + 2 * WSZ, pwlo + 2 * WSZ, nullptr, nullptr,
        pvthi, pvtlo, B_ * LT_, LT_, CTXR, 0);

    // K/V image
    gemm_mma<1, 3><<<dim3(8, 128), 256, GM_SMEM>>>(
        pchi, pclo, pwhi + 3 * WSZ, pwlo + 3 * WSZ, nullptr, nullptr,
        pkihi, pkilo, B_ * LI_, LI_, CTXR, LT_);
    gemm_mma<1, 3><<<dim3(8, 128), 256, GM_SMEM>>>(
        pchi, pclo, pwhi + 4 * WSZ, pwlo + 4 * WSZ, nullptr, nullptr,
        pvihi, pvilo, B_ * LI_, LI_, CTXR, LT_);

    // tensor-core attention -> fp16 hi/lo into final-GEMM input buffers
    attn_mma<<<B_ * H_ * 8, 256, AT_SMEM>>>(
        pqhi, pqlo, pkthi, pktlo, pvthi, pvtlo,
        pkihi, pkilo, pvihi, pvilo, relk, relv, pahi, palo);

    // final projection + bias (2-term: Wout lo dropped)
    gemm_mma<0, 2><<<dim3(8, 512), 256, GM_SMEM>>>(
        pahi, palo, pwhi + 5 * WSZ, pwlo + 5 * WSZ, out, bout,
        nullptr, nullptr, B_ * NQ_, B_ * NQ_, B_ * NQ_, 0);
}

// round 8
// speedup vs baseline: 4.1561x; 1.2020x over previous
#include <cuda_runtime.h>
#include <cuda_fp16.h>
#include <cstdint>

// ---------------------------------------------------------------------------
// Problem constants
// ---------------------------------------------------------------------------
#define B_    64
#define NQ_   1024
#define DM_   1024
#define H_    16
#define D_    64
#define LT_   77
#define LI_   256
#define NR_   33
#define CTXR  (LT_ + LI_)     // 333

__device__ __forceinline__ uint32_t smem_to_u32(const void* p) {
    uint32_t a;
    asm("{ .reg .u64 t; cvta.to.shared.u64 t, %1; cvt.u32.u64 %0, t; }"
        : "=r"(a) : "l"(p));
    return a;
}

#define CPA16(dst, src) \
    asm volatile("cp.async.cg.shared.global [%0], [%1], 16;" \
                 :: "r"(dst), "l"(src))
#define CPA_COMMIT() asm volatile("cp.async.commit_group;" ::: "memory")
#define CPA_WAIT(n)  asm volatile("cp.async.wait_group %0;" :: "n"(n) : "memory")

#define LDMX4(r0, r1, r2, r3, addr) \
    asm volatile("ldmatrix.sync.aligned.m8n8.x4.shared.b16 {%0,%1,%2,%3}, [%4];" \
                 : "=r"(r0), "=r"(r1), "=r"(r2), "=r"(r3) : "r"(addr))
#define LDMX4T(r0, r1, r2, r3, addr) \
    asm volatile("ldmatrix.sync.aligned.m8n8.x4.trans.shared.b16 {%0,%1,%2,%3}, [%4];" \
                 : "=r"(r0), "=r"(r1), "=r"(r2), "=r"(r3) : "r"(addr))

#define MMA16816(c, a, b0, b1) \
    asm volatile("mma.sync.aligned.m16n8k16.row.col.f32.f16.f16.f32 " \
                 "{%0,%1,%2,%3}, {%4,%5,%6,%7}, {%8,%9}, {%0,%1,%2,%3};" \
                 : "+f"((c)[0]), "+f"((c)[1]), "+f"((c)[2]), "+f"((c)[3]) \
                 : "r"((a)[0]), "r"((a)[1]), "r"((a)[2]), "r"((a)[3]), \
                   "r"(b0), "r"(b1))

__device__ __forceinline__ uint32_t packh(float lo, float hi) {
    uint32_t d;
    asm("cvt.rn.f16x2.f32 %0, %1, %2;" : "=r"(d) : "f"(hi), "f"(lo));
    return d;
}

// ---------------------------------------------------------------------------
// Scratch (static device globals)
// ---------------------------------------------------------------------------
__device__ __half g_ahi[(size_t)B_ * NQ_ * DM_];  // x hi, later att hi
__device__ __half g_alo[(size_t)B_ * NQ_ * DM_];
__device__ __half g_qhi[(size_t)B_ * NQ_ * DM_];
__device__ __half g_qlo[(size_t)B_ * NQ_ * DM_];
__device__ __half g_chi[(size_t)B_ * CTXR * DM_];
__device__ __half g_clo[(size_t)B_ * CTXR * DM_];
__device__ __half g_whi[6 * (size_t)DM_ * DM_];
__device__ __half g_wlo[6 * (size_t)DM_ * DM_];
__device__ __half g_kthi[(size_t)B_ * H_ * LT_ * D_];
__device__ __half g_ktlo[(size_t)B_ * H_ * LT_ * D_];
__device__ __half g_vthi[(size_t)B_ * H_ * LT_ * D_];
__device__ __half g_vtlo[(size_t)B_ * H_ * LT_ * D_];
__device__ __half g_kihi[(size_t)B_ * H_ * LI_ * D_];
__device__ __half g_kilo[(size_t)B_ * H_ * LI_ * D_];
__device__ __half g_vihi[(size_t)B_ * H_ * LI_ * D_];
__device__ __half g_vilo[(size_t)B_ * H_ * LI_ * D_];

// ---------------------------------------------------------------------------
// fp32 -> fp16 hi/lo split
// ---------------------------------------------------------------------------
__global__ void conv_rows(const float* __restrict__ src,
                          __half* __restrict__ hi,
                          __half* __restrict__ lo, size_t n)
{
    size_t i = ((size_t)blockIdx.x * blockDim.x + threadIdx.x) * 4;
    if (i >= n) return;
    float4 v = *(const float4*)(src + i);
    float h0 = __half2float(__float2half(v.x));
    float h1 = __half2float(__float2half(v.y));
    float h2 = __half2float(__float2half(v.z));
    float h3 = __half2float(__float2half(v.w));
    *(uint2*)(hi + i) = make_uint2(packh(h0, h1), packh(h2, h3));
    *(uint2*)(lo + i) = make_uint2(packh(v.x - h0, v.y - h1),
                                   packh(v.z - h2, v.w - h3));
}

// W [K=1024, N=1024] -> Wt hi/lo [N, K]
__global__ void conv_wt(const float* __restrict__ W,
                        __half* __restrict__ hi,
                        __half* __restrict__ lo)
{
    __shared__ float tile[32][33];
    const int k0 = blockIdx.y * 32, n0 = blockIdx.x * 32;
    const int tx = threadIdx.x;
    for (int r = threadIdx.y; r < 32; r += 8)
        tile[r][tx] = W[(size_t)(k0 + r) * DM_ + n0 + tx];
    __syncthreads();
    for (int r = threadIdx.y; r < 32; r += 8) {
        float v = tile[tx][r];
        float h = __half2float(__float2half(v));
        size_t oi = (size_t)(n0 + r) * DM_ + k0 + tx;
        hi[oi] = __float2half(h);
        lo[oi] = __float2half(v - h);
    }
}

// ---------------------------------------------------------------------------
// fp16 split GEMM via mma.sync: C[M,1024] = remap(A)[M,1024] @ B^T (B is [N,K])
// MODE 0: fp32 C + bias.  MODE 1: KV scatter fp16 hi/lo.  MODE 2: Q *0.125.
// TERMS 3: AhiBhi + AloBhi + AhiBlo.  TERMS 2: AhiBhi + AloBhi (Blo not loaded).
// CTA 128x128, BK=32, 2-stage cp.async pipeline, 2 CTAs/SM.
// ---------------------------------------------------------------------------
#define BUF_BYTES   40960
#define GM_SMEM     (2 * BUF_BYTES)

template <int MODE, int TERMS>
__global__ void __launch_bounds__(256, 2)
gemm_mma(const __half* __restrict__ Ahi, const __half* __restrict__ Alo,
         const __half* __restrict__ Bhi, const __half* __restrict__ Blo,
         float* __restrict__ C, const float* __restrict__ bias,
         __half* __restrict__ Chi, __half* __restrict__ Clo,
         int M, int rows_per_seg, int seg_stride, int seg_base)
{
    extern __shared__ __align__(128) char smem[];
    const uint32_t sb = smem_to_u32(smem);
    const int tid = threadIdx.x;
    const int bn = blockIdx.x * 128;
    const int bm = blockIdx.y * 128;
    const int wid = tid >> 5, lane = tid & 31;
    const int Wm = (wid & 3) * 32;
    const int Wn = (wid >> 2) * 64;

    const int lrow = tid >> 1;
    const int lc = tid & 1;
    int m = bm + lrow; if (m > M - 1) m = M - 1;
    const int seg = m / rows_per_seg;
    const int t = m - seg * rows_per_seg;
    const size_t aoff = (size_t)(seg * seg_stride + seg_base + t) * 1024 + lc * 16;
    const size_t boff = (size_t)(bn + lrow) * 1024 + lc * 16;
    const uint32_t soff = (uint32_t)lrow * 80u + (uint32_t)lc * 32u;

    float acc[2][8][4];
#pragma unroll
    for (int i = 0; i < 2; i++)
#pragma unroll
        for (int j = 0; j < 8; j++)
#pragma unroll
            for (int c = 0; c < 4; c++) acc[i][j][c] = 0.f;

    const uint32_t a_frag_row = (uint32_t)(Wm + (lane & 15)) * 80u + ((lane >> 4) * 16u);
    const uint32_t b_frag_row =
        (uint32_t)(Wn + (lane & 7) + ((lane >> 4) << 3)) * 80u + (((lane >> 3) & 1) * 16u);

#define ISSUE(p, k0)                                                       \
    {                                                                      \
        uint32_t d = sb + (p) * BUF_BYTES + soff;                          \
        const __half* s;                                                   \
        s = Ahi + aoff + (k0); CPA16(d,           s); CPA16(d + 16,         s + 8); \
        s = Alo + aoff + (k0); CPA16(d + 10240,   s); CPA16(d + 10240 + 16, s + 8); \
        s = Bhi + boff + (k0); CPA16(d + 20480,   s); CPA16(d + 20480 + 16, s + 8); \
        if (TERMS == 3) {                                                  \
            s = Blo + boff + (k0); CPA16(d + 30720, s); CPA16(d + 30720 + 16, s + 8); \
        }                                                                  \
    }

    ISSUE(0, 0);
    CPA_COMMIT();

    for (int i = 0; i < 32; i++) {
        if (i + 1 < 32) {
            ISSUE((i + 1) & 1, (i + 1) * 32);
            CPA_COMMIT();
            CPA_WAIT(1);
        } else {
            CPA_WAIT(0);
        }
        __syncthreads();

        const uint32_t base = sb + (i & 1) * BUF_BYTES;
#pragma unroll
        for (int kk = 0; kk < 2; kk++) {
            uint32_t ah[2][4], al[2][4];
            const uint32_t ar = base + a_frag_row + kk * 32;
            LDMX4(ah[0][0], ah[0][1], ah[0][2], ah[0][3], ar);
            LDMX4(ah[1][0], ah[1][1], ah[1][2], ah[1][3], ar + 16 * 80);
            LDMX4(al[0][0], al[0][1], al[0][2], al[0][3], ar + 10240);
            LDMX4(al[1][0], al[1][1], al[1][2], al[1][3], ar + 10240 + 16 * 80);
#pragma unroll
            for (int j = 0; j < 4; j++) {
                uint32_t bh0, bh1, bh2, bh3;
                const uint32_t br = base + b_frag_row + kk * 32 + (uint32_t)j * (16 * 80);
                LDMX4(bh0, bh1, bh2, bh3, br + 20480);
                uint32_t bl0 = 0, bl1 = 0, bl2 = 0, bl3 = 0;
                if (TERMS == 3) { LDMX4(bl0, bl1, bl2, bl3, br + 30720); }
#pragma unroll
                for (int mt = 0; mt < 2; mt++) {
                    MMA16816(acc[mt][2 * j],     ah[mt], bh0, bh1);
                    MMA16816(acc[mt][2 * j],     al[mt], bh0, bh1);
                    MMA16816(acc[mt][2 * j + 1], ah[mt], bh2, bh3);
                    MMA16816(acc[mt][2 * j + 1], al[mt], bh2, bh3);
                    if (TERMS == 3) {
                        MMA16816(acc[mt][2 * j],     ah[mt], bl0, bl1);
                        MMA16816(acc[mt][2 * j + 1], ah[mt], bl2, bl3);
                    }
                }
            }
        }
        __syncthreads();
    }
#undef ISSUE

    const int er = lane >> 2, ec = (lane & 3) * 2;
#pragma unroll
    for (int mt = 0; mt < 2; mt++) {
#pragma unroll
        for (int hrow = 0; hrow < 2; hrow++) {
            const int cm = bm + Wm + mt * 16 + er + hrow * 8;
            if (cm >= M) continue;
            if (MODE == 1) {
                const int segc = cm / rows_per_seg;
                const int tc = cm - segc * rows_per_seg;
#pragma unroll
                for (int nt = 0; nt < 8; nt++) {
                    const int cn = bn + Wn + nt * 8 + ec;
                    const int hh = cn >> 6, dd = cn & 63;
                    size_t oi = (((size_t)segc * H_ + hh) * rows_per_seg + tc) * 64 + dd;
                    float v0 = acc[mt][nt][hrow * 2], v1 = acc[mt][nt][hrow * 2 + 1];
                    float h0 = __half2float(__float2half(v0));
                    float h1 = __half2float(__float2half(v1));
                    *(uint32_t*)(Chi + oi) = packh(h0, h1);
                    *(uint32_t*)(Clo + oi) = packh(v0 - h0, v1 - h1);
                }
            } else if (MODE == 2) {
#pragma unroll
                for (int nt = 0; nt < 8; nt++) {
                    const int cn = bn + Wn + nt * 8 + ec;
                    size_t oi = (size_t)cm * DM_ + cn;
                    float v0 = acc[mt][nt][hrow * 2] * 0.125f;
                    float v1 = acc[mt][nt][hrow * 2 + 1] * 0.125f;
                    float h0 = __half2float(__float2half(v0));
                    float h1 = __half2float(__float2half(v1));
                    *(uint32_t*)(Chi + oi) = packh(h0, h1);
                    *(uint32_t*)(Clo + oi) = packh(v0 - h0, v1 - h1);
                }
            } else {
                float* Cp = C + (size_t)cm * DM_ + bn + Wn + ec;
                const float* bp = bias + bn + Wn + ec;
#pragma unroll
                for (int nt = 0; nt < 8; nt++) {
                    float2 v = make_float2(acc[mt][nt][hrow * 2] + bp[nt * 8],
                                           acc[mt][nt][hrow * 2 + 1] + bp[nt * 8 + 1]);
                    *(float2*)(Cp + nt * 8) = v;
                }
            }
        }
    }
}

// ---------------------------------------------------------------------------
// Tensor-core flash attention (fp16 hi/lo). One CTA = (b, h, 128-query tile).
// ---------------------------------------------------------------------------
#define AT_KHI 0
#define AT_KLO 48384
#define AT_VHI 96768
#define AT_VLO 145152
#define AT_QHI 193536
#define AT_QLO 211968
#define AT_PS  193536
#define AT_RKH 211968
#define AT_RKL 217728
#define AT_SMEM 230400

__device__ __forceinline__ int bidx(int j, int i)
{
    int d = j - i;
    d = max(-16, min(16, d));
    return d + 16;
}

__device__ __forceinline__ void wsplit(const float* s0, const float* s1,
                                       uint32_t* ahi, uint32_t* alo)
{
    float v[8] = {s0[0], s0[1], s0[2], s0[3], s1[0], s1[1], s1[2], s1[3]};
    float hv[8];
#pragma unroll
    for (int i = 0; i < 8; i++)
        hv[i] = __half2float(__float2half(v[i]));
    ahi[0] = packh(hv[0], hv[1]); ahi[1] = packh(hv[2], hv[3]);
    ahi[2] = packh(hv[4], hv[5]); ahi[3] = packh(hv[6], hv[7]);
    alo[0] = packh(v[0] - hv[0], v[1] - hv[1]);
    alo[1] = packh(v[2] - hv[2], v[3] - hv[3]);
    alo[2] = packh(v[4] - hv[4], v[5] - hv[5]);
    alo[3] = packh(v[6] - hv[6], v[7] - hv[7]);
}

__global__ void __launch_bounds__(256, 1)
attn_mma(const __half* __restrict__ qhi, const __half* __restrict__ qlo,
         const __half* __restrict__ kthi, const __half* __restrict__ ktlo,
         const __half* __restrict__ vthi, const __half* __restrict__ vtlo,
         const __half* __restrict__ kihi, const __half* __restrict__ kilo,
         const __half* __restrict__ vihi, const __half* __restrict__ vilo,
         const float* __restrict__ relk, const float* __restrict__ relv,
         __half* __restrict__ atthi, __half* __restrict__ attlo)
{
    extern __shared__ __align__(128) char sm[];
    const uint32_t sb = smem_to_u32(sm);
    const int tid = threadIdx.x, w = tid >> 5, lane = tid & 31;
    const int bh = blockIdx.x >> 3, qt = blockIdx.x & 7;
    const int b = bh >> 4, h = bh & 15;
    const int i0 = qt * 128;
    const unsigned FULL = 0xffffffffu;

    // ---- stage K/V/Q ----
    {
        size_t tb = (size_t)bh * (LT_ * 64);
        for (int idx = tid; idx < LT_ * 8; idx += 256) {
            int r = idx >> 3, c = idx & 7;
            uint32_t d = (uint32_t)r * 144 + c * 16;
            size_t s = tb + (size_t)r * 64 + c * 8;
            CPA16(sb + AT_KHI + d, kthi + s);
            CPA16(sb + AT_KLO + d, ktlo + s);
            CPA16(sb + AT_VHI + d, vthi + s);
            CPA16(sb + AT_VLO + d, vtlo + s);
        }
        size_t ib = (size_t)bh * (LI_ * 64);
        for (int idx = tid; idx < LI_ * 8; idx += 256) {
            int r = idx >> 3, c = idx & 7;
            uint32_t d = (uint32_t)(80 + r) * 144 + c * 16;
            size_t s = ib + (size_t)r * 64 + c * 8;
            CPA16(sb + AT_KHI + d, kihi + s);
            CPA16(sb + AT_KLO + d, kilo + s);
            CPA16(sb + AT_VHI + d, vihi + s);
            CPA16(sb + AT_VLO + d, vilo + s);
        }
        size_t qb = ((size_t)(b * NQ_ + i0)) * 1024 + h * 64;
        for (int idx = tid; idx < 128 * 8; idx += 256) {
            int r = idx >> 3, c = idx & 7;
            uint32_t d = (uint32_t)r * 144 + c * 16;
            size_t s = qb + (size_t)r * 1024 + c * 8;
            CPA16(sb + AT_QHI + d, qhi + s);
            CPA16(sb + AT_QLO + d, qlo + s);
        }
        for (int idx = tid; idx < 3 * 36; idx += 256) {
            uint32_t d = (uint32_t)(77 + idx / 36) * 144 + (idx % 36) * 4;
            *(uint32_t*)(sm + AT_KHI + d) = 0;
            *(uint32_t*)(sm + AT_KLO + d) = 0;
            *(uint32_t*)(sm + AT_VHI + d) = 0;
            *(uint32_t*)(sm + AT_VLO + d) = 0;
        }
        CPA_COMMIT();
        CPA_WAIT(0);
        __syncthreads();
    }

    const int wr = w * 16;
    const int r0l = wr + (lane >> 2);

    // ---- Q fragments ----
    uint32_t qh[4][4], ql[4][4];
    {
        int row = wr + (lane & 15);
        int kb = (lane >> 4) * 16;
#pragma unroll
        for (int kk = 0; kk < 4; kk++) {
            uint32_t a = sb + AT_QHI + (uint32_t)row * 144 + kk * 32 + kb;
            LDMX4(qh[kk][0], qh[kk][1], qh[kk][2], qh[kk][3], a);
            LDMX4(ql[kk][0], ql[kk][1], ql[kk][2], ql[kk][3], a + (AT_QLO - AT_QHI));
        }
    }
    __syncthreads();

    if (qt == 0) {
        for (int idx = tid; idx < NR_ * 64; idx += 256) {
            int r = idx >> 6, dc = idx & 63;
            float v = relk[idx];
            float hh = __half2float(__float2half(v));
            *(__half*)(sm + AT_RKH + r * 144 + dc * 2) = __float2half(hh);
            *(__half*)(sm + AT_RKL + r * 144 + dc * 2) = __float2half(v - hh);
        }
    }
    __syncthreads();

    float* pS = (float*)(sm + AT_PS);

    const int brow = ((lane >> 4) << 3) + (lane & 7);
    const int bdb = (lane & 8) * 2;

    // ---- rel-K projections (tile 0) ----
    if (qt == 0) {
        float pr[5][4];
#pragma unroll
        for (int i = 0; i < 5; i++)
#pragma unroll
            for (int c = 0; c < 4; c++) pr[i][c] = 0.f;
#pragma unroll
        for (int kk = 0; kk < 4; kk++) {
#pragma unroll
            for (int p2 = 0; p2 < 3; p2++) {
                uint32_t bh4[4], bl4[4];
                uint32_t ad = sb + AT_RKH + (uint32_t)(p2 * 16 + brow) * 144
                              + kk * 32 + bdb;
                LDMX4(bh4[0], bh4[1], bh4[2], bh4[3], ad);
                LDMX4(bl4[0], bl4[1], bl4[2], bl4[3], ad + (AT_RKL - AT_RKH));
                MMA16816(pr[2 * p2], qh[kk], bh4[0], bh4[1]);
                MMA16816(pr[2 * p2], ql[kk], bh4[0], bh4[1]);
                MMA16816(pr[2 * p2], qh[kk], bl4[0], bl4[1]);
                if (p2 < 2) {
                    MMA16816(pr[2 * p2 + 1], qh[kk], bh4[2], bh4[3]);
                    MMA16816(pr[2 * p2 + 1], ql[kk], bh4[2], bh4[3]);
                    MMA16816(pr[2 * p2 + 1], qh[kk], bl4[2], bl4[3]);
                }
            }
        }
#pragma unroll
        for (int nt = 0; nt < 5; nt++) {
            int c0 = nt * 8 + 2 * (lane & 3);
            if (c0 < NR_) {
                pS[r0l * 34 + c0] = pr[nt][0];
                pS[(r0l + 8) * 34 + c0] = pr[nt][2];
            }
            if (c0 + 1 < NR_) {
                pS[r0l * 34 + c0 + 1] = pr[nt][1];
                pS[(r0l + 8) * 34 + c0 + 1] = pr[nt][3];
            }
        }
        __syncwarp();
    }

    // ---- text scores ----
    float s[10][4];
#pragma unroll
    for (int i = 0; i < 10; i++)
#pragma unroll
        for (int c = 0; c < 4; c++) s[i][c] = 0.f;
#pragma unroll
    for (int kk = 0; kk < 4; kk++) {
#pragma unroll
        for (int p2 = 0; p2 < 5; p2++) {
            uint32_t kh4[4], kl4[4];
            uint32_t ad = sb + AT_KHI + (uint32_t)(p2 * 16 + brow) * 144
                          + kk * 32 + bdb;
            LDMX4(kh4[0], kh4[1], kh4[2], kh4[3], ad);
            LDMX4(kl4[0], kl4[1], kl4[2], kl4[3], ad + (AT_KLO - AT_KHI));
            MMA16816(s[2 * p2], qh[kk], kh4[0], kh4[1]);
            MMA16816(s[2 * p2], ql[kk], kh4[0], kh4[1]);
            MMA16816(s[2 * p2], qh[kk], kl4[0], kl4[1]);
            MMA16816(s[2 * p2 + 1], qh[kk], kh4[2], kh4[3]);
            MMA16816(s[2 * p2 + 1], ql[kk], kh4[2], kh4[3]);
            MMA16816(s[2 * p2 + 1], qh[kk], kl4[2], kl4[3]);
        }
    }

#pragma unroll
    for (int nt = 0; nt < 10; nt++) {
        int c0 = nt * 8 + 2 * (lane & 3);
        if (qt == 0) {
            s[nt][0] += pS[r0l * 34 + bidx(c0, r0l)];
            s[nt][1] += pS[r0l * 34 + bidx(c0 + 1, r0l)];
            s[nt][2] += pS[(r0l + 8) * 34 + bidx(c0, r0l + 8)];
            s[nt][3] += pS[(r0l + 8) * 34 + bidx(c0 + 1, r0l + 8)];
        }
        if (c0 >= LT_) { s[nt][0] = -1e30f; s[nt][2] = -1e30f; }
        if (c0 + 1 >= LT_) { s[nt][1] = -1e30f; s[nt][3] = -1e30f; }
    }

    float m0 = -1e30f, m1 = -1e30f;
#pragma unroll
    for (int nt = 0; nt < 10; nt++) {
        m0 = fmaxf(m0, fmaxf(s[nt][0], s[nt][1]));
        m1 = fmaxf(m1, fmaxf(s[nt][2], s[nt][3]));
    }
    m0 = fmaxf(m0, __shfl_xor_sync(FULL, m0, 1));
    m0 = fmaxf(m0, __shfl_xor_sync(FULL, m0, 2));
    m1 = fmaxf(m1, __shfl_xor_sync(FULL, m1, 1));
    m1 = fmaxf(m1, __shfl_xor_sync(FULL, m1, 2));
    float l0 = 0.f, l1 = 0.f;
#pragma unroll
    for (int nt = 0; nt < 10; nt++) {
        s[nt][0] = __expf(s[nt][0] - m0); l0 += s[nt][0];
        s[nt][1] = __expf(s[nt][1] - m0); l0 += s[nt][1];
        s[nt][2] = __expf(s[nt][2] - m1); l1 += s[nt][2];
        s[nt][3] = __expf(s[nt][3] - m1); l1 += s[nt][3];
    }
    l0 += __shfl_xor_sync(FULL, l0, 1); l0 += __shfl_xor_sync(FULL, l0, 2);
    l1 += __shfl_xor_sync(FULL, l1, 1); l1 += __shfl_xor_sync(FULL, l1, 2);
    float inv0 = 1.f / l0, inv1 = 1.f / l1;
#pragma unroll
    for (int nt = 0; nt < 10; nt++) {
        s[nt][0] *= inv0; s[nt][1] *= inv0;
        s[nt][2] *= inv1; s[nt][3] *= inv1;
    }

    if (qt == 0) {
        for (int idx = lane; idx < 16 * 34; idx += 32)
            pS[(wr + idx / 34) * 34 + idx % 34] = 0.f;
        __syncwarp();
#pragma unroll
        for (int nt = 0; nt < 10; nt++) {
            int c0 = nt * 8 + 2 * (lane & 3);
            if (c0 < LT_) {
                atomicAdd(&pS[r0l * 34 + bidx(c0, r0l)], s[nt][0]);
                atomicAdd(&pS[(r0l + 8) * 34 + bidx(c0, r0l + 8)], s[nt][2]);
            }
            if (c0 + 1 < LT_) {
                atomicAdd(&pS[r0l * 34 + bidx(c0 + 1, r0l)], s[nt][1]);
                atomicAdd(&pS[(r0l + 8) * 34 + bidx(c0 + 1, r0l + 8)], s[nt][3]);
            }
        }
        __syncwarp();
    }

    const int vrow = (lane & 8) + (lane & 7);
    const int vdb = (lane >> 4) * 16;

    float ot[8][4];
#pragma unroll
    for (int i = 0; i < 8; i++)
#pragma unroll
        for (int c = 0; c < 4; c++) ot[i][c] = 0.f;
#pragma unroll
    for (int wk = 0; wk < 5; wk++) {
        uint32_t ahi[4], alo[4];
        wsplit(s[2 * wk], s[2 * wk + 1], ahi, alo);
#pragma unroll
        for (int dp = 0; dp < 4; dp++) {
            uint32_t vh4[4], vl4[4];
            uint32_t ad = sb + AT_VHI + (uint32_t)(wk * 16 + vrow) * 144
                          + dp * 32 + vdb;
            LDMX4T(vh4[0], vh4[1], vh4[2], vh4[3], ad);
            LDMX4T(vl4[0], vl4[1], vl4[2], vl4[3], ad + (AT_VLO - AT_VHI));
            MMA16816(ot[2 * dp], ahi, vh4[0], vh4[1]);
            MMA16816(ot[2 * dp], alo, vh4[0], vh4[1]);
            MMA16816(ot[2 * dp], ahi, vl4[0], vl4[1]);
            MMA16816(ot[2 * dp + 1], ahi, vh4[2], vh4[3]);
            MMA16816(ot[2 * dp + 1], alo, vh4[2], vh4[3]);
            MMA16816(ot[2 * dp + 1], ahi, vl4[2], vl4[3]);
        }
    }

    if (qt == 0) {
#pragma unroll 1
        for (int r = 0; r < NR_; r++) {
            float w0 = pS[r0l * 34 + r];
            float w1 = pS[(r0l + 8) * 34 + r];
            const float* rv = relv + r * 64 + 2 * (lane & 3);
#pragma unroll
            for (int dt = 0; dt < 8; dt++) {
                float rv0 = rv[dt * 8], rv1 = rv[dt * 8 + 1];
                ot[dt][0] += w0 * rv0; ot[dt][1] += w0 * rv1;
                ot[dt][2] += w1 * rv0; ot[dt][3] += w1 * rv1;
            }
        }
    } else {
        const float* rv = relv + 2 * (lane & 3);
#pragma unroll
        for (int dt = 0; dt < 8; dt++) {
            float rv0 = rv[dt * 8], rv1 = rv[dt * 8 + 1];
            ot[dt][0] += rv0; ot[dt][1] += rv1;
            ot[dt][2] += rv0; ot[dt][3] += rv1;
        }
    }

    float oi[8][4];
#pragma unroll
    for (int i = 0; i < 8; i++)
#pragma unroll
        for (int c = 0; c < 4; c++) oi[i][c] = 0.f;
    float mi0 = -1e30f, mi1 = -1e30f, li0 = 0.f, li1 = 0.f;
#pragma unroll 1
    for (int ch = 0; ch < 8; ch++) {
        const int j0 = 80 + ch * 32;
        float sc[4][4];
#pragma unroll
        for (int i = 0; i < 4; i++)
#pragma unroll
            for (int c = 0; c < 4; c++) sc[i][c] = 0.f;
#pragma unroll
        for (int kk = 0; kk < 4; kk++) {
#pragma unroll
            for (int p2 = 0; p2 < 2; p2++) {
                uint32_t kh4[4], kl4[4];
                uint32_t ad = sb + AT_KHI + (uint32_t)(j0 + p2 * 16 + brow) * 144
                              + kk * 32 + bdb;
                LDMX4(kh4[0], kh4[1], kh4[2], kh4[3], ad);
                LDMX4(kl4[0], kl4[1], kl4[2], kl4[3], ad + (AT_KLO - AT_KHI));
                MMA16816(sc[2 * p2], qh[kk], kh4[0], kh4[1]);
                MMA16816(sc[2 * p2], ql[kk], kh4[0], kh4[1]);
                MMA16816(sc[2 * p2], qh[kk], kl4[0], kl4[1]);
                MMA16816(sc[2 * p2 + 1], qh[kk], kh4[2], kh4[3]);
                MMA16816(sc[2 * p2 + 1], ql[kk], kh4[2], kh4[3]);
                MMA16816(sc[2 * p2 + 1], qh[kk], kl4[2], kl4[3]);
            }
        }
        float cm0 = -1e30f, cm1 = -1e30f;
#pragma unroll
        for (int t = 0; t < 4; t++) {
            cm0 = fmaxf(cm0, fmaxf(sc[t][0], sc[t][1]));
            cm1 = fmaxf(cm1, fmaxf(sc[t][2], sc[t][3]));
        }
        cm0 = fmaxf(cm0, __shfl_xor_sync(FULL, cm0, 1));
        cm0 = fmaxf(cm0, __shfl_xor_sync(FULL, cm0, 2));
        cm1 = fmaxf(cm1, __shfl_xor_sync(FULL, cm1, 1));
        cm1 = fmaxf(cm1, __shfl_xor_sync(FULL, cm1, 2));
        float mn0 = fmaxf(mi0, cm0), mn1 = fmaxf(mi1, cm1);
        float al0 = __expf(mi0 - mn0), al1 = __expf(mi1 - mn1);
        float cs0 = 0.f, cs1 = 0.f;
#pragma unroll
        for (int t = 0; t < 4; t++) {
            sc[t][0] = __expf(sc[t][0] - mn0); cs0 += sc[t][0];
            sc[t][1] = __expf(sc[t][1] - mn0); cs0 += sc[t][1];
            sc[t][2] = __expf(sc[t][2] - mn1); cs1 += sc[t][2];
            sc[t][3] = __expf(sc[t][3] - mn1); cs1 += sc[t][3];
        }
        cs0 += __shfl_xor_sync(FULL, cs0, 1); cs0 += __shfl_xor_sync(FULL, cs0, 2);
        cs1 += __shfl_xor_sync(FULL, cs1, 1); cs1 += __shfl_xor_sync(FULL, cs1, 2);
        li0 = li0 * al0 + cs0; li1 = li1 * al1 + cs1;
        mi0 = mn0; mi1 = mn1;
#pragma unroll
        for (int dt = 0; dt < 8; dt++) {
            oi[dt][0] *= al0; oi[dt][1] *= al0;
            oi[dt][2] *= al1; oi[dt][3] *= al1;
        }
#pragma unroll
        for (int wk = 0; wk < 2; wk++) {
            uint32_t ahi[4], alo[4];
            wsplit(sc[2 * wk], sc[2 * wk + 1], ahi, alo);
#pragma unroll
            for (int dp = 0; dp < 4; dp++) {
                uint32_t vh4[4], vl4[4];
                uint32_t ad = sb + AT_VHI + (uint32_t)(j0 + wk * 16 + vrow) * 144
                              + dp * 32 + vdb;
                LDMX4T(vh4[0], vh4[1], vh4[2], vh4[3], ad);
                LDMX4T(vl4[0], vl4[1], vl4[2], vl4[3], ad + (AT_VLO - AT_VHI));
                MMA16816(oi[2 * dp], ahi, vh4[0], vh4[1]);
                MMA16816(oi[2 * dp], alo, vh4[0], vh4[1]);
                MMA16816(oi[2 * dp], ahi, vl4[0], vl4[1]);
                MMA16816(oi[2 * dp + 1], ahi, vh4[2], vh4[3]);
                MMA16816(oi[2 * dp + 1], alo, vh4[2], vh4[3]);
                MMA16816(oi[2 * dp + 1], ahi, vl4[2], vl4[3]);
            }
        }
    }
    float ii0 = 1.f / li0, ii1 = 1.f / li1;

    {
        size_t ob = ((size_t)(b * NQ_ + i0 + r0l)) * 1024 + h * 64 + 2 * (lane & 3);
#pragma unroll
        for (int dt = 0; dt < 8; dt++) {
            float v0 = ot[dt][0] + oi[dt][0] * ii0;
            float v1 = ot[dt][1] + oi[dt][1] * ii0;
            float v2 = ot[dt][2] + oi[dt][2] * ii1;
            float v3 = ot[dt][3] + oi[dt][3] * ii1;
            float h0 = __half2float(__float2half(v0));
            float h1 = __half2float(__float2half(v1));
            float h2 = __half2float(__float2half(v2));
            float h3 = __half2float(__float2half(v3));
            size_t o0 = ob + dt * 8;
            size_t o1 = o0 + 8 * 1024;
            *(uint32_t*)(atthi + o0) = packh(h0, h1);
            *(uint32_t*)(attlo + o0) = packh(v0 - h0, v1 - h1);
            *(uint32_t*)(atthi + o1) = packh(h2, h3);
            *(uint32_t*)(attlo + o1) = packh(v2 - h2, v3 - h3);
        }
    }
}

// ---------------------------------------------------------------------------
// Host launcher
// ---------------------------------------------------------------------------
extern "C" void kernel_launch(void* const* d_in, const int* in_sizes, int n_in,
                              void* d_out, int out_size)
{
    const float* x     = (const float*)d_in[0];
    const float* ctx   = (const float*)d_in[1];
    const float* Wq    = (const float*)d_in[2];
    const float* Wk    = (const float*)d_in[3];
    const float* Wv    = (const float*)d_in[4];
    const float* Wk_ip = (const float*)d_in[5];
    const float* Wv_ip = (const float*)d_in[6];
    const float* Wout  = (const float*)d_in[7];
    const float* bout  = (const float*)d_in[8];
    const float* relk  = (const float*)d_in[9];
    const float* relv  = (const float*)d_in[10];
    float* out = (float*)d_out;

    __half *pahi, *palo, *pqhi, *pqlo, *pchi, *pclo, *pwhi, *pwlo;
    __half *pkthi, *pktlo, *pvthi, *pvtlo, *pkihi, *pkilo, *pvihi, *pvilo;
    cudaGetSymbolAddress((void**)&pahi, g_ahi);
    cudaGetSymbolAddress((void**)&palo, g_alo);
    cudaGetSymbolAddress((void**)&pqhi, g_qhi);
    cudaGetSymbolAddress((void**)&pqlo, g_qlo);
    cudaGetSymbolAddress((void**)&pchi, g_chi);
    cudaGetSymbolAddress((void**)&pclo, g_clo);
    cudaGetSymbolAddress((void**)&pwhi, g_whi);
    cudaGetSymbolAddress((void**)&pwlo, g_wlo);
    cudaGetSymbolAddress((void**)&pkthi, g_kthi);
    cudaGetSymbolAddress((void**)&pktlo, g_ktlo);
    cudaGetSymbolAddress((void**)&pvthi, g_vthi);
    cudaGetSymbolAddress((void**)&pvtlo, g_vtlo);
    cudaGetSymbolAddress((void**)&pkihi, g_kihi);
    cudaGetSymbolAddress((void**)&pkilo, g_kilo);
    cudaGetSymbolAddress((void**)&pvihi, g_vihi);
    cudaGetSymbolAddress((void**)&pvilo, g_vilo);

    cudaFuncSetAttribute(gemm_mma<0, 2>,
                         cudaFuncAttributeMaxDynamicSharedMemorySize, GM_SMEM);
    cudaFuncSetAttribute(gemm_mma<1, 2>,
                         cudaFuncAttributeMaxDynamicSharedMemorySize, GM_SMEM);
    cudaFuncSetAttribute(gemm_mma<2, 2>,
                         cudaFuncAttributeMaxDynamicSharedMemorySize, GM_SMEM);
    cudaFuncSetAttribute(attn_mma,
                         cudaFuncAttributeMaxDynamicSharedMemorySize, AT_SMEM);

    const size_t WSZ = (size_t)DM_ * DM_;
    size_t nx = (size_t)B_ * NQ_ * DM_;
    size_t nc = (size_t)B_ * CTXR * DM_;

    conv_wt<<<dim3(32, 32), dim3(32, 8)>>>(Wq, pwhi + 0 * WSZ, pwlo + 0 * WSZ);
    conv_rows<<<(unsigned)(nx / 4 / 256), 256>>>(x, pahi, palo, nx);
    conv_rows<<<(unsigned)((nc / 4 + 255) / 256), 256>>>(ctx, pchi, pclo, nc);
    conv_wt<<<dim3(32, 32), dim3(32, 8)>>>(Wk, pwhi + 1 * WSZ, pwlo + 1 * WSZ);
    conv_wt<<<dim3(32, 32), dim3(32, 8)>>>(Wv, pwhi + 2 * WSZ, pwlo + 2 * WSZ);

    // Q = (x @ Wq) * 0.125 -> fp16 hi/lo  (2-term)
    gemm_mma<2, 2><<<dim3(8, 512), 256, GM_SMEM>>>(
        pahi, palo, pwhi + 0 * WSZ, pwlo + 0 * WSZ, nullptr, nullptr,
        pqhi, pqlo, B_ * NQ_, B_ * NQ_, B_ * NQ_, 0);

    conv_wt<<<dim3(32, 32), dim3(32, 8)>>>(Wk_ip, pwhi + 3 * WSZ, pwlo + 3 * WSZ);
    conv_wt<<<dim3(32, 32), dim3(32, 8)>>>(Wv_ip, pwhi + 4 * WSZ, pwlo + 4 * WSZ);
    conv_wt<<<dim3(32, 32), dim3(32, 8)>>>(Wout,  pwhi + 5 * WSZ, pwlo + 5 * WSZ);

    // K/V text -> [b][h][t][d] fp16 hi/lo  (2-term)
    gemm_mma<1, 2><<<dim3(8, 39), 256, GM_SMEM>>>(
        pchi, pclo, pwhi + 1 * WSZ, pwlo + 1 * WSZ, nullptr, nullptr,
        pkthi, pktlo, B_ * LT_, LT_, CTXR, 0);
    gemm_mma<1, 2><<<dim3(8, 39), 256, GM_SMEM>>>(
        pchi, pclo, pwhi + 2 * WSZ, pwlo + 2 * WSZ, nullptr, nullptr,
        pvthi, pvtlo, B_ * LT_, LT_, CTXR, 0);

    // K/V image  (2-term)
    gemm_mma<1, 2><<<dim3(8, 128), 256, GM_SMEM>>>(
        pchi, pclo, pwhi + 3 * WSZ, pwlo + 3 * WSZ, nullptr, nullptr,
        pkihi, pkilo, B_ * LI_, LI_, CTXR, LT_);
    gemm_mma<1, 2><<<dim3(8, 128), 256, GM_SMEM>>>(
        pchi, pclo, pwhi + 4 * WSZ, pwlo + 4 * WSZ, nullptr, nullptr,
        pvihi, pvilo, B_ * LI_, LI_, CTXR, LT_);

    // tensor-core attention -> fp16 hi/lo into final-GEMM input buffers
    attn_mma<<<B_ * H_ * 8, 256, AT_SMEM>>>(
        pqhi, pqlo, pkthi, pktlo, pvthi, pvtlo,
        pkihi, pkilo, pvihi, pvilo, relk, relv, pahi, palo);

    // final projection + bias  (2-term)
    gemm_mma<0, 2><<<dim3(8, 512), 256, GM_SMEM>>>(
        pahi, palo, pwhi + 5 * WSZ, pwlo + 5 * WSZ, out, bout,
        nullptr, nullptr, B_ * NQ_, B_ * NQ_, B_ * NQ_, 0);
}

// round 9
// speedup vs baseline: 4.1961x; 1.0096x over previous
#include <cuda_runtime.h>
#include <cuda_fp16.h>
#include <cstdint>

// ---------------------------------------------------------------------------
// Problem constants
// ---------------------------------------------------------------------------
#define B_    64
#define NQ_   1024
#define DM_   1024
#define H_    16
#define D_    64
#define LT_   77
#define LI_   256
#define NR_   33
#define CTXR  (LT_ + LI_)     // 333

__device__ __forceinline__ uint32_t smem_to_u32(const void* p) {
    uint32_t a;
    asm("{ .reg .u64 t; cvta.to.shared.u64 t, %1; cvt.u32.u64 %0, t; }"
        : "=r"(a) : "l"(p));
    return a;
}

#define CPA16(dst, src) \
    asm volatile("cp.async.cg.shared.global [%0], [%1], 16;" \
                 :: "r"(dst), "l"(src))
#define CPA_COMMIT() asm volatile("cp.async.commit_group;" ::: "memory")
#define CPA_WAIT(n)  asm volatile("cp.async.wait_group %0;" :: "n"(n) : "memory")

#define LDMX4(r0, r1, r2, r3, addr) \
    asm volatile("ldmatrix.sync.aligned.m8n8.x4.shared.b16 {%0,%1,%2,%3}, [%4];" \
                 : "=r"(r0), "=r"(r1), "=r"(r2), "=r"(r3) : "r"(addr))
#define LDMX4T(r0, r1, r2, r3, addr) \
    asm volatile("ldmatrix.sync.aligned.m8n8.x4.trans.shared.b16 {%0,%1,%2,%3}, [%4];" \
                 : "=r"(r0), "=r"(r1), "=r"(r2), "=r"(r3) : "r"(addr))

#define MMA16816(c, a, b0, b1) \
    asm volatile("mma.sync.aligned.m16n8k16.row.col.f32.f16.f16.f32 " \
                 "{%0,%1,%2,%3}, {%4,%5,%6,%7}, {%8,%9}, {%0,%1,%2,%3};" \
                 : "+f"((c)[0]), "+f"((c)[1]), "+f"((c)[2]), "+f"((c)[3]) \
                 : "r"((a)[0]), "r"((a)[1]), "r"((a)[2]), "r"((a)[3]), \
                   "r"(b0), "r"(b1))

__device__ __forceinline__ uint32_t packh(float lo, float hi) {
    uint32_t d;
    asm("cvt.rn.f16x2.f32 %0, %1, %2;" : "=r"(d) : "f"(hi), "f"(lo));
    return d;
}

// ---------------------------------------------------------------------------
// Scratch (static device globals)
// ---------------------------------------------------------------------------
__device__ __half g_ahi[(size_t)B_ * NQ_ * DM_];  // x hi, later att hi
__device__ __half g_alo[(size_t)B_ * NQ_ * DM_];
__device__ __half g_qhi[(size_t)B_ * NQ_ * DM_];
__device__ __half g_qlo[(size_t)B_ * NQ_ * DM_];
__device__ __half g_chi[(size_t)B_ * CTXR * DM_];
__device__ __half g_clo[(size_t)B_ * CTXR * DM_];
__device__ __half g_whi[6 * (size_t)DM_ * DM_];
__device__ __half g_wlo[6 * (size_t)DM_ * DM_];
__device__ __half g_kthi[(size_t)B_ * H_ * LT_ * D_];
__device__ __half g_ktlo[(size_t)B_ * H_ * LT_ * D_];
__device__ __half g_vthi[(size_t)B_ * H_ * LT_ * D_];
__device__ __half g_vtlo[(size_t)B_ * H_ * LT_ * D_];
__device__ __half g_kihi[(size_t)B_ * H_ * LI_ * D_];
__device__ __half g_kilo[(size_t)B_ * H_ * LI_ * D_];
__device__ __half g_vihi[(size_t)B_ * H_ * LI_ * D_];
__device__ __half g_vilo[(size_t)B_ * H_ * LI_ * D_];

// ---------------------------------------------------------------------------
// fp32 -> fp16 hi/lo split
// ---------------------------------------------------------------------------
__global__ void conv_rows(const float* __restrict__ src,
                          __half* __restrict__ hi,
                          __half* __restrict__ lo, size_t n)
{
    size_t i = ((size_t)blockIdx.x * blockDim.x + threadIdx.x) * 4;
    if (i >= n) return;
    float4 v = *(const float4*)(src + i);
    float h0 = __half2float(__float2half(v.x));
    float h1 = __half2float(__float2half(v.y));
    float h2 = __half2float(__float2half(v.z));
    float h3 = __half2float(__float2half(v.w));
    *(uint2*)(hi + i) = make_uint2(packh(h0, h1), packh(h2, h3));
    *(uint2*)(lo + i) = make_uint2(packh(v.x - h0, v.y - h1),
                                   packh(v.z - h2, v.w - h3));
}

// W [K=1024, N=1024] -> Wt hi/lo [N, K]
__global__ void conv_wt(const float* __restrict__ W,
                        __half* __restrict__ hi,
                        __half* __restrict__ lo)
{
    __shared__ float tile[32][33];
    const int k0 = blockIdx.y * 32, n0 = blockIdx.x * 32;
    const int tx = threadIdx.x;
    for (int r = threadIdx.y; r < 32; r += 8)
        tile[r][tx] = W[(size_t)(k0 + r) * DM_ + n0 + tx];
    __syncthreads();
    for (int r = threadIdx.y; r < 32; r += 8) {
        float v = tile[tx][r];
        float h = __half2float(__float2half(v));
        size_t oi = (size_t)(n0 + r) * DM_ + k0 + tx;
        hi[oi] = __float2half(h);
        lo[oi] = __float2half(v - h);
    }
}

// ---------------------------------------------------------------------------
// fp16 2-term GEMM via mma.sync: C = remap(A) @ B^T, AhiBhi + AloBhi.
// MODE 0: fp32 C + bias.  MODE 1: KV scatter fp16 hi/lo.  MODE 2: Q *0.125.
// CTA 128x128, BK=32, 3-stage cp.async pipeline (1 sync/iter), 2 CTAs/SM.
// Per-stage smem: Ahi/Alo/Bhi each 128x40 fp16 (80B rows) = 30720 B.
// ---------------------------------------------------------------------------
#define BUF_BYTES   30720
#define GM_SMEM     (3 * BUF_BYTES)   // 92160

template <int MODE>
__global__ void __launch_bounds__(256, 2)
gemm_mma(const __half* __restrict__ Ahi, const __half* __restrict__ Alo,
         const __half* __restrict__ Bhi,
         float* __restrict__ C, const float* __restrict__ bias,
         __half* __restrict__ Chi, __half* __restrict__ Clo,
         int M, int rows_per_seg, int seg_stride, int seg_base)
{
    extern __shared__ __align__(128) char smem[];
    const uint32_t sb = smem_to_u32(smem);
    const int tid = threadIdx.x;
    const int bn = blockIdx.x * 128;
    const int bm = blockIdx.y * 128;
    const int wid = tid >> 5, lane = tid & 31;
    const int Wm = (wid & 3) * 32;
    const int Wn = (wid >> 2) * 64;

    const int lrow = tid >> 1;
    const int lc = tid & 1;
    int m = bm + lrow; if (m > M - 1) m = M - 1;
    const int seg = m / rows_per_seg;
    const int t = m - seg * rows_per_seg;
    const size_t aoff = (size_t)(seg * seg_stride + seg_base + t) * 1024 + lc * 16;
    const size_t boff = (size_t)(bn + lrow) * 1024 + lc * 16;
    const uint32_t soff = (uint32_t)lrow * 80u + (uint32_t)lc * 32u;

    float acc[2][8][4];
#pragma unroll
    for (int i = 0; i < 2; i++)
#pragma unroll
        for (int j = 0; j < 8; j++)
#pragma unroll
            for (int c = 0; c < 4; c++) acc[i][j][c] = 0.f;

    const uint32_t a_frag_row = (uint32_t)(Wm + (lane & 15)) * 80u + ((lane >> 4) * 16u);
    const uint32_t b_frag_row =
        (uint32_t)(Wn + (lane & 7) + ((lane >> 4) << 3)) * 80u + (((lane >> 3) & 1) * 16u);

#define ISSUE(p, k0)                                                       \
    {                                                                      \
        uint32_t d = sb + (p) * BUF_BYTES + soff;                          \
        const __half* s;                                                   \
        s = Ahi + aoff + (k0); CPA16(d,           s); CPA16(d + 16,         s + 8); \
        s = Alo + aoff + (k0); CPA16(d + 10240,   s); CPA16(d + 10240 + 16, s + 8); \
        s = Bhi + boff + (k0); CPA16(d + 20480,   s); CPA16(d + 20480 + 16, s + 8); \
    }

    ISSUE(0, 0);
    CPA_COMMIT();
    ISSUE(1, 32);
    CPA_COMMIT();

    int stage = 0;
    for (int i = 0; i < 32; i++) {
        if (i < 31) { CPA_WAIT(1); } else { CPA_WAIT(0); }
        __syncthreads();
        if (i + 2 < 32) {
            int ns = stage + 2; if (ns >= 3) ns -= 3;
            ISSUE(ns, (i + 2) * 32);
            CPA_COMMIT();
        }

        const uint32_t base = sb + stage * BUF_BYTES;
#pragma unroll
        for (int kk = 0; kk < 2; kk++) {
            uint32_t ah[2][4], al[2][4];
            const uint32_t ar = base + a_frag_row + kk * 32;
            LDMX4(ah[0][0], ah[0][1], ah[0][2], ah[0][3], ar);
            LDMX4(ah[1][0], ah[1][1], ah[1][2], ah[1][3], ar + 16 * 80);
            LDMX4(al[0][0], al[0][1], al[0][2], al[0][3], ar + 10240);
            LDMX4(al[1][0], al[1][1], al[1][2], al[1][3], ar + 10240 + 16 * 80);
#pragma unroll
            for (int j = 0; j < 4; j++) {
                uint32_t bh0, bh1, bh2, bh3;
                const uint32_t br = base + b_frag_row + kk * 32 + (uint32_t)j * (16 * 80);
                LDMX4(bh0, bh1, bh2, bh3, br + 20480);
#pragma unroll
                for (int mt = 0; mt < 2; mt++) {
                    MMA16816(acc[mt][2 * j],     ah[mt], bh0, bh1);
                    MMA16816(acc[mt][2 * j],     al[mt], bh0, bh1);
                    MMA16816(acc[mt][2 * j + 1], ah[mt], bh2, bh3);
                    MMA16816(acc[mt][2 * j + 1], al[mt], bh2, bh3);
                }
            }
        }
        stage++; if (stage >= 3) stage = 0;
    }
#undef ISSUE

    const int er = lane >> 2, ec = (lane & 3) * 2;
#pragma unroll
    for (int mt = 0; mt < 2; mt++) {
#pragma unroll
        for (int hrow = 0; hrow < 2; hrow++) {
            const int cm = bm + Wm + mt * 16 + er + hrow * 8;
            if (cm >= M) continue;
            if (MODE == 1) {
                const int segc = cm / rows_per_seg;
                const int tc = cm - segc * rows_per_seg;
#pragma unroll
                for (int nt = 0; nt < 8; nt++) {
                    const int cn = bn + Wn + nt * 8 + ec;
                    const int hh = cn >> 6, dd = cn & 63;
                    size_t oi = (((size_t)segc * H_ + hh) * rows_per_seg + tc) * 64 + dd;
                    float v0 = acc[mt][nt][hrow * 2], v1 = acc[mt][nt][hrow * 2 + 1];
                    float h0 = __half2float(__float2half(v0));
                    float h1 = __half2float(__float2half(v1));
                    *(uint32_t*)(Chi + oi) = packh(h0, h1);
                    *(uint32_t*)(Clo + oi) = packh(v0 - h0, v1 - h1);
                }
            } else if (MODE == 2) {
#pragma unroll
                for (int nt = 0; nt < 8; nt++) {
                    const int cn = bn + Wn + nt * 8 + ec;
                    size_t oi = (size_t)cm * DM_ + cn;
                    float v0 = acc[mt][nt][hrow * 2] * 0.125f;
                    float v1 = acc[mt][nt][hrow * 2 + 1] * 0.125f;
                    float h0 = __half2float(__float2half(v0));
                    float h1 = __half2float(__float2half(v1));
                    *(uint32_t*)(Chi + oi) = packh(h0, h1);
                    *(uint32_t*)(Clo + oi) = packh(v0 - h0, v1 - h1);
                }
            } else {
                float* Cp = C + (size_t)cm * DM_ + bn + Wn + ec;
                const float* bp = bias + bn + Wn + ec;
#pragma unroll
                for (int nt = 0; nt < 8; nt++) {
                    float2 v = make_float2(acc[mt][nt][hrow * 2] + bp[nt * 8],
                                           acc[mt][nt][hrow * 2 + 1] + bp[nt * 8 + 1]);
                    *(float2*)(Cp + nt * 8) = v;
                }
            }
        }
    }
}

// ---------------------------------------------------------------------------
// Tensor-core flash attention (fp16 hi/lo). One CTA = (b, h, 128-query tile).
// ---------------------------------------------------------------------------
#define AT_KHI 0
#define AT_KLO 48384
#define AT_VHI 96768
#define AT_VLO 145152
#define AT_QHI 193536
#define AT_QLO 211968
#define AT_PS  193536
#define AT_RKH 211968
#define AT_RKL 217728
#define AT_SMEM 230400

__device__ __forceinline__ int bidx(int j, int i)
{
    int d = j - i;
    d = max(-16, min(16, d));
    return d + 16;
}

__device__ __forceinline__ void wsplit(const float* s0, const float* s1,
                                       uint32_t* ahi, uint32_t* alo)
{
    float v[8] = {s0[0], s0[1], s0[2], s0[3], s1[0], s1[1], s1[2], s1[3]};
    float hv[8];
#pragma unroll
    for (int i = 0; i < 8; i++)
        hv[i] = __half2float(__float2half(v[i]));
    ahi[0] = packh(hv[0], hv[1]); ahi[1] = packh(hv[2], hv[3]);
    ahi[2] = packh(hv[4], hv[5]); ahi[3] = packh(hv[6], hv[7]);
    alo[0] = packh(v[0] - hv[0], v[1] - hv[1]);
    alo[1] = packh(v[2] - hv[2], v[3] - hv[3]);
    alo[2] = packh(v[4] - hv[4], v[5] - hv[5]);
    alo[3] = packh(v[6] - hv[6], v[7] - hv[7]);
}

__global__ void __launch_bounds__(256, 1)
attn_mma(const __half* __restrict__ qhi, const __half* __restrict__ qlo,
         const __half* __restrict__ kthi, const __half* __restrict__ ktlo,
         const __half* __restrict__ vthi, const __half* __restrict__ vtlo,
         const __half* __restrict__ kihi, const __half* __restrict__ kilo,
         const __half* __restrict__ vihi, const __half* __restrict__ vilo,
         const float* __restrict__ relk, const float* __restrict__ relv,
         __half* __restrict__ atthi, __half* __restrict__ attlo)
{
    extern __shared__ __align__(128) char sm[];
    const uint32_t sb = smem_to_u32(sm);
    const int tid = threadIdx.x, w = tid >> 5, lane = tid & 31;
    const int bh = blockIdx.x >> 3, qt = blockIdx.x & 7;
    const int b = bh >> 4, h = bh & 15;
    const int i0 = qt * 128;
    const unsigned FULL = 0xffffffffu;

    // ---- stage K/V/Q ----
    {
        size_t tb = (size_t)bh * (LT_ * 64);
        for (int idx = tid; idx < LT_ * 8; idx += 256) {
            int r = idx >> 3, c = idx & 7;
            uint32_t d = (uint32_t)r * 144 + c * 16;
            size_t s = tb + (size_t)r * 64 + c * 8;
            CPA16(sb + AT_KHI + d, kthi + s);
            CPA16(sb + AT_KLO + d, ktlo + s);
            CPA16(sb + AT_VHI + d, vthi + s);
            CPA16(sb + AT_VLO + d, vtlo + s);
        }
        size_t ib = (size_t)bh * (LI_ * 64);
        for (int idx = tid; idx < LI_ * 8; idx += 256) {
            int r = idx >> 3, c = idx & 7;
            uint32_t d = (uint32_t)(80 + r) * 144 + c * 16;
            size_t s = ib + (size_t)r * 64 + c * 8;
            CPA16(sb + AT_KHI + d, kihi + s);
            CPA16(sb + AT_KLO + d, kilo + s);
            CPA16(sb + AT_VHI + d, vihi + s);
            CPA16(sb + AT_VLO + d, vilo + s);
        }
        size_t qb = ((size_t)(b * NQ_ + i0)) * 1024 + h * 64;
        for (int idx = tid; idx < 128 * 8; idx += 256) {
            int r = idx >> 3, c = idx & 7;
            uint32_t d = (uint32_t)r * 144 + c * 16;
            size_t s = qb + (size_t)r * 1024 + c * 8;
            CPA16(sb + AT_QHI + d, qhi + s);
            CPA16(sb + AT_QLO + d, qlo + s);
        }
        for (int idx = tid; idx < 3 * 36; idx += 256) {
            uint32_t d = (uint32_t)(77 + idx / 36) * 144 + (idx % 36) * 4;
            *(uint32_t*)(sm + AT_KHI + d) = 0;
            *(uint32_t*)(sm + AT_KLO + d) = 0;
            *(uint32_t*)(sm + AT_VHI + d) = 0;
            *(uint32_t*)(sm + AT_VLO + d) = 0;
        }
        CPA_COMMIT();
        CPA_WAIT(0);
        __syncthreads();
    }

    const int wr = w * 16;
    const int r0l = wr + (lane >> 2);

    // ---- Q fragments ----
    uint32_t qh[4][4], ql[4][4];
    {
        int row = wr + (lane & 15);
        int kb = (lane >> 4) * 16;
#pragma unroll
        for (int kk = 0; kk < 4; kk++) {
            uint32_t a = sb + AT_QHI + (uint32_t)row * 144 + kk * 32 + kb;
            LDMX4(qh[kk][0], qh[kk][1], qh[kk][2], qh[kk][3], a);
            LDMX4(ql[kk][0], ql[kk][1], ql[kk][2], ql[kk][3], a + (AT_QLO - AT_QHI));
        }
    }
    __syncthreads();

    if (qt == 0) {
        for (int idx = tid; idx < NR_ * 64; idx += 256) {
            int r = idx >> 6, dc = idx & 63;
            float v = relk[idx];
            float hh = __half2float(__float2half(v));
            *(__half*)(sm + AT_RKH + r * 144 + dc * 2) = __float2half(hh);
            *(__half*)(sm + AT_RKL + r * 144 + dc * 2) = __float2half(v - hh);
        }
    }
    __syncthreads();

    float* pS = (float*)(sm + AT_PS);

    const int brow = ((lane >> 4) << 3) + (lane & 7);
    const int bdb = (lane & 8) * 2;

    // ---- rel-K projections (tile 0) ----
    if (qt == 0) {
        float pr[5][4];
#pragma unroll
        for (int i = 0; i < 5; i++)
#pragma unroll
            for (int c = 0; c < 4; c++) pr[i][c] = 0.f;
#pragma unroll
        for (int kk = 0; kk < 4; kk++) {
#pragma unroll
            for (int p2 = 0; p2 < 3; p2++) {
                uint32_t bh4[4], bl4[4];
                uint32_t ad = sb + AT_RKH + (uint32_t)(p2 * 16 + brow) * 144
                              + kk * 32 + bdb;
                LDMX4(bh4[0], bh4[1], bh4[2], bh4[3], ad);
                LDMX4(bl4[0], bl4[1], bl4[2], bl4[3], ad + (AT_RKL - AT_RKH));
                MMA16816(pr[2 * p2], qh[kk], bh4[0], bh4[1]);
                MMA16816(pr[2 * p2], ql[kk], bh4[0], bh4[1]);
                MMA16816(pr[2 * p2], qh[kk], bl4[0], bl4[1]);
                if (p2 < 2) {
                    MMA16816(pr[2 * p2 + 1], qh[kk], bh4[2], bh4[3]);
                    MMA16816(pr[2 * p2 + 1], ql[kk], bh4[2], bh4[3]);
                    MMA16816(pr[2 * p2 + 1], qh[kk], bl4[2], bl4[3]);
                }
            }
        }
#pragma unroll
        for (int nt = 0; nt < 5; nt++) {
            int c0 = nt * 8 + 2 * (lane & 3);
            if (c0 < NR_) {
                pS[r0l * 34 + c0] = pr[nt][0];
                pS[(r0l + 8) * 34 + c0] = pr[nt][2];
            }
            if (c0 + 1 < NR_) {
                pS[r0l * 34 + c0 + 1] = pr[nt][1];
                pS[(r0l + 8) * 34 + c0 + 1] = pr[nt][3];
            }
        }
        __syncwarp();
    }

    // ---- text scores ----
    float s[10][4];
#pragma unroll
    for (int i = 0; i < 10; i++)
#pragma unroll
        for (int c = 0; c < 4; c++) s[i][c] = 0.f;
#pragma unroll
    for (int kk = 0; kk < 4; kk++) {
#pragma unroll
        for (int p2 = 0; p2 < 5; p2++) {
            uint32_t kh4[4], kl4[4];
            uint32_t ad = sb + AT_KHI + (uint32_t)(p2 * 16 + brow) * 144
                          + kk * 32 + bdb;
            LDMX4(kh4[0], kh4[1], kh4[2], kh4[3], ad);
            LDMX4(kl4[0], kl4[1], kl4[2], kl4[3], ad + (AT_KLO - AT_KHI));
            MMA16816(s[2 * p2], qh[kk], kh4[0], kh4[1]);
            MMA16816(s[2 * p2], ql[kk], kh4[0], kh4[1]);
            MMA16816(s[2 * p2], qh[kk], kl4[0], kl4[1]);
            MMA16816(s[2 * p2 + 1], qh[kk], kh4[2], kh4[3]);
            MMA16816(s[2 * p2 + 1], ql[kk], kh4[2], kh4[3]);
            MMA16816(s[2 * p2 + 1], qh[kk], kl4[2], kl4[3]);
        }
    }

#pragma unroll
    for (int nt = 0; nt < 10; nt++) {
        int c0 = nt * 8 + 2 * (lane & 3);
        if (qt == 0) {
            s[nt][0] += pS[r0l * 34 + bidx(c0, r0l)];
            s[nt][1] += pS[r0l * 34 + bidx(c0 + 1, r0l)];
            s[nt][2] += pS[(r0l + 8) * 34 + bidx(c0, r0l + 8)];
            s[nt][3] += pS[(r0l + 8) * 34 + bidx(c0 + 1, r0l + 8)];
        }
        if (c0 >= LT_) { s[nt][0] = -1e30f; s[nt][2] = -1e30f; }
        if (c0 + 1 >= LT_) { s[nt][1] = -1e30f; s[nt][3] = -1e30f; }
    }

    float m0 = -1e30f, m1 = -1e30f;
#pragma unroll
    for (int nt = 0; nt < 10; nt++) {
        m0 = fmaxf(m0, fmaxf(s[nt][0], s[nt][1]));
        m1 = fmaxf(m1, fmaxf(s[nt][2], s[nt][3]));
    }
    m0 = fmaxf(m0, __shfl_xor_sync(FULL, m0, 1));
    m0 = fmaxf(m0, __shfl_xor_sync(FULL, m0, 2));
    m1 = fmaxf(m1, __shfl_xor_sync(FULL, m1, 1));
    m1 = fmaxf(m1, __shfl_xor_sync(FULL, m1, 2));
    float l0 = 0.f, l1 = 0.f;
#pragma unroll
    for (int nt = 0; nt < 10; nt++) {
        s[nt][0] = __expf(s[nt][0] - m0); l0 += s[nt][0];
        s[nt][1] = __expf(s[nt][1] - m0); l0 += s[nt][1];
        s[nt][2] = __expf(s[nt][2] - m1); l1 += s[nt][2];
        s[nt][3] = __expf(s[nt][3] - m1); l1 += s[nt][3];
    }
    l0 += __shfl_xor_sync(FULL, l0, 1); l0 += __shfl_xor_sync(FULL, l0, 2);
    l1 += __shfl_xor_sync(FULL, l1, 1); l1 += __shfl_xor_sync(FULL, l1, 2);
    float inv0 = 1.f / l0, inv1 = 1.f / l1;
#pragma unroll
    for (int nt = 0; nt < 10; nt++) {
        s[nt][0] *= inv0; s[nt][1] *= inv0;
        s[nt][2] *= inv1; s[nt][3] *= inv1;
    }

    if (qt == 0) {
        for (int idx = lane; idx < 16 * 34; idx += 32)
            pS[(wr + idx / 34) * 34 + idx % 34] = 0.f;
        __syncwarp();
#pragma unroll
        for (int nt = 0; nt < 10; nt++) {
            int c0 = nt * 8 + 2 * (lane & 3);
            if (c0 < LT_) {
                atomicAdd(&pS[r0l * 34 + bidx(c0, r0l)], s[nt][0]);
                atomicAdd(&pS[(r0l + 8) * 34 + bidx(c0, r0l + 8)], s[nt][2]);
            }
            if (c0 + 1 < LT_) {
                atomicAdd(&pS[r0l * 34 + bidx(c0 + 1, r0l)], s[nt][1]);
                atomicAdd(&pS[(r0l + 8) * 34 + bidx(c0 + 1, r0l + 8)], s[nt][3]);
            }
        }
        __syncwarp();
    }

    const int vrow = (lane & 8) + (lane & 7);
    const int vdb = (lane >> 4) * 16;

    float ot[8][4];
#pragma unroll
    for (int i = 0; i < 8; i++)
#pragma unroll
        for (int c = 0; c < 4; c++) ot[i][c] = 0.f;
#pragma unroll
    for (int wk = 0; wk < 5; wk++) {
        uint32_t ahi[4], alo[4];
        wsplit(s[2 * wk], s[2 * wk + 1], ahi, alo);
#pragma unroll
        for (int dp = 0; dp < 4; dp++) {
            uint32_t vh4[4], vl4[4];
            uint32_t ad = sb + AT_VHI + (uint32_t)(wk * 16 + vrow) * 144
                          + dp * 32 + vdb;
            LDMX4T(vh4[0], vh4[1], vh4[2], vh4[3], ad);
            LDMX4T(vl4[0], vl4[1], vl4[2], vl4[3], ad + (AT_VLO - AT_VHI));
            MMA16816(ot[2 * dp], ahi, vh4[0], vh4[1]);
            MMA16816(ot[2 * dp], alo, vh4[0], vh4[1]);
            MMA16816(ot[2 * dp], ahi, vl4[0], vl4[1]);
            MMA16816(ot[2 * dp + 1], ahi, vh4[2], vh4[3]);
            MMA16816(ot[2 * dp + 1], alo, vh4[2], vh4[3]);
            MMA16816(ot[2 * dp + 1], ahi, vl4[2], vl4[3]);
        }
    }

    if (qt == 0) {
#pragma unroll 1
        for (int r = 0; r < NR_; r++) {
            float w0 = pS[r0l * 34 + r];
            float w1 = pS[(r0l + 8) * 34 + r];
            const float* rv = relv + r * 64 + 2 * (lane & 3);
#pragma unroll
            for (int dt = 0; dt < 8; dt++) {
                float rv0 = rv[dt * 8], rv1 = rv[dt * 8 + 1];
                ot[dt][0] += w0 * rv0; ot[dt][1] += w0 * rv1;
                ot[dt][2] += w1 * rv0; ot[dt][3] += w1 * rv1;
            }
        }
    } else {
        const float* rv = relv + 2 * (lane & 3);
#pragma unroll
        for (int dt = 0; dt < 8; dt++) {
            float rv0 = rv[dt * 8], rv1 = rv[dt * 8 + 1];
            ot[dt][0] += rv0; ot[dt][1] += rv1;
            ot[dt][2] += rv0; ot[dt][3] += rv1;
        }
    }

    float oi[8][4];
#pragma unroll
    for (int i = 0; i < 8; i++)
#pragma unroll
        for (int c = 0; c < 4; c++) oi[i][c] = 0.f;
    float mi0 = -1e30f, mi1 = -1e30f, li0 = 0.f, li1 = 0.f;
#pragma unroll 1
    for (int ch = 0; ch < 8; ch++) {
        const int j0 = 80 + ch * 32;
        float sc[4][4];
#pragma unroll
        for (int i = 0; i < 4; i++)
#pragma unroll
            for (int c = 0; c < 4; c++) sc[i][c] = 0.f;
#pragma unroll
        for (int kk = 0; kk < 4; kk++) {
#pragma unroll
            for (int p2 = 0; p2 < 2; p2++) {
                uint32_t kh4[4], kl4[4];
                uint32_t ad = sb + AT_KHI + (uint32_t)(j0 + p2 * 16 + brow) * 144
                              + kk * 32 + bdb;
                LDMX4(kh4[0], kh4[1], kh4[2], kh4[3], ad);
                LDMX4(kl4[0], kl4[1], kl4[2], kl4[3], ad + (AT_KLO - AT_KHI));
                MMA16816(sc[2 * p2], qh[kk], kh4[0], kh4[1]);
                MMA16816(sc[2 * p2], ql[kk], kh4[0], kh4[1]);
                MMA16816(sc[2 * p2], qh[kk], kl4[0], kl4[1]);
                MMA16816(sc[2 * p2 + 1], qh[kk], kh4[2], kh4[3]);
                MMA16816(sc[2 * p2 + 1], ql[kk], kh4[2], kh4[3]);
                MMA16816(sc[2 * p2 + 1], qh[kk], kl4[2], kl4[3]);
            }
        }
        float cm0 = -1e30f, cm1 = -1e30f;
#pragma unroll
        for (int t = 0; t < 4; t++) {
            cm0 = fmaxf(cm0, fmaxf(sc[t][0], sc[t][1]));
            cm1 = fmaxf(cm1, fmaxf(sc[t][2], sc[t][3]));
        }
        cm0 = fmaxf(cm0, __shfl_xor_sync(FULL, cm0, 1));
        cm0 = fmaxf(cm0, __shfl_xor_sync(FULL, cm0, 2));
        cm1 = fmaxf(cm1, __shfl_xor_sync(FULL, cm1, 1));
        cm1 = fmaxf(cm1, __shfl_xor_sync(FULL, cm1, 2));
        float mn0 = fmaxf(mi0, cm0), mn1 = fmaxf(mi1, cm1);
        float al0 = __expf(mi0 - mn0), al1 = __expf(mi1 - mn1);
        float cs0 = 0.f, cs1 = 0.f;
#pragma unroll
        for (int t = 0; t < 4; t++) {
            sc[t][0] = __expf(sc[t][0] - mn0); cs0 += sc[t][0];
            sc[t][1] = __expf(sc[t][1] - mn0); cs0 += sc[t][1];
            sc[t][2] = __expf(sc[t][2] - mn1); cs1 += sc[t][2];
            sc[t][3] = __expf(sc[t][3] - mn1); cs1 += sc[t][3];
        }
        cs0 += __shfl_xor_sync(FULL, cs0, 1); cs0 += __shfl_xor_sync(FULL, cs0, 2);
        cs1 += __shfl_xor_sync(FULL, cs1, 1); cs1 += __shfl_xor_sync(FULL, cs1, 2);
        li0 = li0 * al0 + cs0; li1 = li1 * al1 + cs1;
        mi0 = mn0; mi1 = mn1;
#pragma unroll
        for (int dt = 0; dt < 8; dt++) {
            oi[dt][0] *= al0; oi[dt][1] *= al0;
            oi[dt][2] *= al1; oi[dt][3] *= al1;
        }
#pragma unroll
        for (int wk = 0; wk < 2; wk++) {
            uint32_t ahi[4], alo[4];
            wsplit(sc[2 * wk], sc[2 * wk + 1], ahi, alo);
#pragma unroll
            for (int dp = 0; dp < 4; dp++) {
                uint32_t vh4[4], vl4[4];
                uint32_t ad = sb + AT_VHI + (uint32_t)(j0 + wk * 16 + vrow) * 144
                              + dp * 32 + vdb;
                LDMX4T(vh4[0], vh4[1], vh4[2], vh4[3], ad);
                LDMX4T(vl4[0], vl4[1], vl4[2], vl4[3], ad + (AT_VLO - AT_VHI));
                MMA16816(oi[2 * dp], ahi, vh4[0], vh4[1]);
                MMA16816(oi[2 * dp], alo, vh4[0], vh4[1]);
                MMA16816(oi[2 * dp], ahi, vl4[0], vl4[1]);
                MMA16816(oi[2 * dp + 1], ahi, vh4[2], vh4[3]);
                MMA16816(oi[2 * dp + 1], alo, vh4[2], vh4[3]);
                MMA16816(oi[2 * dp + 1], ahi, vl4[2], vl4[3]);
            }
        }
    }
    float ii0 = 1.f / li0, ii1 = 1.f / li1;

    {
        size_t ob = ((size_t)(b * NQ_ + i0 + r0l)) * 1024 + h * 64 + 2 * (lane & 3);
#pragma unroll
        for (int dt = 0; dt < 8; dt++) {
            float v0 = ot[dt][0] + oi[dt][0] * ii0;
            float v1 = ot[dt][1] + oi[dt][1] * ii0;
            float v2 = ot[dt][2] + oi[dt][2] * ii1;
            float v3 = ot[dt][3] + oi[dt][3] * ii1;
            float h0 = __half2float(__float2half(v0));
            float h1 = __half2float(__float2half(v1));
            float h2 = __half2float(__float2half(v2));
            float h3 = __half2float(__float2half(v3));
            size_t o0 = ob + dt * 8;
            size_t o1 = o0 + 8 * 1024;
            *(uint32_t*)(atthi + o0) = packh(h0, h1);
            *(uint32_t*)(attlo + o0) = packh(v0 - h0, v1 - h1);
            *(uint32_t*)(atthi + o1) = packh(h2, h3);
            *(uint32_t*)(attlo + o1) = packh(v2 - h2, v3 - h3);
        }
    }
}

// ---------------------------------------------------------------------------
// Host launcher
// ---------------------------------------------------------------------------
extern "C" void kernel_launch(void* const* d_in, const int* in_sizes, int n_in,
                              void* d_out, int out_size)
{
    const float* x     = (const float*)d_in[0];
    const float* ctx   = (const float*)d_in[1];
    const float* Wq    = (const float*)d_in[2];
    const float* Wk    = (const float*)d_in[3];
    const float* Wv    = (const float*)d_in[4];
    const float* Wk_ip = (const float*)d_in[5];
    const float* Wv_ip = (const float*)d_in[6];
    const float* Wout  = (const float*)d_in[7];
    const float* bout  = (const float*)d_in[8];
    const float* relk  = (const float*)d_in[9];
    const float* relv  = (const float*)d_in[10];
    float* out = (float*)d_out;

    __half *pahi, *palo, *pqhi, *pqlo, *pchi, *pclo, *pwhi, *pwlo;
    __half *pkthi, *pktlo, *pvthi, *pvtlo, *pkihi, *pkilo, *pvihi, *pvilo;
    cudaGetSymbolAddress((void**)&pahi, g_ahi);
    cudaGetSymbolAddress((void**)&palo, g_alo);
    cudaGetSymbolAddress((void**)&pqhi, g_qhi);
    cudaGetSymbolAddress((void**)&pqlo, g_qlo);
    cudaGetSymbolAddress((void**)&pchi, g_chi);
    cudaGetSymbolAddress((void**)&pclo, g_clo);
    cudaGetSymbolAddress((void**)&pwhi, g_whi);
    cudaGetSymbolAddress((void**)&pwlo, g_wlo);
    cudaGetSymbolAddress((void**)&pkthi, g_kthi);
    cudaGetSymbolAddress((void**)&pktlo, g_ktlo);
    cudaGetSymbolAddress((void**)&pvthi, g_vthi);
    cudaGetSymbolAddress((void**)&pvtlo, g_vtlo);
    cudaGetSymbolAddress((void**)&pkihi, g_kihi);
    cudaGetSymbolAddress((void**)&pkilo, g_kilo);
    cudaGetSymbolAddress((void**)&pvihi, g_vihi);
    cudaGetSymbolAddress((void**)&pvilo, g_vilo);

    cudaFuncSetAttribute(gemm_mma<0>,
                         cudaFuncAttributeMaxDynamicSharedMemorySize, GM_SMEM);
    cudaFuncSetAttribute(gemm_mma<1>,
                         cudaFuncAttributeMaxDynamicSharedMemorySize, GM_SMEM);
    cudaFuncSetAttribute(gemm_mma<2>,
                         cudaFuncAttributeMaxDynamicSharedMemorySize, GM_SMEM);
    cudaFuncSetAttribute(attn_mma,
                         cudaFuncAttributeMaxDynamicSharedMemorySize, AT_SMEM);

    const size_t WSZ = (size_t)DM_ * DM_;
    size_t nx = (size_t)B_ * NQ_ * DM_;
    size_t nc = (size_t)B_ * CTXR * DM_;

    conv_wt<<<dim3(32, 32), dim3(32, 8)>>>(Wq, pwhi + 0 * WSZ, pwlo + 0 * WSZ);
    conv_rows<<<(unsigned)(nx / 4 / 256), 256>>>(x, pahi, palo, nx);
    conv_rows<<<(unsigned)((nc / 4 + 255) / 256), 256>>>(ctx, pchi, pclo, nc);
    conv_wt<<<dim3(32, 32), dim3(32, 8)>>>(Wk, pwhi + 1 * WSZ, pwlo + 1 * WSZ);
    conv_wt<<<dim3(32, 32), dim3(32, 8)>>>(Wv, pwhi + 2 * WSZ, pwlo + 2 * WSZ);

    // Q = (x @ Wq) * 0.125 -> fp16 hi/lo
    gemm_mma<2><<<dim3(8, 512), 256, GM_SMEM>>>(
        pahi, palo, pwhi + 0 * WSZ, nullptr, nullptr,
        pqhi, pqlo, B_ * NQ_, B_ * NQ_, B_ * NQ_, 0);

    conv_wt<<<dim3(32, 32), dim3(32, 8)>>>(Wk_ip, pwhi + 3 * WSZ, pwlo + 3 * WSZ);
    conv_wt<<<dim3(32, 32), dim3(32, 8)>>>(Wv_ip, pwhi + 4 * WSZ, pwlo + 4 * WSZ);
    conv_wt<<<dim3(32, 32), dim3(32, 8)>>>(Wout,  pwhi + 5 * WSZ, pwlo + 5 * WSZ);

    // K/V text -> [b][h][t][d] fp16 hi/lo
    gemm_mma<1><<<dim3(8, 39), 256, GM_SMEM>>>(
        pchi, pclo, pwhi + 1 * WSZ, nullptr, nullptr,
        pkthi, pktlo, B_ * LT_, LT_, CTXR, 0);
    gemm_mma<1><<<dim3(8, 39), 256, GM_SMEM>>>(
        pchi, pclo, pwhi + 2 * WSZ, nullptr, nullptr,
        pvthi, pvtlo, B_ * LT_, LT_, CTXR, 0);

    // K/V image
    gemm_mma<1><<<dim3(8, 128), 256, GM_SMEM>>>(
        pchi, pclo, pwhi + 3 * WSZ, nullptr, nullptr,
        pkihi, pkilo, B_ * LI_, LI_, CTXR, LT_);
    gemm_mma<1><<<dim3(8, 128), 256, GM_SMEM>>>(
        pchi, pclo, pwhi + 4 * WSZ, nullptr, nullptr,
        pvihi, pvilo, B_ * LI_, LI_, CTXR, LT_);

    // tensor-core attention -> fp16 hi/lo into final-GEMM input buffers
    attn_mma<<<B_ * H_ * 8, 256, AT_SMEM>>>(
        pqhi, pqlo, pkthi, pktlo, pvthi, pvtlo,
        pkihi, pkilo, pvihi, pvilo, relk, relv, pahi, palo);

    // final projection + bias
    gemm_mma<0><<<dim3(8, 512), 256, GM_SMEM>>>(
        pahi, palo, pwhi + 5 * WSZ, out, bout,
        nullptr, nullptr, B_ * NQ_, B_ * NQ_, B_ * NQ_, 0);
}

// round 10
// speedup vs baseline: 4.2061x; 1.0024x over previous
#include <cuda_runtime.h>
#include <cuda_fp16.h>
#include <cstdint>

// ---------------------------------------------------------------------------
// Problem constants
// ---------------------------------------------------------------------------
#define B_    64
#define NQ_   1024
#define DM_   1024
#define H_    16
#define D_    64
#define LT_   77
#define LI_   256
#define NR_   33
#define CTXR  (LT_ + LI_)     // 333

__device__ __forceinline__ uint32_t smem_to_u32(const void* p) {
    uint32_t a;
    asm("{ .reg .u64 t; cvta.to.shared.u64 t, %1; cvt.u32.u64 %0, t; }"
        : "=r"(a) : "l"(p));
    return a;
}

#define CPA16(dst, src) \
    asm volatile("cp.async.cg.shared.global [%0], [%1], 16;" \
                 :: "r"(dst), "l"(src))
#define CPA_COMMIT() asm volatile("cp.async.commit_group;" ::: "memory")
#define CPA_WAIT(n)  asm volatile("cp.async.wait_group %0;" :: "n"(n) : "memory")

#define LDMX4(r0, r1, r2, r3, addr) \
    asm volatile("ldmatrix.sync.aligned.m8n8.x4.shared.b16 {%0,%1,%2,%3}, [%4];" \
                 : "=r"(r0), "=r"(r1), "=r"(r2), "=r"(r3) : "r"(addr))
#define LDMX4T(r0, r1, r2, r3, addr) \
    asm volatile("ldmatrix.sync.aligned.m8n8.x4.trans.shared.b16 {%0,%1,%2,%3}, [%4];" \
                 : "=r"(r0), "=r"(r1), "=r"(r2), "=r"(r3) : "r"(addr))

#define MMA16816(c, a, b0, b1) \
    asm volatile("mma.sync.aligned.m16n8k16.row.col.f32.f16.f16.f32 " \
                 "{%0,%1,%2,%3}, {%4,%5,%6,%7}, {%8,%9}, {%0,%1,%2,%3};" \
                 : "+f"((c)[0]), "+f"((c)[1]), "+f"((c)[2]), "+f"((c)[3]) \
                 : "r"((a)[0]), "r"((a)[1]), "r"((a)[2]), "r"((a)[3]), \
                   "r"(b0), "r"(b1))

__device__ __forceinline__ uint32_t packh(float lo, float hi) {
    uint32_t d;
    asm("cvt.rn.f16x2.f32 %0, %1, %2;" : "=r"(d) : "f"(hi), "f"(lo));
    return d;
}

// ---------------------------------------------------------------------------
// Scratch (static device globals)
// ---------------------------------------------------------------------------
__device__ __half g_ahi[(size_t)B_ * NQ_ * DM_];  // x hi, later att hi
__device__ __half g_alo[(size_t)B_ * NQ_ * DM_];
__device__ __half g_qhi[(size_t)B_ * NQ_ * DM_];
__device__ __half g_qlo[(size_t)B_ * NQ_ * DM_];
__device__ __half g_chi[(size_t)B_ * CTXR * DM_];
__device__ __half g_clo[(size_t)B_ * CTXR * DM_];
__device__ __half g_whi[6 * (size_t)DM_ * DM_];
__device__ __half g_wlo[6 * (size_t)DM_ * DM_];
__device__ __half g_kthi[(size_t)B_ * H_ * LT_ * D_];
__device__ __half g_ktlo[(size_t)B_ * H_ * LT_ * D_];
__device__ __half g_vthi[(size_t)B_ * H_ * LT_ * D_];
__device__ __half g_vtlo[(size_t)B_ * H_ * LT_ * D_];
__device__ __half g_kihi[(size_t)B_ * H_ * LI_ * D_];
__device__ __half g_kilo[(size_t)B_ * H_ * LI_ * D_];
__device__ __half g_vihi[(size_t)B_ * H_ * LI_ * D_];
__device__ __half g_vilo[(size_t)B_ * H_ * LI_ * D_];

// ---------------------------------------------------------------------------
// fp32 -> fp16 hi/lo split
// ---------------------------------------------------------------------------
__global__ void conv_rows(const float* __restrict__ src,
                          __half* __restrict__ hi,
                          __half* __restrict__ lo, size_t n)
{
    size_t i = ((size_t)blockIdx.x * blockDim.x + threadIdx.x) * 4;
    if (i >= n) return;
    float4 v = *(const float4*)(src + i);
    float h0 = __half2float(__float2half(v.x));
    float h1 = __half2float(__float2half(v.y));
    float h2 = __half2float(__float2half(v.z));
    float h3 = __half2float(__float2half(v.w));
    *(uint2*)(hi + i) = make_uint2(packh(h0, h1), packh(h2, h3));
    *(uint2*)(lo + i) = make_uint2(packh(v.x - h0, v.y - h1),
                                   packh(v.z - h2, v.w - h3));
}

// W [K=1024, N=1024] -> Wt hi/lo [N, K]
__global__ void conv_wt(const float* __restrict__ W,
                        __half* __restrict__ hi,
                        __half* __restrict__ lo)
{
    __shared__ float tile[32][33];
    const int k0 = blockIdx.y * 32, n0 = blockIdx.x * 32;
    const int tx = threadIdx.x;
    for (int r = threadIdx.y; r < 32; r += 8)
        tile[r][tx] = W[(size_t)(k0 + r) * DM_ + n0 + tx];
    __syncthreads();
    for (int r = threadIdx.y; r < 32; r += 8) {
        float v = tile[tx][r];
        float h = __half2float(__float2half(v));
        size_t oi = (size_t)(n0 + r) * DM_ + k0 + tx;
        hi[oi] = __float2half(h);
        lo[oi] = __float2half(v - h);
    }
}

// ---------------------------------------------------------------------------
// fp16 2-term GEMM via mma.sync: C = remap(A) @ B^T, AhiBhi + AloBhi.
// MODE 0: fp32 C + bias.  MODE 1: KV scatter fp16 hi/lo.  MODE 2: Q *0.125.
// CTA 128x128, BK=32, 3-stage cp.async pipeline, 2 CTAs/SM.
// Mainloop: all B frags register-resident per k16 chunk; hi-term MMA sweep
// (16 independent accs) then lo-term sweep -> dependent MMAs >=16 apart.
// ---------------------------------------------------------------------------
#define BUF_BYTES   30720
#define GM_SMEM     (3 * BUF_BYTES)   // 92160

template <int MODE>
__global__ void __launch_bounds__(256, 2)
gemm_mma(const __half* __restrict__ Ahi, const __half* __restrict__ Alo,
         const __half* __restrict__ Bhi,
         float* __restrict__ C, const float* __restrict__ bias,
         __half* __restrict__ Chi, __half* __restrict__ Clo,
         int M, int rows_per_seg, int seg_stride, int seg_base)
{
    extern __shared__ __align__(128) char smem[];
    const uint32_t sb = smem_to_u32(smem);
    const int tid = threadIdx.x;
    const int bn = blockIdx.x * 128;
    const int bm = blockIdx.y * 128;
    const int wid = tid >> 5, lane = tid & 31;
    const int Wm = (wid & 3) * 32;
    const int Wn = (wid >> 2) * 64;

    const int lrow = tid >> 1;
    const int lc = tid & 1;
    int m = bm + lrow; if (m > M - 1) m = M - 1;
    const int seg = m / rows_per_seg;
    const int t = m - seg * rows_per_seg;
    const size_t aoff = (size_t)(seg * seg_stride + seg_base + t) * 1024 + lc * 16;
    const size_t boff = (size_t)(bn + lrow) * 1024 + lc * 16;
    const uint32_t soff = (uint32_t)lrow * 80u + (uint32_t)lc * 32u;

    float acc[2][8][4];
#pragma unroll
    for (int i = 0; i < 2; i++)
#pragma unroll
        for (int j = 0; j < 8; j++)
#pragma unroll
            for (int c = 0; c < 4; c++) acc[i][j][c] = 0.f;

    const uint32_t a_frag_row = (uint32_t)(Wm + (lane & 15)) * 80u + ((lane >> 4) * 16u);
    const uint32_t b_frag_row =
        (uint32_t)(Wn + (lane & 7) + ((lane >> 4) << 3)) * 80u + (((lane >> 3) & 1) * 16u);

#define ISSUE(p, k0)                                                       \
    {                                                                      \
        uint32_t d = sb + (p) * BUF_BYTES + soff;                          \
        const __half* s;                                                   \
        s = Ahi + aoff + (k0); CPA16(d,           s); CPA16(d + 16,         s + 8); \
        s = Alo + aoff + (k0); CPA16(d + 10240,   s); CPA16(d + 10240 + 16, s + 8); \
        s = Bhi + boff + (k0); CPA16(d + 20480,   s); CPA16(d + 20480 + 16, s + 8); \
    }

    ISSUE(0, 0);
    CPA_COMMIT();
    ISSUE(1, 32);
    CPA_COMMIT();

    int stage = 0;
    for (int i = 0; i < 32; i++) {
        if (i < 31) { CPA_WAIT(1); } else { CPA_WAIT(0); }
        __syncthreads();
        if (i + 2 < 32) {
            int ns = stage + 2; if (ns >= 3) ns -= 3;
            ISSUE(ns, (i + 2) * 32);
            CPA_COMMIT();
        }

        const uint32_t base = sb + stage * BUF_BYTES;
#pragma unroll
        for (int kk = 0; kk < 2; kk++) {
            uint32_t ah[2][4], al[2][4], bh[4][4];
            const uint32_t ar = base + a_frag_row + kk * 32;
            LDMX4(ah[0][0], ah[0][1], ah[0][2], ah[0][3], ar);
            LDMX4(ah[1][0], ah[1][1], ah[1][2], ah[1][3], ar + 16 * 80);
            LDMX4(al[0][0], al[0][1], al[0][2], al[0][3], ar + 10240);
            LDMX4(al[1][0], al[1][1], al[1][2], al[1][3], ar + 10240 + 16 * 80);
#pragma unroll
            for (int j = 0; j < 4; j++) {
                const uint32_t br = base + 20480 + b_frag_row + kk * 32
                                    + (uint32_t)j * (16 * 80);
                LDMX4(bh[j][0], bh[j][1], bh[j][2], bh[j][3], br);
            }
            // hi-term sweep: 16 independent accumulators
#pragma unroll
            for (int j = 0; j < 4; j++)
#pragma unroll
                for (int mt = 0; mt < 2; mt++) {
                    MMA16816(acc[mt][2 * j],     ah[mt], bh[j][0], bh[j][1]);
                    MMA16816(acc[mt][2 * j + 1], ah[mt], bh[j][2], bh[j][3]);
                }
            // lo-term sweep: each dep >=16 MMAs after its hi partner
#pragma unroll
            for (int j = 0; j < 4; j++)
#pragma unroll
                for (int mt = 0; mt < 2; mt++) {
                    MMA16816(acc[mt][2 * j],     al[mt], bh[j][0], bh[j][1]);
                    MMA16816(acc[mt][2 * j + 1], al[mt], bh[j][2], bh[j][3]);
                }
        }
        stage++; if (stage >= 3) stage = 0;
    }
#undef ISSUE

    const int er = lane >> 2, ec = (lane & 3) * 2;
#pragma unroll
    for (int mt = 0; mt < 2; mt++) {
#pragma unroll
        for (int hrow = 0; hrow < 2; hrow++) {
            const int cm = bm + Wm + mt * 16 + er + hrow * 8;
            if (cm >= M) continue;
            if (MODE == 1) {
                const int segc = cm / rows_per_seg;
                const int tc = cm - segc * rows_per_seg;
#pragma unroll
                for (int nt = 0; nt < 8; nt++) {
                    const int cn = bn + Wn + nt * 8 + ec;
                    const int hh = cn >> 6, dd = cn & 63;
                    size_t oi = (((size_t)segc * H_ + hh) * rows_per_seg + tc) * 64 + dd;
                    float v0 = acc[mt][nt][hrow * 2], v1 = acc[mt][nt][hrow * 2 + 1];
                    float h0 = __half2float(__float2half(v0));
                    float h1 = __half2float(__float2half(v1));
                    *(uint32_t*)(Chi + oi) = packh(h0, h1);
                    *(uint32_t*)(Clo + oi) = packh(v0 - h0, v1 - h1);
                }
            } else if (MODE == 2) {
#pragma unroll
                for (int nt = 0; nt < 8; nt++) {
                    const int cn = bn + Wn + nt * 8 + ec;
                    size_t oi = (size_t)cm * DM_ + cn;
                    float v0 = acc[mt][nt][hrow * 2] * 0.125f;
                    float v1 = acc[mt][nt][hrow * 2 + 1] * 0.125f;
                    float h0 = __half2float(__float2half(v0));
                    float h1 = __half2float(__float2half(v1));
                    *(uint32_t*)(Chi + oi) = packh(h0, h1);
                    *(uint32_t*)(Clo + oi) = packh(v0 - h0, v1 - h1);
                }
            } else {
                float* Cp = C + (size_t)cm * DM_ + bn + Wn + ec;
                const float* bp = bias + bn + Wn + ec;
#pragma unroll
                for (int nt = 0; nt < 8; nt++) {
                    float2 v = make_float2(acc[mt][nt][hrow * 2] + bp[nt * 8],
                                           acc[mt][nt][hrow * 2 + 1] + bp[nt * 8 + 1]);
                    *(float2*)(Cp + nt * 8) = v;
                }
            }
        }
    }
}

// ---------------------------------------------------------------------------
// Tensor-core flash attention (fp16 hi/lo). One CTA = (b, h, 128-query tile).
// ---------------------------------------------------------------------------
#define AT_KHI 0
#define AT_KLO 48384
#define AT_VHI 96768
#define AT_VLO 145152
#define AT_QHI 193536
#define AT_QLO 211968
#define AT_PS  193536
#define AT_RKH 211968
#define AT_RKL 217728
#define AT_SMEM 230400

__device__ __forceinline__ int bidx(int j, int i)
{
    int d = j - i;
    d = max(-16, min(16, d));
    return d + 16;
}

__device__ __forceinline__ void wsplit(const float* s0, const float* s1,
                                       uint32_t* ahi, uint32_t* alo)
{
    float v[8] = {s0[0], s0[1], s0[2], s0[3], s1[0], s1[1], s1[2], s1[3]};
    float hv[8];
#pragma unroll
    for (int i = 0; i < 8; i++)
        hv[i] = __half2float(__float2half(v[i]));
    ahi[0] = packh(hv[0], hv[1]); ahi[1] = packh(hv[2], hv[3]);
    ahi[2] = packh(hv[4], hv[5]); ahi[3] = packh(hv[6], hv[7]);
    alo[0] = packh(v[0] - hv[0], v[1] - hv[1]);
    alo[1] = packh(v[2] - hv[2], v[3] - hv[3]);
    alo[2] = packh(v[4] - hv[4], v[5] - hv[5]);
    alo[3] = packh(v[6] - hv[6], v[7] - hv[7]);
}

__global__ void __launch_bounds__(256, 1)
attn_mma(const __half* __restrict__ qhi, const __half* __restrict__ qlo,
         const __half* __restrict__ kthi, const __half* __restrict__ ktlo,
         const __half* __restrict__ vthi, const __half* __restrict__ vtlo,
         const __half* __restrict__ kihi, const __half* __restrict__ kilo,
         const __half* __restrict__ vihi, const __half* __restrict__ vilo,
         const float* __restrict__ relk, const float* __restrict__ relv,
         __half* __restrict__ atthi, __half* __restrict__ attlo)
{
    extern __shared__ __align__(128) char sm[];
    const uint32_t sb = smem_to_u32(sm);
    const int tid = threadIdx.x, w = tid >> 5, lane = tid & 31;
    const int bh = blockIdx.x >> 3, qt = blockIdx.x & 7;
    const int b = bh >> 4, h = bh & 15;
    const int i0 = qt * 128;
    const unsigned FULL = 0xffffffffu;

    // ---- stage K/V/Q ----
    {
        size_t tb = (size_t)bh * (LT_ * 64);
        for (int idx = tid; idx < LT_ * 8; idx += 256) {
            int r = idx >> 3, c = idx & 7;
            uint32_t d = (uint32_t)r * 144 + c * 16;
            size_t s = tb + (size_t)r * 64 + c * 8;
            CPA16(sb + AT_KHI + d, kthi + s);
            CPA16(sb + AT_KLO + d, ktlo + s);
            CPA16(sb + AT_VHI + d, vthi + s);
            CPA16(sb + AT_VLO + d, vtlo + s);
        }
        size_t ib = (size_t)bh * (LI_ * 64);
        for (int idx = tid; idx < LI_ * 8; idx += 256) {
            int r = idx >> 3, c = idx & 7;
            uint32_t d = (uint32_t)(80 + r) * 144 + c * 16;
            size_t s = ib + (size_t)r * 64 + c * 8;
            CPA16(sb + AT_KHI + d, kihi + s);
            CPA16(sb + AT_KLO + d, kilo + s);
            CPA16(sb + AT_VHI + d, vihi + s);
            CPA16(sb + AT_VLO + d, vilo + s);
        }
        size_t qb = ((size_t)(b * NQ_ + i0)) * 1024 + h * 64;
        for (int idx = tid; idx < 128 * 8; idx += 256) {
            int r = idx >> 3, c = idx & 7;
            uint32_t d = (uint32_t)r * 144 + c * 16;
            size_t s = qb + (size_t)r * 1024 + c * 8;
            CPA16(sb + AT_QHI + d, qhi + s);
            CPA16(sb + AT_QLO + d, qlo + s);
        }
        for (int idx = tid; idx < 3 * 36; idx += 256) {
            uint32_t d = (uint32_t)(77 + idx / 36) * 144 + (idx % 36) * 4;
            *(uint32_t*)(sm + AT_KHI + d) = 0;
            *(uint32_t*)(sm + AT_KLO + d) = 0;
            *(uint32_t*)(sm + AT_VHI + d) = 0;
            *(uint32_t*)(sm + AT_VLO + d) = 0;
        }
        CPA_COMMIT();
        CPA_WAIT(0);
        __syncthreads();
    }

    const int wr = w * 16;
    const int r0l = wr + (lane >> 2);

    // ---- Q fragments ----
    uint32_t qh[4][4], ql[4][4];
    {
        int row = wr + (lane & 15);
        int kb = (lane >> 4) * 16;
#pragma unroll
        for (int kk = 0; kk < 4; kk++) {
            uint32_t a = sb + AT_QHI + (uint32_t)row * 144 + kk * 32 + kb;
            LDMX4(qh[kk][0], qh[kk][1], qh[kk][2], qh[kk][3], a);
            LDMX4(ql[kk][0], ql[kk][1], ql[kk][2], ql[kk][3], a + (AT_QLO - AT_QHI));
        }
    }
    __syncthreads();

    if (qt == 0) {
        for (int idx = tid; idx < NR_ * 64; idx += 256) {
            int r = idx >> 6, dc = idx & 63;
            float v = relk[idx];
            float hh = __half2float(__float2half(v));
            *(__half*)(sm + AT_RKH + r * 144 + dc * 2) = __float2half(hh);
            *(__half*)(sm + AT_RKL + r * 144 + dc * 2) = __float2half(v - hh);
        }
    }
    __syncthreads();

    float* pS = (float*)(sm + AT_PS);

    const int brow = ((lane >> 4) << 3) + (lane & 7);
    const int bdb = (lane & 8) * 2;

    // ---- rel-K projections (tile 0) ----
    if (qt == 0) {
        float pr[5][4];
#pragma unroll
        for (int i = 0; i < 5; i++)
#pragma unroll
            for (int c = 0; c < 4; c++) pr[i][c] = 0.f;
#pragma unroll
        for (int kk = 0; kk < 4; kk++) {
#pragma unroll
            for (int p2 = 0; p2 < 3; p2++) {
                uint32_t bh4[4], bl4[4];
                uint32_t ad = sb + AT_RKH + (uint32_t)(p2 * 16 + brow) * 144
                              + kk * 32 + bdb;
                LDMX4(bh4[0], bh4[1], bh4[2], bh4[3], ad);
                LDMX4(bl4[0], bl4[1], bl4[2], bl4[3], ad + (AT_RKL - AT_RKH));
                MMA16816(pr[2 * p2], qh[kk], bh4[0], bh4[1]);
                MMA16816(pr[2 * p2], ql[kk], bh4[0], bh4[1]);
                MMA16816(pr[2 * p2], qh[kk], bl4[0], bl4[1]);
                if (p2 < 2) {
                    MMA16816(pr[2 * p2 + 1], qh[kk], bh4[2], bh4[3]);
                    MMA16816(pr[2 * p2 + 1], ql[kk], bh4[2], bh4[3]);
                    MMA16816(pr[2 * p2 + 1], qh[kk], bl4[2], bl4[3]);
                }
            }
        }
#pragma unroll
        for (int nt = 0; nt < 5; nt++) {
            int c0 = nt * 8 + 2 * (lane & 3);
            if (c0 < NR_) {
                pS[r0l * 34 + c0] = pr[nt][0];
                pS[(r0l + 8) * 34 + c0] = pr[nt][2];
            }
            if (c0 + 1 < NR_) {
                pS[r0l * 34 + c0 + 1] = pr[nt][1];
                pS[(r0l + 8) * 34 + c0 + 1] = pr[nt][3];
            }
        }
        __syncwarp();
    }

    // ---- text scores ----
    float s[10][4];
#pragma unroll
    for (int i = 0; i < 10; i++)
#pragma unroll
        for (int c = 0; c < 4; c++) s[i][c] = 0.f;
#pragma unroll
    for (int kk = 0; kk < 4; kk++) {
#pragma unroll
        for (int p2 = 0; p2 < 5; p2++) {
            uint32_t kh4[4], kl4[4];
            uint32_t ad = sb + AT_KHI + (uint32_t)(p2 * 16 + brow) * 144
                          + kk * 32 + bdb;
            LDMX4(kh4[0], kh4[1], kh4[2], kh4[3], ad);
            LDMX4(kl4[0], kl4[1], kl4[2], kl4[3], ad + (AT_KLO - AT_KHI));
            MMA16816(s[2 * p2], qh[kk], kh4[0], kh4[1]);
            MMA16816(s[2 * p2], ql[kk], kh4[0], kh4[1]);
            MMA16816(s[2 * p2], qh[kk], kl4[0], kl4[1]);
            MMA16816(s[2 * p2 + 1], qh[kk], kh4[2], kh4[3]);
            MMA16816(s[2 * p2 + 1], ql[kk], kh4[2], kh4[3]);
            MMA16816(s[2 * p2 + 1], qh[kk], kl4[2], kl4[3]);
        }
    }

#pragma unroll
    for (int nt = 0; nt < 10; nt++) {
        int c0 = nt * 8 + 2 * (lane & 3);
        if (qt == 0) {
            s[nt][0] += pS[r0l * 34 + bidx(c0, r0l)];
            s[nt][1] += pS[r0l * 34 + bidx(c0 + 1, r0l)];
            s[nt][2] += pS[(r0l + 8) * 34 + bidx(c0, r0l + 8)];
            s[nt][3] += pS[(r0l + 8) * 34 + bidx(c0 + 1, r0l + 8)];
        }
        if (c0 >= LT_) { s[nt][0] = -1e30f; s[nt][2] = -1e30f; }
        if (c0 + 1 >= LT_) { s[nt][1] = -1e30f; s[nt][3] = -1e30f; }
    }

    float m0 = -1e30f, m1 = -1e30f;
#pragma unroll
    for (int nt = 0; nt < 10; nt++) {
        m0 = fmaxf(m0, fmaxf(s[nt][0], s[nt][1]));
        m1 = fmaxf(m1, fmaxf(s[nt][2], s[nt][3]));
    }
    m0 = fmaxf(m0, __shfl_xor_sync(FULL, m0, 1));
    m0 = fmaxf(m0, __shfl_xor_sync(FULL, m0, 2));
    m1 = fmaxf(m1, __shfl_xor_sync(FULL, m1, 1));
    m1 = fmaxf(m1, __shfl_xor_sync(FULL, m1, 2));
    float l0 = 0.f, l1 = 0.f;
#pragma unroll
    for (int nt = 0; nt < 10; nt++) {
        s[nt][0] = __expf(s[nt][0] - m0); l0 += s[nt][0];
        s[nt][1] = __expf(s[nt][1] - m0); l0 += s[nt][1];
        s[nt][2] = __expf(s[nt][2] - m1); l1 += s[nt][2];
        s[nt][3] = __expf(s[nt][3] - m1); l1 += s[nt][3];
    }
    l0 += __shfl_xor_sync(FULL, l0, 1); l0 += __shfl_xor_sync(FULL, l0, 2);
    l1 += __shfl_xor_sync(FULL, l1, 1); l1 += __shfl_xor_sync(FULL, l1, 2);
    float inv0 = 1.f / l0, inv1 = 1.f / l1;
#pragma unroll
    for (int nt = 0; nt < 10; nt++) {
        s[nt][0] *= inv0; s[nt][1] *= inv0;
        s[nt][2] *= inv1; s[nt][3] *= inv1;
    }

    if (qt == 0) {
        for (int idx = lane; idx < 16 * 34; idx += 32)
            pS[(wr + idx / 34) * 34 + idx % 34] = 0.f;
        __syncwarp();
#pragma unroll
        for (int nt = 0; nt < 10; nt++) {
            int c0 = nt * 8 + 2 * (lane & 3);
            if (c0 < LT_) {
                atomicAdd(&pS[r0l * 34 + bidx(c0, r0l)], s[nt][0]);
                atomicAdd(&pS[(r0l + 8) * 34 + bidx(c0, r0l + 8)], s[nt][2]);
            }
            if (c0 + 1 < LT_) {
                atomicAdd(&pS[r0l * 34 + bidx(c0 + 1, r0l)], s[nt][1]);
                atomicAdd(&pS[(r0l + 8) * 34 + bidx(c0 + 1, r0l + 8)], s[nt][3]);
            }
        }
        __syncwarp();
    }

    const int vrow = (lane & 8) + (lane & 7);
    const int vdb = (lane >> 4) * 16;

    float ot[8][4];
#pragma unroll
    for (int i = 0; i < 8; i++)
#pragma unroll
        for (int c = 0; c < 4; c++) ot[i][c] = 0.f;
#pragma unroll
    for (int wk = 0; wk < 5; wk++) {
        uint32_t ahi[4], alo[4];
        wsplit(s[2 * wk], s[2 * wk + 1], ahi, alo);
#pragma unroll
        for (int dp = 0; dp < 4; dp++) {
            uint32_t vh4[4], vl4[4];
            uint32_t ad = sb + AT_VHI + (uint32_t)(wk * 16 + vrow) * 144
                          + dp * 32 + vdb;
            LDMX4T(vh4[0], vh4[1], vh4[2], vh4[3], ad);
            LDMX4T(vl4[0], vl4[1], vl4[2], vl4[3], ad + (AT_VLO - AT_VHI));
            MMA16816(ot[2 * dp], ahi, vh4[0], vh4[1]);
            MMA16816(ot[2 * dp], alo, vh4[0], vh4[1]);
            MMA16816(ot[2 * dp], ahi, vl4[0], vl4[1]);
            MMA16816(ot[2 * dp + 1], ahi, vh4[2], vh4[3]);
            MMA16816(ot[2 * dp + 1], alo, vh4[2], vh4[3]);
            MMA16816(ot[2 * dp + 1], ahi, vl4[2], vl4[3]);
        }
    }

    if (qt == 0) {
#pragma unroll 1
        for (int r = 0; r < NR_; r++) {
            float w0 = pS[r0l * 34 + r];
            float w1 = pS[(r0l + 8) * 34 + r];
            const float* rv = relv + r * 64 + 2 * (lane & 3);
#pragma unroll
            for (int dt = 0; dt < 8; dt++) {
                float rv0 = rv[dt * 8], rv1 = rv[dt * 8 + 1];
                ot[dt][0] += w0 * rv0; ot[dt][1] += w0 * rv1;
                ot[dt][2] += w1 * rv0; ot[dt][3] += w1 * rv1;
            }
        }
    } else {
        const float* rv = relv + 2 * (lane & 3);
#pragma unroll
        for (int dt = 0; dt < 8; dt++) {
            float rv0 = rv[dt * 8], rv1 = rv[dt * 8 + 1];
            ot[dt][0] += rv0; ot[dt][1] += rv1;
            ot[dt][2] += rv0; ot[dt][3] += rv1;
        }
    }

    float oi[8][4];
#pragma unroll
    for (int i = 0; i < 8; i++)
#pragma unroll
        for (int c = 0; c < 4; c++) oi[i][c] = 0.f;
    float mi0 = -1e30f, mi1 = -1e30f, li0 = 0.f, li1 = 0.f;
#pragma unroll 1
    for (int ch = 0; ch < 8; ch++) {
        const int j0 = 80 + ch * 32;
        float sc[4][4];
#pragma unroll
        for (int i = 0; i < 4; i++)
#pragma unroll
            for (int c = 0; c < 4; c++) sc[i][c] = 0.f;
#pragma unroll
        for (int kk = 0; kk < 4; kk++) {
#pragma unroll
            for (int p2 = 0; p2 < 2; p2++) {
                uint32_t kh4[4], kl4[4];
                uint32_t ad = sb + AT_KHI + (uint32_t)(j0 + p2 * 16 + brow) * 144
                              + kk * 32 + bdb;
                LDMX4(kh4[0], kh4[1], kh4[2], kh4[3], ad);
                LDMX4(kl4[0], kl4[1], kl4[2], kl4[3], ad + (AT_KLO - AT_KHI));
                MMA16816(sc[2 * p2], qh[kk], kh4[0], kh4[1]);
                MMA16816(sc[2 * p2], ql[kk], kh4[0], kh4[1]);
                MMA16816(sc[2 * p2], qh[kk], kl4[0], kl4[1]);
                MMA16816(sc[2 * p2 + 1], qh[kk], kh4[2], kh4[3]);
                MMA16816(sc[2 * p2 + 1], ql[kk], kh4[2], kh4[3]);
                MMA16816(sc[2 * p2 + 1], qh[kk], kl4[2], kl4[3]);
            }
        }
        float cm0 = -1e30f, cm1 = -1e30f;
#pragma unroll
        for (int t = 0; t < 4; t++) {
            cm0 = fmaxf(cm0, fmaxf(sc[t][0], sc[t][1]));
            cm1 = fmaxf(cm1, fmaxf(sc[t][2], sc[t][3]));
        }
        cm0 = fmaxf(cm0, __shfl_xor_sync(FULL, cm0, 1));
        cm0 = fmaxf(cm0, __shfl_xor_sync(FULL, cm0, 2));
        cm1 = fmaxf(cm1, __shfl_xor_sync(FULL, cm1, 1));
        cm1 = fmaxf(cm1, __shfl_xor_sync(FULL, cm1, 2));
        float mn0 = fmaxf(mi0, cm0), mn1 = fmaxf(mi1, cm1);
        float al0 = __expf(mi0 - mn0), al1 = __expf(mi1 - mn1);
        float cs0 = 0.f, cs1 = 0.f;
#pragma unroll
        for (int t = 0; t < 4; t++) {
            sc[t][0] = __expf(sc[t][0] - mn0); cs0 += sc[t][0];
            sc[t][1] = __expf(sc[t][1] - mn0); cs0 += sc[t][1];
            sc[t][2] = __expf(sc[t][2] - mn1); cs1 += sc[t][2];
            sc[t][3] = __expf(sc[t][3] - mn1); cs1 += sc[t][3];
        }
        cs0 += __shfl_xor_sync(FULL, cs0, 1); cs0 += __shfl_xor_sync(FULL, cs0, 2);
        cs1 += __shfl_xor_sync(FULL, cs1, 1); cs1 += __shfl_xor_sync(FULL, cs1, 2);
        li0 = li0 * al0 + cs0; li1 = li1 * al1 + cs1;
        mi0 = mn0; mi1 = mn1;
#pragma unroll
        for (int dt = 0; dt < 8; dt++) {
            oi[dt][0] *= al0; oi[dt][1] *= al0;
            oi[dt][2] *= al1; oi[dt][3] *= al1;
        }
#pragma unroll
        for (int wk = 0; wk < 2; wk++) {
            uint32_t ahi[4], alo[4];
            wsplit(sc[2 * wk], sc[2 * wk + 1], ahi, alo);
#pragma unroll
            for (int dp = 0; dp < 4; dp++) {
                uint32_t vh4[4], vl4[4];
                uint32_t ad = sb + AT_VHI + (uint32_t)(j0 + wk * 16 + vrow) * 144
                              + dp * 32 + vdb;
                LDMX4T(vh4[0], vh4[1], vh4[2], vh4[3], ad);
                LDMX4T(vl4[0], vl4[1], vl4[2], vl4[3], ad + (AT_VLO - AT_VHI));
                MMA16816(oi[2 * dp], ahi, vh4[0], vh4[1]);
                MMA16816(oi[2 * dp], alo, vh4[0], vh4[1]);
                MMA16816(oi[2 * dp], ahi, vl4[0], vl4[1]);
                MMA16816(oi[2 * dp + 1], ahi, vh4[2], vh4[3]);
                MMA16816(oi[2 * dp + 1], alo, vh4[2], vh4[3]);
                MMA16816(oi[2 * dp + 1], ahi, vl4[2], vl4[3]);
            }
        }
    }
    float ii0 = 1.f / li0, ii1 = 1.f / li1;

    {
        size_t ob = ((size_t)(b * NQ_ + i0 + r0l)) * 1024 + h * 64 + 2 * (lane & 3);
#pragma unroll
        for (int dt = 0; dt < 8; dt++) {
            float v0 = ot[dt][0] + oi[dt][0] * ii0;
            float v1 = ot[dt][1] + oi[dt][1] * ii0;
            float v2 = ot[dt][2] + oi[dt][2] * ii1;
            float v3 = ot[dt][3] + oi[dt][3] * ii1;
            float h0 = __half2float(__float2half(v0));
            float h1 = __half2float(__float2half(v1));
            float h2 = __half2float(__float2half(v2));
            float h3 = __half2float(__float2half(v3));
            size_t o0 = ob + dt * 8;
            size_t o1 = o0 + 8 * 1024;
            *(uint32_t*)(atthi + o0) = packh(h0, h1);
            *(uint32_t*)(attlo + o0) = packh(v0 - h0, v1 - h1);
            *(uint32_t*)(atthi + o1) = packh(h2, h3);
            *(uint32_t*)(attlo + o1) = packh(v2 - h2, v3 - h3);
        }
    }
}

// ---------------------------------------------------------------------------
// Host launcher
// ---------------------------------------------------------------------------
extern "C" void kernel_launch(void* const* d_in, const int* in_sizes, int n_in,
                              void* d_out, int out_size)
{
    const float* x     = (const float*)d_in[0];
    const float* ctx   = (const float*)d_in[1];
    const float* Wq    = (const float*)d_in[2];
    const float* Wk    = (const float*)d_in[3];
    const float* Wv    = (const float*)d_in[4];
    const float* Wk_ip = (const float*)d_in[5];
    const float* Wv_ip = (const float*)d_in[6];
    const float* Wout  = (const float*)d_in[7];
    const float* bout  = (const float*)d_in[8];
    const float* relk  = (const float*)d_in[9];
    const float* relv  = (const float*)d_in[10];
    float* out = (float*)d_out;

    __half *pahi, *palo, *pqhi, *pqlo, *pchi, *pclo, *pwhi, *pwlo;
    __half *pkthi, *pktlo, *pvthi, *pvtlo, *pkihi, *pkilo, *pvihi, *pvilo;
    cudaGetSymbolAddress((void**)&pahi, g_ahi);
    cudaGetSymbolAddress((void**)&palo, g_alo);
    cudaGetSymbolAddress((void**)&pqhi, g_qhi);
    cudaGetSymbolAddress((void**)&pqlo, g_qlo);
    cudaGetSymbolAddress((void**)&pchi, g_chi);
    cudaGetSymbolAddress((void**)&pclo, g_clo);
    cudaGetSymbolAddress((void**)&pwhi, g_whi);
    cudaGetSymbolAddress((void**)&pwlo, g_wlo);
    cudaGetSymbolAddress((void**)&pkthi, g_kthi);
    cudaGetSymbolAddress((void**)&pktlo, g_ktlo);
    cudaGetSymbolAddress((void**)&pvthi, g_vthi);
    cudaGetSymbolAddress((void**)&pvtlo, g_vtlo);
    cudaGetSymbolAddress((void**)&pkihi, g_kihi);
    cudaGetSymbolAddress((void**)&pkilo, g_kilo);
    cudaGetSymbolAddress((void**)&pvihi, g_vihi);
    cudaGetSymbolAddress((void**)&pvilo, g_vilo);

    cudaFuncSetAttribute(gemm_mma<0>,
                         cudaFuncAttributeMaxDynamicSharedMemorySize, GM_SMEM);
    cudaFuncSetAttribute(gemm_mma<1>,
                         cudaFuncAttributeMaxDynamicSharedMemorySize, GM_SMEM);
    cudaFuncSetAttribute(gemm_mma<2>,
                         cudaFuncAttributeMaxDynamicSharedMemorySize, GM_SMEM);
    cudaFuncSetAttribute(attn_mma,
                         cudaFuncAttributeMaxDynamicSharedMemorySize, AT_SMEM);

    const size_t WSZ = (size_t)DM_ * DM_;
    size_t nx = (size_t)B_ * NQ_ * DM_;
    size_t nc = (size_t)B_ * CTXR * DM_;

    conv_wt<<<dim3(32, 32), dim3(32, 8)>>>(Wq, pwhi + 0 * WSZ, pwlo + 0 * WSZ);
    conv_rows<<<(unsigned)(nx / 4 / 256), 256>>>(x, pahi, palo, nx);
    conv_rows<<<(unsigned)((nc / 4 + 255) / 256), 256>>>(ctx, pchi, pclo, nc);
    conv_wt<<<dim3(32, 32), dim3(32, 8)>>>(Wk, pwhi + 1 * WSZ, pwlo + 1 * WSZ);
    conv_wt<<<dim3(32, 32), dim3(32, 8)>>>(Wv, pwhi + 2 * WSZ, pwlo + 2 * WSZ);

    // Q = (x @ Wq) * 0.125 -> fp16 hi/lo
    gemm_mma<2><<<dim3(8, 512), 256, GM_SMEM>>>(
        pahi, palo, pwhi + 0 * WSZ, nullptr, nullptr,
        pqhi, pqlo, B_ * NQ_, B_ * NQ_, B_ * NQ_, 0);

    conv_wt<<<dim3(32, 32), dim3(32, 8)>>>(Wk_ip, pwhi + 3 * WSZ, pwlo + 3 * WSZ);
    conv_wt<<<dim3(32, 32), dim3(32, 8)>>>(Wv_ip, pwhi + 4 * WSZ, pwlo + 4 * WSZ);
    conv_wt<<<dim3(32, 32), dim3(32, 8)>>>(Wout,  pwhi + 5 * WSZ, pwlo + 5 * WSZ);

    // K/V text -> [b][h][t][d] fp16 hi/lo
    gemm_mma<1><<<dim3(8, 39), 256, GM_SMEM>>>(
        pchi, pclo, pwhi + 1 * WSZ, nullptr, nullptr,
        pkthi, pktlo, B_ * LT_, LT_, CTXR, 0);
    gemm_mma<1><<<dim3(8, 39), 256, GM_SMEM>>>(
        pchi, pclo, pwhi + 2 * WSZ, nullptr, nullptr,
        pvthi, pvtlo, B_ * LT_, LT_, CTXR, 0);

    // K/V image
    gemm_mma<1><<<dim3(8, 128), 256, GM_SMEM>>>(
        pchi, pclo, pwhi + 3 * WSZ, nullptr, nullptr,
        pkihi, pkilo, B_ * LI_, LI_, CTXR, LT_);
    gemm_mma<1><<<dim3(8, 128), 256, GM_SMEM>>>(
        pchi, pclo, pwhi + 4 * WSZ, nullptr, nullptr,
        pvihi, pvilo, B_ * LI_, LI_, CTXR, LT_);

    // tensor-core attention -> fp16 hi/lo into final-GEMM input buffers
    attn_mma<<<B_ * H_ * 8, 256, AT_SMEM>>>(
        pqhi, pqlo, pkthi, pktlo, pvthi, pvtlo,
        pkihi, pkilo, pvihi, pvilo, relk, relv, pahi, palo);

    // final projection + bias
    gemm_mma<0><<<dim3(8, 512), 256, GM_SMEM>>>(
        pahi, palo, pwhi + 5 * WSZ, out, bout,
        nullptr, nullptr, B_ * NQ_, B_ * NQ_, B_ * NQ_, 0);
}